// round 3
// baseline (speedup 1.0000x reference)
#include <cuda_runtime.h>
#include <math.h>

#define Nn 2048
#define Dd 256
#define Hh 8
#define DKk 32
#define Ll 4
#define DFFf 1024
#define NEDGEe 5

typedef unsigned long long u64t;

// packed fp32x2 FMA (FFMA2): 2 FLOPs per fma-pipe slot
__device__ __forceinline__ u64t ffma2(u64t a, u64t b, u64t c) {
    u64t d;
    asm("fma.rn.f32x2 %0, %1, %2, %3;" : "=l"(d) : "l"(a), "l"(b), "l"(c));
    return d;
}
__device__ __forceinline__ u64t bcast2(float x) {
    u64t r;
    asm("mov.b64 %0, {%1, %1};" : "=l"(r) : "f"(x), "f"(x));
    return r;
}
union f2u { u64t u; float2 f; };

// ---------------- scratch (static device globals: no allocation) ----------------
__device__ float g_x[Nn * Dd];
__device__ float g_q[Nn * Dd];
__device__ float g_k[Nn * Dd];
__device__ float g_v[Nn * Dd];
__device__ float g_att[Nn * Dd];
__device__ float g_t1[Nn * DFFf];
__device__ float g_part[4 * Nn * Dd];
__device__ unsigned char g_e8[Nn * Nn];
__device__ float g_pool[2 * Dd];

// ---------------- embedding gather ----------------
__global__ void embed_kernel(const int* __restrict__ nt, const float* __restrict__ emb,
                             float* __restrict__ x) {
    int i = blockIdx.x;
    int d = threadIdx.x;
    x[i * Dd + d] = emb[nt[i] * Dd + d];
}

// ---------------- int32 edge matrix -> uint8 ----------------
__global__ void cvt_e8_kernel(const int* __restrict__ e, unsigned char* __restrict__ o) {
    int i = blockIdx.x * blockDim.x + threadIdx.x;
    int4 v = ((const int4*)e)[i];
    uchar4 u;
    u.x = (unsigned char)v.x; u.y = (unsigned char)v.y;
    u.z = (unsigned char)v.z; u.w = (unsigned char)v.w;
    ((uchar4*)o)[i] = u;
}

// ---------------- common GEMM body: C[64x64 tile] = A[:,kbeg:kend] @ B ----------
// block 256 threads, per-thread 4x4 via f32x2. i0/j0 from blockIdx.y/x.
template <int ACT>
__device__ __forceinline__ void gemm_body(const float* __restrict__ A,
                                          const float* __restrict__ B,
                                          const float* __restrict__ bias,
                                          float* __restrict__ C, int Kd, int M,
                                          int kbeg, int kend) {
    __shared__ float AsT[16][64];
    __shared__ float Bs[16][64];
    const int tid = threadIdx.x;
    const int tx = tid & 15, ty = tid >> 4;
    const int i0 = blockIdx.y << 6, j0 = blockIdx.x << 6;

    u64t acc[4][2];
#pragma unroll
    for (int r = 0; r < 4; r++) { acc[r][0] = 0ull; acc[r][1] = 0ull; }

    const int aRow = tid >> 2, aK4 = (tid & 3) << 2;
    const int bK = tid >> 4, bC4 = (tid & 15) << 2;

    for (int kt = kbeg; kt < kend; kt += 16) {
        float4 av = *(const float4*)&A[(size_t)(i0 + aRow) * Kd + kt + aK4];
        float4 bv = *(const float4*)&B[(size_t)(kt + bK) * M + j0 + bC4];
        AsT[aK4 + 0][aRow] = av.x;
        AsT[aK4 + 1][aRow] = av.y;
        AsT[aK4 + 2][aRow] = av.z;
        AsT[aK4 + 3][aRow] = av.w;
        *(float4*)&Bs[bK][bC4] = bv;
        __syncthreads();
#pragma unroll
        for (int k = 0; k < 16; k++) {
            float4 a = *(const float4*)&AsT[k][ty << 2];
            ulonglong2 b = *(const ulonglong2*)&Bs[k][tx << 2];
            u64t a0 = bcast2(a.x), a1 = bcast2(a.y), a2 = bcast2(a.z), a3 = bcast2(a.w);
            acc[0][0] = ffma2(a0, b.x, acc[0][0]);
            acc[0][1] = ffma2(a0, b.y, acc[0][1]);
            acc[1][0] = ffma2(a1, b.x, acc[1][0]);
            acc[1][1] = ffma2(a1, b.y, acc[1][1]);
            acc[2][0] = ffma2(a2, b.x, acc[2][0]);
            acc[2][1] = ffma2(a2, b.y, acc[2][1]);
            acc[3][0] = ffma2(a3, b.x, acc[3][0]);
            acc[3][1] = ffma2(a3, b.y, acc[3][1]);
        }
        __syncthreads();
    }

#pragma unroll
    for (int r = 0; r < 4; r++) {
        f2u c0, c1;
        c0.u = acc[r][0];
        c1.u = acc[r][1];
        float vv[4] = {c0.f.x, c0.f.y, c1.f.x, c1.f.y};
        float4 o;
        float* po = &o.x;
#pragma unroll
        for (int c = 0; c < 4; c++) {
            float v = vv[c];
            if (bias) v += bias[j0 + (tx << 2) + c];
            if (ACT == 1) v = 0.5f * v * (1.0f + erff(v * 0.70710678118654752f));
            po[c] = v;
        }
        *(float4*)&C[(size_t)(i0 + (ty << 2) + r) * M + j0 + (tx << 2)] = o;
    }
}

// general GEMM with optional K-split (grid.z): partial z writes to C + z*Nn*M
template <int ACT, int SPLIT>
__global__ void __launch_bounds__(256) gemm_kernel(const float* __restrict__ A,
                                                   const float* __restrict__ B,
                                                   const float* __restrict__ bias,
                                                   float* __restrict__ C, int Kd, int M) {
    int kslice = Kd / SPLIT;
    int kbeg = blockIdx.z * kslice;
    float* Cz = C + (size_t)blockIdx.z * Nn * M;
    gemm_body<ACT>(A, B, SPLIT == 1 ? bias : nullptr, Cz, Kd, M, kbeg, kbeg + kslice);
}

// batched QKV: grid.z in {0,1,2} selects weight + destination
__global__ void __launch_bounds__(256) gemm_qkv_kernel(
    const float* __restrict__ A, const float* __restrict__ Wq,
    const float* __restrict__ Wk, const float* __restrict__ Wv,
    float* __restrict__ q, float* __restrict__ k, float* __restrict__ v) {
    int z = blockIdx.z;
    const float* B = (z == 0) ? Wq : (z == 1) ? Wk : Wv;
    float* C = (z == 0) ? q : (z == 1) ? k : v;
    gemm_body<0>(A, B, nullptr, C, Dd, Dd, 0, Dd);
}

// ---------------- flash attention with edge bias ----------------
__global__ void __launch_bounds__(256) attn_kernel(
    const float* __restrict__ Qg, const float* __restrict__ Kg, const float* __restrict__ Vg,
    const unsigned char* __restrict__ E8, const float* __restrict__ ebl,
    float* __restrict__ Og) {
    const int h = blockIdx.y;
    const int i0 = blockIdx.x << 6;
    const int tid = threadIdx.x;
    const int tx = tid & 15, ty = tid >> 4;

    __shared__ float QsT[DKk][64];
    __shared__ float KsT[DKk][64];
    __shared__ float Vs[64][DKk];
    __shared__ float Ps[64][65];
    __shared__ float s_eb[8];

    if (tid < NEDGEe) s_eb[tid] = ebl[tid * Hh + h];

#pragma unroll
    for (int it = 0; it < 2; it++) {
        int ff = tid + it * 256;
        int row = ff >> 3, c4 = (ff & 7) << 2;
        float4 q = *(const float4*)&Qg[(size_t)(i0 + row) * Dd + h * DKk + c4];
        QsT[c4 + 0][row] = q.x;
        QsT[c4 + 1][row] = q.y;
        QsT[c4 + 2][row] = q.z;
        QsT[c4 + 3][row] = q.w;
    }

    float m[4], l[4], o[4][2];
#pragma unroll
    for (int r = 0; r < 4; r++) {
        m[r] = -1e30f; l[r] = 0.f; o[r][0] = 0.f; o[r][1] = 0.f;
    }
    const float scale = 0.17677669529663687f;  // 1/sqrt(32)

    for (int jt = 0; jt < Nn; jt += 64) {
        __syncthreads();
#pragma unroll
        for (int it = 0; it < 2; it++) {
            int ff = tid + it * 256;
            int row = ff >> 3, c4 = (ff & 7) << 2;
            float4 kv = *(const float4*)&Kg[(size_t)(jt + row) * Dd + h * DKk + c4];
            KsT[c4 + 0][row] = kv.x;
            KsT[c4 + 1][row] = kv.y;
            KsT[c4 + 2][row] = kv.z;
            KsT[c4 + 3][row] = kv.w;
            float4 vv = *(const float4*)&Vg[(size_t)(jt + row) * Dd + h * DKk + c4];
            *(float4*)&Vs[row][c4] = vv;
        }
        __syncthreads();

        // S = Q K^T via f32x2
        u64t s2[4][2];
#pragma unroll
        for (int r = 0; r < 4; r++) { s2[r][0] = 0ull; s2[r][1] = 0ull; }
#pragma unroll
        for (int k = 0; k < DKk; k++) {
            float4 a = *(const float4*)&QsT[k][ty << 2];
            ulonglong2 b = *(const ulonglong2*)&KsT[k][tx << 2];
            u64t a0 = bcast2(a.x), a1 = bcast2(a.y), a2 = bcast2(a.z), a3 = bcast2(a.w);
            s2[0][0] = ffma2(a0, b.x, s2[0][0]);
            s2[0][1] = ffma2(a0, b.y, s2[0][1]);
            s2[1][0] = ffma2(a1, b.x, s2[1][0]);
            s2[1][1] = ffma2(a1, b.y, s2[1][1]);
            s2[2][0] = ffma2(a2, b.x, s2[2][0]);
            s2[2][1] = ffma2(a2, b.y, s2[2][1]);
            s2[3][0] = ffma2(a3, b.x, s2[3][0]);
            s2[3][1] = ffma2(a3, b.y, s2[3][1]);
        }

        float s[4][4];
#pragma unroll
        for (int r = 0; r < 4; r++) {
            f2u c0, c1;
            c0.u = s2[r][0];
            c1.u = s2[r][1];
            s[r][0] = c0.f.x; s[r][1] = c0.f.y; s[r][2] = c1.f.x; s[r][3] = c1.f.y;
        }

        // scale + edge bias
#pragma unroll
        for (int r = 0; r < 4; r++) {
            unsigned int e4 =
                *(const unsigned int*)&E8[(size_t)(i0 + (ty << 2) + r) * Nn + jt + (tx << 2)];
            s[r][0] = fmaf(s[r][0], scale, s_eb[e4 & 0xffu]);
            s[r][1] = fmaf(s[r][1], scale, s_eb[(e4 >> 8) & 0xffu]);
            s[r][2] = fmaf(s[r][2], scale, s_eb[(e4 >> 16) & 0xffu]);
            s[r][3] = fmaf(s[r][3], scale, s_eb[(e4 >> 24) & 0xffu]);
        }

        // online softmax
#pragma unroll
        for (int r = 0; r < 4; r++) {
            float rm = fmaxf(fmaxf(s[r][0], s[r][1]), fmaxf(s[r][2], s[r][3]));
#pragma unroll
            for (int off = 1; off < 16; off <<= 1)
                rm = fmaxf(rm, __shfl_xor_sync(0xffffffffu, rm, off));
            float mnew = fmaxf(m[r], rm);
            float alpha = __expf(m[r] - mnew);
            m[r] = mnew;
            o[r][0] *= alpha;
            o[r][1] *= alpha;
            float ps = 0.f;
#pragma unroll
            for (int c = 0; c < 4; c++) {
                float p = __expf(s[r][c] - mnew);
                ps += p;
                Ps[(ty << 2) + r][(tx << 2) + c] = p;
            }
#pragma unroll
            for (int off = 1; off < 16; off <<= 1)
                ps += __shfl_xor_sync(0xffffffffu, ps, off);
            l[r] = l[r] * alpha + ps;
        }
        __syncthreads();

        // O += P @ V
#pragma unroll 4
        for (int j = 0; j < 64; j++) {
            float2 v = *(const float2*)&Vs[j][tx << 1];
#pragma unroll
            for (int r = 0; r < 4; r++) {
                float p = Ps[(ty << 2) + r][j];
                o[r][0] = fmaf(p, v.x, o[r][0]);
                o[r][1] = fmaf(p, v.y, o[r][1]);
            }
        }
    }

#pragma unroll
    for (int r = 0; r < 4; r++) {
        float inv = 1.0f / l[r];
        float2 ov = make_float2(o[r][0] * inv, o[r][1] * inv);
        *(float2*)&Og[(size_t)(i0 + (ty << 2) + r) * Dd + h * DKk + (tx << 1)] = ov;
    }
}

// ---------------- partial-sum reduce + bias + residual + LayerNorm ----------------
template <int S>
__global__ void addln_red_kernel(float* __restrict__ x, const float* __restrict__ part,
                                 const float* __restrict__ bias, const float* __restrict__ g,
                                 const float* __restrict__ b) {
    int i = blockIdx.x, d = threadIdx.x;
    __shared__ float red[256];
    float v = x[i * Dd + d] + bias[d];
#pragma unroll
    for (int s = 0; s < S; s++) v += part[(size_t)s * Nn * Dd + (size_t)i * Dd + d];
    red[d] = v;
    __syncthreads();
    for (int s = 128; s > 0; s >>= 1) {
        if (d < s) red[d] += red[d + s];
        __syncthreads();
    }
    float mean = red[0] * (1.0f / Dd);
    __syncthreads();
    float dv = v - mean;
    red[d] = dv * dv;
    __syncthreads();
    for (int s = 128; s > 0; s >>= 1) {
        if (d < s) red[d] += red[d + s];
        __syncthreads();
    }
    float var = red[0] * (1.0f / Dd);
    x[i * Dd + d] = dv * rsqrtf(var + 1e-5f) * g[d] + b[d];
}

// ---------------- column-wise mean/max pooling ----------------
__global__ void pool_kernel(const float* __restrict__ x, float* __restrict__ p) {
    int j = blockIdx.x * 32 + threadIdx.x;
    int yy = threadIdx.y;
    float s = 0.f, mx = -1e30f;
    for (int i = yy; i < Nn; i += 8) {
        float v = x[(size_t)i * Dd + j];
        s += v;
        mx = fmaxf(mx, v);
    }
    __shared__ float ss[8][33], sm[8][33];
    ss[yy][threadIdx.x] = s;
    sm[yy][threadIdx.x] = mx;
    __syncthreads();
    if (yy == 0) {
        for (int k2 = 1; k2 < 8; k2++) {
            s += ss[k2][threadIdx.x];
            mx = fmaxf(mx, sm[k2][threadIdx.x]);
        }
        p[j] = s * (1.0f / Nn);
        p[Dd + j] = mx;
    }
}

// ---------------- final head ----------------
__global__ void head_kernel(const float* __restrict__ pooled, const float* __restrict__ Wr,
                            const float* __restrict__ br, float* __restrict__ out) {
    __shared__ float sp[2 * Dd];
    int d = threadIdx.x;
    sp[d] = pooled[d];
    sp[d + Dd] = pooled[d + Dd];
    __syncthreads();
    float acc = br[d];
#pragma unroll 8
    for (int k2 = 0; k2 < 2 * Dd; k2++) acc = fmaf(sp[k2], Wr[(size_t)k2 * Dd + d], acc);
    out[d] = acc;
}

// ---------------- host launcher ----------------
extern "C" void kernel_launch(void* const* d_in, const int* in_sizes, int n_in,
                              void* d_out, int out_size) {
    const int* node_types = (const int*)d_in[0];
    const int* edge_idx = (const int*)d_in[1];
    const float* node_emb = (const float*)d_in[2];
    const float* Wq = (const float*)d_in[3];
    const float* Wk = (const float*)d_in[4];
    const float* Wv = (const float*)d_in[5];
    const float* Wo = (const float*)d_in[6];
    const float* bo = (const float*)d_in[7];
    const float* eb = (const float*)d_in[8];
    const float* W1 = (const float*)d_in[9];
    const float* b1 = (const float*)d_in[10];
    const float* W2 = (const float*)d_in[11];
    const float* b2 = (const float*)d_in[12];
    const float* ln1g = (const float*)d_in[13];
    const float* ln1b = (const float*)d_in[14];
    const float* ln2g = (const float*)d_in[15];
    const float* ln2b = (const float*)d_in[16];
    const float* Wr = (const float*)d_in[17];
    const float* brr = (const float*)d_in[18];
    float* out = (float*)d_out;

    float *x, *q, *k, *v, *att, *t1, *part, *pool;
    unsigned char* e8;
    cudaGetSymbolAddress((void**)&x, g_x);
    cudaGetSymbolAddress((void**)&q, g_q);
    cudaGetSymbolAddress((void**)&k, g_k);
    cudaGetSymbolAddress((void**)&v, g_v);
    cudaGetSymbolAddress((void**)&att, g_att);
    cudaGetSymbolAddress((void**)&t1, g_t1);
    cudaGetSymbolAddress((void**)&part, g_part);
    cudaGetSymbolAddress((void**)&pool, g_pool);
    cudaGetSymbolAddress((void**)&e8, g_e8);

    embed_kernel<<<Nn, Dd>>>(node_types, node_emb, x);
    cvt_e8_kernel<<<(Nn * Nn / 4) / 256, 256>>>(edge_idx, e8);

    for (int l = 0; l < Ll; l++) {
        gemm_qkv_kernel<<<dim3(4, 32, 3), 256>>>(x, Wq + (size_t)l * Dd * Dd,
                                                 Wk + (size_t)l * Dd * Dd,
                                                 Wv + (size_t)l * Dd * Dd, q, k, v);

        attn_kernel<<<dim3(Nn / 64, Hh), 256>>>(q, k, v, e8, eb + l * NEDGEe * Hh, att);

        gemm_kernel<0, 2><<<dim3(4, 32, 2), 256>>>(att, Wo + (size_t)l * Dd * Dd, nullptr,
                                                   part, Dd, Dd);
        addln_red_kernel<2><<<Nn, Dd>>>(x, part, bo + l * Dd, ln1g + l * Dd, ln1b + l * Dd);

        gemm_kernel<1, 1><<<dim3(16, 32, 1), 256>>>(x, W1 + (size_t)l * Dd * DFFf,
                                                    b1 + l * DFFf, t1, Dd, DFFf);
        gemm_kernel<0, 4><<<dim3(4, 32, 4), 256>>>(t1, W2 + (size_t)l * DFFf * Dd, nullptr,
                                                   part, DFFf, Dd);
        addln_red_kernel<4><<<Nn, Dd>>>(x, part, b2 + l * Dd, ln2g + l * Dd, ln2b + l * Dd);
    }

    pool_kernel<<<Dd / 32, dim3(32, 8)>>>(x, pool);
    head_kernel<<<1, Dd>>>(pool, Wr, brr, out);
}

// round 4
// speedup vs baseline: 1.0030x; 1.0030x over previous
#include <cuda_runtime.h>
#include <math.h>

#define Nn 2048
#define Dd 256
#define Hh 8
#define DKk 32
#define Ll 4
#define DFFf 1024
#define NEDGEe 5

typedef unsigned long long u64t;

__device__ __forceinline__ u64t ffma2(u64t a, u64t b, u64t c) {
    u64t d;
    asm("fma.rn.f32x2 %0, %1, %2, %3;" : "=l"(d) : "l"(a), "l"(b), "l"(c));
    return d;
}
__device__ __forceinline__ u64t mul2(u64t a, u64t b) {
    u64t d;
    asm("mul.rn.f32x2 %0, %1, %2;" : "=l"(d) : "l"(a), "l"(b));
    return d;
}
__device__ __forceinline__ u64t bcast2(float x) {
    u64t r;
    asm("mov.b64 %0, {%1, %1};" : "=l"(r) : "f"(x), "f"(x));
    return r;
}
union f2u { u64t u; float2 f; };
__device__ __forceinline__ float hsum2(u64t a) {
    f2u t; t.u = a; return t.f.x + t.f.y;
}

// ---------------- scratch ----------------
__device__ float g_x[Nn * Dd];
__device__ float g_q[Nn * Dd];
__device__ float g_k[Nn * Dd];
__device__ float g_v[Nn * Dd];
__device__ float g_att[Nn * Dd];
__device__ float g_t1[Nn * DFFf];
__device__ float g_part[4 * Nn * Dd];
__device__ unsigned char g_e8[Nn * Nn];
__device__ float g_pool[2 * Dd];

__global__ void embed_kernel(const int* __restrict__ nt, const float* __restrict__ emb,
                             float* __restrict__ x) {
    int i = blockIdx.x;
    int d = threadIdx.x;
    x[i * Dd + d] = emb[nt[i] * Dd + d];
}

__global__ void cvt_e8_kernel(const int* __restrict__ e, unsigned char* __restrict__ o) {
    int i = blockIdx.x * blockDim.x + threadIdx.x;
    int4 v = ((const int4*)e)[i];
    uchar4 u;
    u.x = (unsigned char)v.x; u.y = (unsigned char)v.y;
    u.z = (unsigned char)v.z; u.w = (unsigned char)v.w;
    ((uchar4*)o)[i] = u;
}

// ---------------- GEMM: 128x64 tile, 8x4 per thread, f32x2 ----------------
template <int ACT>
__device__ __forceinline__ void gemm_body(const float* __restrict__ A,
                                          const float* __restrict__ B,
                                          const float* __restrict__ bias,
                                          float* __restrict__ C, int Kd, int M,
                                          int kbeg, int kend) {
    __shared__ float AsT[16][132];
    __shared__ float Bs[16][64];
    const int tid = threadIdx.x;
    const int tx = tid & 15, ty = tid >> 4;
    const int i0 = blockIdx.y << 7, j0 = blockIdx.x << 6;

    u64t acc[8][2];
#pragma unroll
    for (int r = 0; r < 8; r++) { acc[r][0] = 0ull; acc[r][1] = 0ull; }

    const int bK = tid >> 4, bC4 = (tid & 15) << 2;

    for (int kt = kbeg; kt < kend; kt += 16) {
#pragma unroll
        for (int it = 0; it < 2; it++) {
            int ff = tid + (it << 8);
            int aRow = ff >> 2, aK4 = (ff & 3) << 2;
            float4 av = *(const float4*)&A[(size_t)(i0 + aRow) * Kd + kt + aK4];
            float avv[4] = {av.x, av.y, av.z, av.w};
#pragma unroll
            for (int i = 0; i < 4; i++) {
                int k = aK4 + i;
                AsT[k][aRow ^ ((k & 12) << 1)] = avv[i];
            }
        }
        float4 bv = *(const float4*)&B[(size_t)(kt + bK) * M + j0 + bC4];
        *(float4*)&Bs[bK][bC4] = bv;
        __syncthreads();
#pragma unroll
        for (int k = 0; k < 16; k++) {
            int base = (ty << 3) ^ ((k & 12) << 1);
            float4 a0 = *(const float4*)&AsT[k][base];
            float4 a1 = *(const float4*)&AsT[k][base + 4];
            ulonglong2 b2 = *(const ulonglong2*)&Bs[k][tx << 2];
            float ar[8] = {a0.x, a0.y, a0.z, a0.w, a1.x, a1.y, a1.z, a1.w};
#pragma unroll
            for (int r = 0; r < 8; r++) {
                u64t ab = bcast2(ar[r]);
                acc[r][0] = ffma2(ab, b2.x, acc[r][0]);
                acc[r][1] = ffma2(ab, b2.y, acc[r][1]);
            }
        }
        __syncthreads();
    }

#pragma unroll
    for (int r = 0; r < 8; r++) {
        f2u c0, c1;
        c0.u = acc[r][0];
        c1.u = acc[r][1];
        float vv[4] = {c0.f.x, c0.f.y, c1.f.x, c1.f.y};
        float4 o;
        float* po = &o.x;
#pragma unroll
        for (int c = 0; c < 4; c++) {
            float v = vv[c];
            if (bias) v += bias[j0 + (tx << 2) + c];
            if (ACT == 1) v = 0.5f * v * (1.0f + erff(v * 0.70710678118654752f));
            po[c] = v;
        }
        *(float4*)&C[(size_t)(i0 + (ty << 3) + r) * M + j0 + (tx << 2)] = o;
    }
}

template <int ACT, int SPLIT>
__global__ void __launch_bounds__(256) gemm_kernel(const float* __restrict__ A,
                                                   const float* __restrict__ B,
                                                   const float* __restrict__ bias,
                                                   float* __restrict__ C, int Kd, int M) {
    int kslice = Kd / SPLIT;
    int kbeg = blockIdx.z * kslice;
    float* Cz = C + (size_t)blockIdx.z * Nn * M;
    gemm_body<ACT>(A, B, SPLIT == 1 ? bias : nullptr, Cz, Kd, M, kbeg, kbeg + kslice);
}

__global__ void __launch_bounds__(256) gemm_qkv_kernel(
    const float* __restrict__ A, const float* __restrict__ Wq,
    const float* __restrict__ Wk, const float* __restrict__ Wv,
    float* __restrict__ q, float* __restrict__ k, float* __restrict__ v) {
    int z = blockIdx.z;
    const float* B = (z == 0) ? Wq : (z == 1) ? Wk : Wv;
    float* C = (z == 0) ? q : (z == 1) ? k : v;
    gemm_body<0>(A, B, nullptr, C, Dd, Dd, 0, Dd);
}

// ---------------- flash attention v2: pair-packed f32x2, no broadcast movs -------
// 64 rows/tile; thread owns rows ty*4+r, score cols j = tx+16c, out dims tx, tx+16.
__global__ void __launch_bounds__(256) attn_kernel(
    const float* __restrict__ Qg, const float* __restrict__ Kg, const float* __restrict__ Vg,
    const unsigned char* __restrict__ E8, const float* __restrict__ ebl,
    float* __restrict__ Og) {
    const int h = blockIdx.y;
    const int i0 = blockIdx.x << 6;
    const int tid = threadIdx.x;
    const int tx = tid & 15, ty = tid >> 4;

    __shared__ float Qs[64][36];
    __shared__ float Ks[64][36];
    __shared__ float VsT[32][68];
    __shared__ float Ps[64][68];
    __shared__ float s_eb[8];

    if (tid < NEDGEe) s_eb[tid] = ebl[tid * Hh + h];

#pragma unroll
    for (int it = 0; it < 2; it++) {
        int ff = tid + (it << 8);
        int row = ff >> 3, c4 = (ff & 7) << 2;
        float4 q = *(const float4*)&Qg[(size_t)(i0 + row) * Dd + h * DKk + c4];
        *(float4*)&Qs[row][c4] = q;
    }

    float m[4], l[4];
    u64t o2[4][2];
#pragma unroll
    for (int r = 0; r < 4; r++) {
        m[r] = -1e30f; l[r] = 0.f; o2[r][0] = 0ull; o2[r][1] = 0ull;
    }
    const float scale = 0.17677669529663687f;  // 1/sqrt(32)
    const int sw0 = ((tx >> 2) & 7) << 2;
    const int sw1 = (((tx + 16) >> 2) & 7) << 2;

    for (int jt = 0; jt < Nn; jt += 64) {
        __syncthreads();
#pragma unroll
        for (int it = 0; it < 2; it++) {
            int ff = tid + (it << 8);
            int row = ff >> 3, c4 = (ff & 7) << 2;
            float4 kv = *(const float4*)&Kg[(size_t)(jt + row) * Dd + h * DKk + c4];
            *(float4*)&Ks[row][c4] = kv;
            float4 vv = *(const float4*)&Vg[(size_t)(jt + row) * Dd + h * DKk + c4];
            float vvv[4] = {vv.x, vv.y, vv.z, vv.w};
#pragma unroll
            for (int i = 0; i < 4; i++) {
                int d = c4 + i;
                VsT[d][row ^ (((d >> 2) & 7) << 2)] = vvv[i];
            }
        }
        unsigned e_[4];
#pragma unroll
        for (int r = 0; r < 4; r++) {
            const unsigned char* eb8 = &E8[(size_t)(i0 + (ty << 2) + r) * Nn + jt + tx];
            e_[r] = (unsigned)eb8[0] | ((unsigned)eb8[16] << 8) |
                    ((unsigned)eb8[32] << 16) | ((unsigned)eb8[48] << 24);
        }
        __syncthreads();

        u64t acc2[4][4];
#pragma unroll
        for (int r = 0; r < 4; r++)
#pragma unroll
            for (int c = 0; c < 4; c++) acc2[r][c] = 0ull;

#pragma unroll
        for (int k4 = 0; k4 < DKk; k4 += 4) {
            ulonglong2 qv[4], kv[4];
#pragma unroll
            for (int r = 0; r < 4; r++)
                qv[r] = *(const ulonglong2*)&Qs[(ty << 2) + r][k4];
#pragma unroll
            for (int c = 0; c < 4; c++)
                kv[c] = *(const ulonglong2*)&Ks[tx + (c << 4)][k4];
#pragma unroll
            for (int r = 0; r < 4; r++)
#pragma unroll
                for (int c = 0; c < 4; c++) {
                    acc2[r][c] = ffma2(qv[r].x, kv[c].x, acc2[r][c]);
                    acc2[r][c] = ffma2(qv[r].y, kv[c].y, acc2[r][c]);
                }
        }

        float s[4][4];
#pragma unroll
        for (int r = 0; r < 4; r++)
#pragma unroll
            for (int c = 0; c < 4; c++)
                s[r][c] = fmaf(hsum2(acc2[r][c]), scale, s_eb[(e_[r] >> (c << 3)) & 0xffu]);

#pragma unroll
        for (int r = 0; r < 4; r++) {
            float rm = fmaxf(fmaxf(s[r][0], s[r][1]), fmaxf(s[r][2], s[r][3]));
#pragma unroll
            for (int off = 1; off < 16; off <<= 1)
                rm = fmaxf(rm, __shfl_xor_sync(0xffffffffu, rm, off));
            float mnew = fmaxf(m[r], rm);
            float alpha = __expf(m[r] - mnew);
            m[r] = mnew;
            u64t a2 = bcast2(alpha);
            o2[r][0] = mul2(o2[r][0], a2);
            o2[r][1] = mul2(o2[r][1], a2);
            float ps = 0.f;
#pragma unroll
            for (int c = 0; c < 4; c++) {
                float p = __expf(s[r][c] - mnew);
                ps += p;
                Ps[(ty << 2) + r][tx + (c << 4)] = p;
            }
#pragma unroll
            for (int off = 1; off < 16; off <<= 1)
                ps += __shfl_xor_sync(0xffffffffu, ps, off);
            l[r] = l[r] * alpha + ps;
        }
        __syncthreads();

#pragma unroll 4
        for (int j4 = 0; j4 < 16; j4++) {
            ulonglong2 p2[4];
#pragma unroll
            for (int r = 0; r < 4; r++)
                p2[r] = *(const ulonglong2*)&Ps[(ty << 2) + r][j4 << 2];
            ulonglong2 v20 = *(const ulonglong2*)&VsT[tx][(j4 << 2) ^ sw0];
            ulonglong2 v21 = *(const ulonglong2*)&VsT[tx + 16][(j4 << 2) ^ sw1];
#pragma unroll
            for (int r = 0; r < 4; r++) {
                o2[r][0] = ffma2(p2[r].x, v20.x, o2[r][0]);
                o2[r][0] = ffma2(p2[r].y, v20.y, o2[r][0]);
                o2[r][1] = ffma2(p2[r].x, v21.x, o2[r][1]);
                o2[r][1] = ffma2(p2[r].y, v21.y, o2[r][1]);
            }
        }
    }

#pragma unroll
    for (int r = 0; r < 4; r++) {
        float inv = 1.0f / l[r];
        size_t base = (size_t)(i0 + (ty << 2) + r) * Dd + h * DKk;
        Og[base + tx] = hsum2(o2[r][0]) * inv;
        Og[base + tx + 16] = hsum2(o2[r][1]) * inv;
    }
}

// ---------------- partial reduce + bias + residual + LayerNorm ----------------
template <int S>
__global__ void addln_red_kernel(float* __restrict__ x, const float* __restrict__ part,
                                 const float* __restrict__ bias, const float* __restrict__ g,
                                 const float* __restrict__ b) {
    int i = blockIdx.x, d = threadIdx.x;
    __shared__ float red[256];
    float v = x[i * Dd + d] + bias[d];
#pragma unroll
    for (int s = 0; s < S; s++) v += part[(size_t)s * Nn * Dd + (size_t)i * Dd + d];
    red[d] = v;
    __syncthreads();
    for (int s = 128; s > 0; s >>= 1) {
        if (d < s) red[d] += red[d + s];
        __syncthreads();
    }
    float mean = red[0] * (1.0f / Dd);
    __syncthreads();
    float dv = v - mean;
    red[d] = dv * dv;
    __syncthreads();
    for (int s = 128; s > 0; s >>= 1) {
        if (d < s) red[d] += red[d + s];
        __syncthreads();
    }
    float var = red[0] * (1.0f / Dd);
    x[i * Dd + d] = dv * rsqrtf(var + 1e-5f) * g[d] + b[d];
}

__global__ void pool_kernel(const float* __restrict__ x, float* __restrict__ p) {
    int j = blockIdx.x * 32 + threadIdx.x;
    int yy = threadIdx.y;
    float s = 0.f, mx = -1e30f;
    for (int i = yy; i < Nn; i += 8) {
        float v = x[(size_t)i * Dd + j];
        s += v;
        mx = fmaxf(mx, v);
    }
    __shared__ float ss[8][33], sm[8][33];
    ss[yy][threadIdx.x] = s;
    sm[yy][threadIdx.x] = mx;
    __syncthreads();
    if (yy == 0) {
        for (int k2 = 1; k2 < 8; k2++) {
            s += ss[k2][threadIdx.x];
            mx = fmaxf(mx, sm[k2][threadIdx.x]);
        }
        p[j] = s * (1.0f / Nn);
        p[Dd + j] = mx;
    }
}

__global__ void head_kernel(const float* __restrict__ pooled, const float* __restrict__ Wr,
                            const float* __restrict__ br, float* __restrict__ out) {
    __shared__ float sp[2 * Dd];
    int d = threadIdx.x;
    sp[d] = pooled[d];
    sp[d + Dd] = pooled[d + Dd];
    __syncthreads();
    float acc = br[d];
#pragma unroll 8
    for (int k2 = 0; k2 < 2 * Dd; k2++) acc = fmaf(sp[k2], Wr[(size_t)k2 * Dd + d], acc);
    out[d] = acc;
}

extern "C" void kernel_launch(void* const* d_in, const int* in_sizes, int n_in,
                              void* d_out, int out_size) {
    const int* node_types = (const int*)d_in[0];
    const int* edge_idx = (const int*)d_in[1];
    const float* node_emb = (const float*)d_in[2];
    const float* Wq = (const float*)d_in[3];
    const float* Wk = (const float*)d_in[4];
    const float* Wv = (const float*)d_in[5];
    const float* Wo = (const float*)d_in[6];
    const float* bo = (const float*)d_in[7];
    const float* eb = (const float*)d_in[8];
    const float* W1 = (const float*)d_in[9];
    const float* b1 = (const float*)d_in[10];
    const float* W2 = (const float*)d_in[11];
    const float* b2 = (const float*)d_in[12];
    const float* ln1g = (const float*)d_in[13];
    const float* ln1b = (const float*)d_in[14];
    const float* ln2g = (const float*)d_in[15];
    const float* ln2b = (const float*)d_in[16];
    const float* Wr = (const float*)d_in[17];
    const float* brr = (const float*)d_in[18];
    float* out = (float*)d_out;

    float *x, *q, *k, *v, *att, *t1, *part, *pool;
    unsigned char* e8;
    cudaGetSymbolAddress((void**)&x, g_x);
    cudaGetSymbolAddress((void**)&q, g_q);
    cudaGetSymbolAddress((void**)&k, g_k);
    cudaGetSymbolAddress((void**)&v, g_v);
    cudaGetSymbolAddress((void**)&att, g_att);
    cudaGetSymbolAddress((void**)&t1, g_t1);
    cudaGetSymbolAddress((void**)&part, g_part);
    cudaGetSymbolAddress((void**)&pool, g_pool);
    cudaGetSymbolAddress((void**)&e8, g_e8);

    embed_kernel<<<Nn, Dd>>>(node_types, node_emb, x);
    cvt_e8_kernel<<<(Nn * Nn / 4) / 256, 256>>>(edge_idx, e8);

    for (int l = 0; l < Ll; l++) {
        gemm_qkv_kernel<<<dim3(4, 16, 3), 256>>>(x, Wq + (size_t)l * Dd * Dd,
                                                 Wk + (size_t)l * Dd * Dd,
                                                 Wv + (size_t)l * Dd * Dd, q, k, v);

        attn_kernel<<<dim3(Nn / 64, Hh), 256>>>(q, k, v, e8, eb + l * NEDGEe * Hh, att);

        gemm_kernel<0, 4><<<dim3(4, 16, 4), 256>>>(att, Wo + (size_t)l * Dd * Dd, nullptr,
                                                   part, Dd, Dd);
        addln_red_kernel<4><<<Nn, Dd>>>(x, part, bo + l * Dd, ln1g + l * Dd, ln1b + l * Dd);

        gemm_kernel<1, 1><<<dim3(16, 16, 1), 256>>>(x, W1 + (size_t)l * Dd * DFFf,
                                                    b1 + l * DFFf, t1, Dd, DFFf);
        gemm_kernel<0, 4><<<dim3(4, 16, 4), 256>>>(t1, W2 + (size_t)l * DFFf * Dd, nullptr,
                                                   part, DFFf, Dd);
        addln_red_kernel<4><<<Nn, Dd>>>(x, part, b2 + l * Dd, ln2g + l * Dd, ln2b + l * Dd);
    }

    pool_kernel<<<Dd / 32, dim3(32, 8)>>>(x, pool);
    head_kernel<<<1, Dd>>>(pool, Wr, brr, out);
}

// round 8
// speedup vs baseline: 1.1269x; 1.1235x over previous
#include <cuda_runtime.h>
#include <cuda_bf16.h>
#include <stdint.h>
#include <math.h>

#define Nn 2048
#define Dd 256
#define Hh 8
#define DKk 32
#define Ll 4
#define DFFf 1024
#define NEDGEe 5

typedef unsigned long long u64t;
typedef __nv_bfloat16 bf16;

// ---------------- portable helpers ----------------
__device__ __forceinline__ uint32_t smem_u32(const void* p) {
    uint32_t a;
    asm("{ .reg .u64 t; cvta.to.shared.u64 t, %1; cvt.u32.u64 %0, t; }" : "=r"(a) : "l"(p));
    return a;
}
__device__ __forceinline__ void ldsm4(uint32_t& r0, uint32_t& r1, uint32_t& r2, uint32_t& r3,
                                      uint32_t addr) {
    asm volatile("ldmatrix.sync.aligned.m8n8.x4.shared.b16 {%0,%1,%2,%3}, [%4];"
                 : "=r"(r0), "=r"(r1), "=r"(r2), "=r"(r3)
                 : "r"(addr));
}
__device__ __forceinline__ void mma_bf16(float* d, const uint32_t* a, const uint32_t* b) {
    asm volatile(
        "mma.sync.aligned.m16n8k16.row.col.f32.bf16.bf16.f32 "
        "{%0,%1,%2,%3}, {%4,%5,%6,%7}, {%8,%9}, {%0,%1,%2,%3};"
        : "+f"(d[0]), "+f"(d[1]), "+f"(d[2]), "+f"(d[3])
        : "r"(a[0]), "r"(a[1]), "r"(a[2]), "r"(a[3]), "r"(b[0]), "r"(b[1]));
}
__device__ __forceinline__ u64t ffma2(u64t a, u64t b, u64t c) {
    u64t d;
    asm("fma.rn.f32x2 %0, %1, %2, %3;" : "=l"(d) : "l"(a), "l"(b), "l"(c));
    return d;
}
__device__ __forceinline__ u64t bcast2(float x) {
    u64t r;
    asm("mov.b64 %0, {%1, %1};" : "=l"(r) : "f"(x), "f"(x));
    return r;
}
union f2u { u64t u; float2 f; };

// ---------------- scratch ----------------
__device__ float g_x[Nn * Dd];
__device__ float g_q[Nn * Dd];
__device__ float g_k[Nn * Dd];
__device__ float g_v[Nn * Dd];
__device__ float g_part[2 * Nn * Dd];
__device__ unsigned char g_e8[Nn * Nn];
__device__ float g_pool[2 * Dd];
__device__ bf16 g_xh[Nn * Dd], g_xl[Nn * Dd];
__device__ bf16 g_atth[Nn * Dd], g_attl[Nn * Dd];
__device__ bf16 g_t1h[Nn * DFFf], g_t1l[Nn * DFFf];
__device__ bf16 g_wqh[Ll * Dd * Dd], g_wql[Ll * Dd * Dd];
__device__ bf16 g_wkh[Ll * Dd * Dd], g_wkl[Ll * Dd * Dd];
__device__ bf16 g_wvh[Ll * Dd * Dd], g_wvl[Ll * Dd * Dd];
__device__ bf16 g_woh[Ll * Dd * Dd], g_wol[Ll * Dd * Dd];
__device__ bf16 g_w1h[Ll * Dd * DFFf], g_w1l[Ll * Dd * DFFf];
__device__ bf16 g_w2h[Ll * DFFf * Dd], g_w2l[Ll * DFFf * Dd];

// ---------------- embedding gather (+split) ----------------
__global__ void embed_kernel(const int* __restrict__ nt, const float* __restrict__ emb,
                             float* __restrict__ x, bf16* __restrict__ xh, bf16* __restrict__ xl) {
    int i = blockIdx.x;
    int d = threadIdx.x;
    float v = emb[nt[i] * Dd + d];
    x[i * Dd + d] = v;
    bf16 h = __float2bfloat16(v);
    xh[i * Dd + d] = h;
    xl[i * Dd + d] = __float2bfloat16(v - __bfloat162float(h));
}

__global__ void cvt_e8_kernel(const int* __restrict__ e, unsigned char* __restrict__ o) {
    int i = blockIdx.x * blockDim.x + threadIdx.x;
    int4 v = ((const int4*)e)[i];
    uchar4 u;
    u.x = (unsigned char)v.x; u.y = (unsigned char)v.y;
    u.z = (unsigned char)v.z; u.w = (unsigned char)v.w;
    ((uchar4*)o)[i] = u;
}

// ---------------- weight transpose + split: W[L][Kd][Nc] -> T{h,l}[L][Nc][Kd] ----------------
__global__ void wsplit_kernel(const float* __restrict__ W, bf16* __restrict__ Th,
                              bf16* __restrict__ Tl, int Kd, int Nc) {
    __shared__ float sh[32][33], slo[32][33];
    const float* Wl = W + (size_t)blockIdx.z * Kd * Nc;
    bf16* Thl = Th + (size_t)blockIdx.z * Kd * Nc;
    bf16* Tll = Tl + (size_t)blockIdx.z * Kd * Nc;
    int n0 = blockIdx.x << 5, k0 = blockIdx.y << 5;
    int tx = threadIdx.x, ty = threadIdx.y;
#pragma unroll
    for (int r = 0; r < 4; r++) {
        int kk = ty + (r << 3);
        float v = Wl[(size_t)(k0 + kk) * Nc + n0 + tx];
        float h = __bfloat162float(__float2bfloat16(v));
        sh[kk][tx] = h;
        slo[kk][tx] = v - h;
    }
    __syncthreads();
#pragma unroll
    for (int r = 0; r < 4; r++) {
        int nn = ty + (r << 3);
        Thl[(size_t)(n0 + nn) * Kd + k0 + tx] = __float2bfloat16(sh[tx][nn]);
        Tll[(size_t)(n0 + nn) * Kd + k0 + tx] = __float2bfloat16(slo[tx][nn]);
    }
}

// ---------------- split-bf16 HMMA GEMM (mma.sync m16n8k16) ----------------
// C tile [128 x 64] = A[:, kbeg:kbeg+kslice] @ B^T. A hi/lo [rows][Kd], B hi/lo [Nc][Kd].
// 256 threads = 8 warps in 4(m) x 2(n); warp tile 32x32 = 2x4 m16n8 frags.
template <int ACT, int OSPLIT>
__device__ __forceinline__ void hmma_gemm_body(
    const bf16* __restrict__ Ah, const bf16* __restrict__ Al,
    const bf16* __restrict__ Bh, const bf16* __restrict__ Bl,
    const float* __restrict__ bias, float* __restrict__ Cf,
    bf16* __restrict__ Ch, bf16* __restrict__ Cl,
    int Kd, int kbeg, int kslice, int Nc) {
    __shared__ bf16 sAh[128][40], sAl[128][40], sBh[64][40], sBl[64][40];
    const int tid = threadIdx.x;
    const int wid = tid >> 5, lane = tid & 31;
    const int i0 = blockIdx.y << 7, j0 = blockIdx.x << 6;
    const int mw = (wid & 3) << 5;
    const int nw = (wid >> 2) << 5;

    float acc[2][4][4];
#pragma unroll
    for (int a = 0; a < 2; a++)
#pragma unroll
        for (int b = 0; b < 4; b++)
#pragma unroll
            for (int cc = 0; cc < 4; cc++) acc[a][b][cc] = 0.f;

    // ldmatrix lane->row/k mapping (PTX m8n8.x4 matrix order)
    const int a_r = lane & 15;
    const int a_k = (lane >> 4) << 3;
    const int b_n = (lane & 7) + ((lane & 16) >> 1);
    const int b_k = lane & 8;

    const uint32_t uAh = smem_u32(&sAh[0][0]);
    const uint32_t uAl = smem_u32(&sAl[0][0]);
    const uint32_t uBh = smem_u32(&sBh[0][0]);
    const uint32_t uBl = smem_u32(&sBl[0][0]);

    // stage mapping: 2 threads per row, each thread covers 16 bf16 (2x uint4)
    const int r = tid >> 1, hf = (tid & 1) << 4;
    const int tb = tid & 127;
    const int rb = tb >> 1, hb = (tb & 1) << 4;

    const int nch = kslice >> 5;
    for (int c = 0; c < nch; c++) {
        int kt = kbeg + (c << 5);
        if (c) __syncthreads();
        {
            const bf16* pAh = Ah + (size_t)(i0 + r) * Kd + kt + hf;
            const bf16* pAl = Al + (size_t)(i0 + r) * Kd + kt + hf;
            *(uint4*)&sAh[r][hf] = *(const uint4*)pAh;
            *(uint4*)&sAh[r][hf + 8] = *(const uint4*)(pAh + 8);
            *(uint4*)&sAl[r][hf] = *(const uint4*)pAl;
            *(uint4*)&sAl[r][hf + 8] = *(const uint4*)(pAl + 8);
        }
        if (tid < 128) {
            const bf16* pBh = Bh + (size_t)(j0 + rb) * Kd + kt + hb;
            *(uint4*)&sBh[rb][hb] = *(const uint4*)pBh;
            *(uint4*)&sBh[rb][hb + 8] = *(const uint4*)(pBh + 8);
        } else {
            const bf16* pBl = Bl + (size_t)(j0 + rb) * Kd + kt + hb;
            *(uint4*)&sBl[rb][hb] = *(const uint4*)pBl;
            *(uint4*)&sBl[rb][hb + 8] = *(const uint4*)(pBl + 8);
        }
        __syncthreads();
#pragma unroll
        for (int ks = 0; ks < 2; ks++) {
            const int kk = ks << 4;
            uint32_t ah[2][4], al[2][4], bhf[2][4], blf[2][4];
#pragma unroll
            for (int mf = 0; mf < 2; mf++) {
                uint32_t off = (uint32_t)(((mw + (mf << 4) + a_r) * 40 + kk + a_k) << 1);
                ldsm4(ah[mf][0], ah[mf][1], ah[mf][2], ah[mf][3], uAh + off);
                ldsm4(al[mf][0], al[mf][1], al[mf][2], al[mf][3], uAl + off);
            }
#pragma unroll
            for (int g = 0; g < 2; g++) {
                uint32_t off = (uint32_t)(((nw + (g << 4) + b_n) * 40 + kk + b_k) << 1);
                ldsm4(bhf[g][0], bhf[g][1], bhf[g][2], bhf[g][3], uBh + off);
                ldsm4(blf[g][0], blf[g][1], blf[g][2], blf[g][3], uBl + off);
            }
#pragma unroll
            for (int mf = 0; mf < 2; mf++)
#pragma unroll
                for (int nf = 0; nf < 4; nf++) {
                    const uint32_t* ph = &bhf[nf >> 1][(nf & 1) << 1];
                    const uint32_t* pl = &blf[nf >> 1][(nf & 1) << 1];
                    mma_bf16(acc[mf][nf], ah[mf], ph);
                    mma_bf16(acc[mf][nf], ah[mf], pl);
                    mma_bf16(acc[mf][nf], al[mf], ph);
                }
        }
    }

    // epilogue
    const int lr = lane >> 2, lc = (lane & 3) << 1;
#pragma unroll
    for (int mf = 0; mf < 2; mf++)
#pragma unroll
        for (int rp = 0; rp < 2; rp++) {
            int row = i0 + mw + (mf << 4) + lr + (rp << 3);
#pragma unroll
            for (int nf = 0; nf < 4; nf++) {
                float v0 = acc[mf][nf][(rp << 1) + 0];
                float v1 = acc[mf][nf][(rp << 1) + 1];
                int col = j0 + nw + (nf << 3) + lc;
                if (OSPLIT == 0) {
                    if (bias) {
                        v0 += bias[col];
                        v1 += bias[col + 1];
                    }
                    *(float2*)&Cf[(size_t)row * Nc + col] = make_float2(v0, v1);
                } else {
                    v0 += bias[col];
                    v1 += bias[col + 1];
                    if (ACT == 1) {
                        v0 = 0.5f * v0 * (1.0f + erff(v0 * 0.70710678118654752f));
                        v1 = 0.5f * v1 * (1.0f + erff(v1 * 0.70710678118654752f));
                    }
                    bf16 h0 = __float2bfloat16(v0), h1 = __float2bfloat16(v1);
                    Ch[(size_t)row * Nc + col] = h0;
                    Ch[(size_t)row * Nc + col + 1] = h1;
                    Cl[(size_t)row * Nc + col] = __float2bfloat16(v0 - __bfloat162float(h0));
                    Cl[(size_t)row * Nc + col + 1] = __float2bfloat16(v1 - __bfloat162float(h1));
                }
            }
        }
}

template <int ACT, int SPLIT, int OSPLIT>
__global__ void __launch_bounds__(256) hmma_gemm_kernel(
    const bf16* __restrict__ Ah, const bf16* __restrict__ Al,
    const bf16* __restrict__ Bh, const bf16* __restrict__ Bl,
    const float* __restrict__ bias, float* __restrict__ Cf,
    bf16* __restrict__ Ch, bf16* __restrict__ Cl, int Kd, int Nc) {
    int kslice = Kd / SPLIT;
    int kbeg = blockIdx.z * kslice;
    float* Cz = (SPLIT > 1) ? Cf + (size_t)blockIdx.z * Nn * Nc : Cf;
    hmma_gemm_body<ACT, OSPLIT>(Ah, Al, Bh, Bl, SPLIT > 1 ? nullptr : bias, Cz, Ch, Cl,
                                Kd, kbeg, kslice, Nc);
}

__global__ void __launch_bounds__(256) hmma_qkv_kernel(
    const bf16* __restrict__ Ah, const bf16* __restrict__ Al,
    const bf16* __restrict__ Bh0, const bf16* __restrict__ Bl0,
    const bf16* __restrict__ Bh1, const bf16* __restrict__ Bl1,
    const bf16* __restrict__ Bh2, const bf16* __restrict__ Bl2,
    float* __restrict__ C0, float* __restrict__ C1, float* __restrict__ C2) {
    int z = blockIdx.z;
    const bf16* Bh = (z == 0) ? Bh0 : (z == 1) ? Bh1 : Bh2;
    const bf16* Bl = (z == 0) ? Bl0 : (z == 1) ? Bl1 : Bl2;
    float* C = (z == 0) ? C0 : (z == 1) ? C1 : C2;
    hmma_gemm_body<0, 0>(Ah, Al, Bh, Bl, nullptr, C, nullptr, nullptr, Dd, 0, Dd, Dd);
}

// ---------------- flash attention (v1 layout) + bf16 split output ----------------
__global__ void __launch_bounds__(256) attn_kernel(
    const float* __restrict__ Qg, const float* __restrict__ Kg, const float* __restrict__ Vg,
    const unsigned char* __restrict__ E8, const float* __restrict__ ebl,
    bf16* __restrict__ Oh, bf16* __restrict__ Ol) {
    const int h = blockIdx.y;
    const int i0 = blockIdx.x << 6;
    const int tid = threadIdx.x;
    const int tx = tid & 15, ty = tid >> 4;

    __shared__ float QsT[DKk][64];
    __shared__ float KsT[DKk][64];
    __shared__ float Vs[64][DKk];
    __shared__ float Ps[64][65];
    __shared__ float s_eb[8];

    if (tid < NEDGEe) s_eb[tid] = ebl[tid * Hh + h];

#pragma unroll
    for (int it = 0; it < 2; it++) {
        int ff = tid + it * 256;
        int row = ff >> 3, c4 = (ff & 7) << 2;
        float4 q = *(const float4*)&Qg[(size_t)(i0 + row) * Dd + h * DKk + c4];
        QsT[c4 + 0][row] = q.x;
        QsT[c4 + 1][row] = q.y;
        QsT[c4 + 2][row] = q.z;
        QsT[c4 + 3][row] = q.w;
    }

    float m[4], l[4], o[4][2];
#pragma unroll
    for (int r = 0; r < 4; r++) {
        m[r] = -1e30f; l[r] = 0.f; o[r][0] = 0.f; o[r][1] = 0.f;
    }
    const float scale = 0.17677669529663687f;

    for (int jt = 0; jt < Nn; jt += 64) {
        __syncthreads();
#pragma unroll
        for (int it = 0; it < 2; it++) {
            int ff = tid + it * 256;
            int row = ff >> 3, c4 = (ff & 7) << 2;
            float4 kv = *(const float4*)&Kg[(size_t)(jt + row) * Dd + h * DKk + c4];
            KsT[c4 + 0][row] = kv.x;
            KsT[c4 + 1][row] = kv.y;
            KsT[c4 + 2][row] = kv.z;
            KsT[c4 + 3][row] = kv.w;
            float4 vv = *(const float4*)&Vg[(size_t)(jt + row) * Dd + h * DKk + c4];
            *(float4*)&Vs[row][c4] = vv;
        }
        __syncthreads();

        u64t s2[4][2];
#pragma unroll
        for (int r = 0; r < 4; r++) { s2[r][0] = 0ull; s2[r][1] = 0ull; }
#pragma unroll
        for (int k = 0; k < DKk; k++) {
            float4 a = *(const float4*)&QsT[k][ty << 2];
            ulonglong2 b = *(const ulonglong2*)&KsT[k][tx << 2];
            u64t a0 = bcast2(a.x), a1 = bcast2(a.y), a2 = bcast2(a.z), a3 = bcast2(a.w);
            s2[0][0] = ffma2(a0, b.x, s2[0][0]);
            s2[0][1] = ffma2(a0, b.y, s2[0][1]);
            s2[1][0] = ffma2(a1, b.x, s2[1][0]);
            s2[1][1] = ffma2(a1, b.y, s2[1][1]);
            s2[2][0] = ffma2(a2, b.x, s2[2][0]);
            s2[2][1] = ffma2(a2, b.y, s2[2][1]);
            s2[3][0] = ffma2(a3, b.x, s2[3][0]);
            s2[3][1] = ffma2(a3, b.y, s2[3][1]);
        }

        float s[4][4];
#pragma unroll
        for (int r = 0; r < 4; r++) {
            f2u c0, c1;
            c0.u = s2[r][0];
            c1.u = s2[r][1];
            s[r][0] = c0.f.x; s[r][1] = c0.f.y; s[r][2] = c1.f.x; s[r][3] = c1.f.y;
        }

#pragma unroll
        for (int r = 0; r < 4; r++) {
            unsigned int e4 =
                *(const unsigned int*)&E8[(size_t)(i0 + (ty << 2) + r) * Nn + jt + (tx << 2)];
            s[r][0] = fmaf(s[r][0], scale, s_eb[e4 & 0xffu]);
            s[r][1] = fmaf(s[r][1], scale, s_eb[(e4 >> 8) & 0xffu]);
            s[r][2] = fmaf(s[r][2], scale, s_eb[(e4 >> 16) & 0xffu]);
            s[r][3] = fmaf(s[r][3], scale, s_eb[(e4 >> 24) & 0xffu]);
        }

#pragma unroll
        for (int r = 0; r < 4; r++) {
            float rm = fmaxf(fmaxf(s[r][0], s[r][1]), fmaxf(s[r][2], s[r][3]));
#pragma unroll
            for (int off = 1; off < 16; off <<= 1)
                rm = fmaxf(rm, __shfl_xor_sync(0xffffffffu, rm, off));
            float mnew = fmaxf(m[r], rm);
            float alpha = __expf(m[r] - mnew);
            m[r] = mnew;
            o[r][0] *= alpha;
            o[r][1] *= alpha;
            float ps = 0.f;
#pragma unroll
            for (int c = 0; c < 4; c++) {
                float p = __expf(s[r][c] - mnew);
                ps += p;
                Ps[(ty << 2) + r][(tx << 2) + c] = p;
            }
#pragma unroll
            for (int off = 1; off < 16; off <<= 1)
                ps += __shfl_xor_sync(0xffffffffu, ps, off);
            l[r] = l[r] * alpha + ps;
        }
        __syncthreads();

#pragma unroll 4
        for (int j = 0; j < 64; j++) {
            float2 v = *(const float2*)&Vs[j][tx << 1];
#pragma unroll
            for (int r = 0; r < 4; r++) {
                float p = Ps[(ty << 2) + r][j];
                o[r][0] = fmaf(p, v.x, o[r][0]);
                o[r][1] = fmaf(p, v.y, o[r][1]);
            }
        }
    }

#pragma unroll
    for (int r = 0; r < 4; r++) {
        float inv = 1.0f / l[r];
        size_t basei = (size_t)(i0 + (ty << 2) + r) * Dd + h * DKk + (tx << 1);
        float v0 = o[r][0] * inv, v1 = o[r][1] * inv;
        bf16 h0 = __float2bfloat16(v0), h1 = __float2bfloat16(v1);
        Oh[basei] = h0;
        Oh[basei + 1] = h1;
        Ol[basei] = __float2bfloat16(v0 - __bfloat162float(h0));
        Ol[basei + 1] = __float2bfloat16(v1 - __bfloat162float(h1));
    }
}

// ---------------- partial reduce + bias + residual + LayerNorm (+split out) ----------------
template <int S>
__global__ void addln_red_kernel(float* __restrict__ x, const float* __restrict__ part,
                                 const float* __restrict__ bias, const float* __restrict__ g,
                                 const float* __restrict__ b, bf16* __restrict__ xh,
                                 bf16* __restrict__ xl) {
    int i = blockIdx.x, d = threadIdx.x;
    __shared__ float red[256];
    float v = x[i * Dd + d] + bias[d];
#pragma unroll
    for (int s = 0; s < S; s++) v += part[(size_t)s * Nn * Dd + (size_t)i * Dd + d];
    red[d] = v;
    __syncthreads();
    for (int s = 128; s > 0; s >>= 1) {
        if (d < s) red[d] += red[d + s];
        __syncthreads();
    }
    float mean = red[0] * (1.0f / Dd);
    __syncthreads();
    float dv = v - mean;
    red[d] = dv * dv;
    __syncthreads();
    for (int s = 128; s > 0; s >>= 1) {
        if (d < s) red[d] += red[d + s];
        __syncthreads();
    }
    float var = red[0] * (1.0f / Dd);
    float outv = dv * rsqrtf(var + 1e-5f) * g[d] + b[d];
    x[i * Dd + d] = outv;
    bf16 h = __float2bfloat16(outv);
    xh[i * Dd + d] = h;
    xl[i * Dd + d] = __float2bfloat16(outv - __bfloat162float(h));
}

__global__ void pool_kernel(const float* __restrict__ x, float* __restrict__ p) {
    int j = blockIdx.x * 32 + threadIdx.x;
    int yy = threadIdx.y;
    float s = 0.f, mx = -1e30f;
    for (int i = yy; i < Nn; i += 8) {
        float v = x[(size_t)i * Dd + j];
        s += v;
        mx = fmaxf(mx, v);
    }
    __shared__ float ss[8][33], sm[8][33];
    ss[yy][threadIdx.x] = s;
    sm[yy][threadIdx.x] = mx;
    __syncthreads();
    if (yy == 0) {
        for (int k2 = 1; k2 < 8; k2++) {
            s += ss[k2][threadIdx.x];
            mx = fmaxf(mx, sm[k2][threadIdx.x]);
        }
        p[j] = s * (1.0f / Nn);
        p[Dd + j] = mx;
    }
}

__global__ void head_kernel(const float* __restrict__ pooled, const float* __restrict__ Wr,
                            const float* __restrict__ br, float* __restrict__ out) {
    __shared__ float sp[2 * Dd];
    int d = threadIdx.x;
    sp[d] = pooled[d];
    sp[d + Dd] = pooled[d + Dd];
    __syncthreads();
    float acc = br[d];
#pragma unroll 8
    for (int k2 = 0; k2 < 2 * Dd; k2++) acc = fmaf(sp[k2], Wr[(size_t)k2 * Dd + d], acc);
    out[d] = acc;
}

// ---------------- host launcher ----------------
extern "C" void kernel_launch(void* const* d_in, const int* in_sizes, int n_in,
                              void* d_out, int out_size) {
    const int* node_types = (const int*)d_in[0];
    const int* edge_idx = (const int*)d_in[1];
    const float* node_emb = (const float*)d_in[2];
    const float* Wq = (const float*)d_in[3];
    const float* Wk = (const float*)d_in[4];
    const float* Wv = (const float*)d_in[5];
    const float* Wo = (const float*)d_in[6];
    const float* bo = (const float*)d_in[7];
    const float* eb = (const float*)d_in[8];
    const float* W1 = (const float*)d_in[9];
    const float* b1 = (const float*)d_in[10];
    const float* W2 = (const float*)d_in[11];
    const float* b2 = (const float*)d_in[12];
    const float* ln1g = (const float*)d_in[13];
    const float* ln1b = (const float*)d_in[14];
    const float* ln2g = (const float*)d_in[15];
    const float* ln2b = (const float*)d_in[16];
    const float* Wr = (const float*)d_in[17];
    const float* brr = (const float*)d_in[18];
    float* out = (float*)d_out;

    float *x, *q, *k, *v, *part, *pool;
    unsigned char* e8;
    bf16 *xh, *xl, *atth, *attl, *t1h, *t1l;
    bf16 *wqh, *wql, *wkh, *wkl, *wvh, *wvl, *woh, *wol, *w1h, *w1l, *w2h, *w2l;
    cudaGetSymbolAddress((void**)&x, g_x);
    cudaGetSymbolAddress((void**)&q, g_q);
    cudaGetSymbolAddress((void**)&k, g_k);
    cudaGetSymbolAddress((void**)&v, g_v);
    cudaGetSymbolAddress((void**)&part, g_part);
    cudaGetSymbolAddress((void**)&pool, g_pool);
    cudaGetSymbolAddress((void**)&e8, g_e8);
    cudaGetSymbolAddress((void**)&xh, g_xh);
    cudaGetSymbolAddress((void**)&xl, g_xl);
    cudaGetSymbolAddress((void**)&atth, g_atth);
    cudaGetSymbolAddress((void**)&attl, g_attl);
    cudaGetSymbolAddress((void**)&t1h, g_t1h);
    cudaGetSymbolAddress((void**)&t1l, g_t1l);
    cudaGetSymbolAddress((void**)&wqh, g_wqh);
    cudaGetSymbolAddress((void**)&wql, g_wql);
    cudaGetSymbolAddress((void**)&wkh, g_wkh);
    cudaGetSymbolAddress((void**)&wkl, g_wkl);
    cudaGetSymbolAddress((void**)&wvh, g_wvh);
    cudaGetSymbolAddress((void**)&wvl, g_wvl);
    cudaGetSymbolAddress((void**)&woh, g_woh);
    cudaGetSymbolAddress((void**)&wol, g_wol);
    cudaGetSymbolAddress((void**)&w1h, g_w1h);
    cudaGetSymbolAddress((void**)&w1l, g_w1l);
    cudaGetSymbolAddress((void**)&w2h, g_w2h);
    cudaGetSymbolAddress((void**)&w2l, g_w2l);

    embed_kernel<<<Nn, Dd>>>(node_types, node_emb, x, xh, xl);
    cvt_e8_kernel<<<(Nn * Nn / 4) / 256, 256>>>(edge_idx, e8);

    wsplit_kernel<<<dim3(8, 8, Ll), dim3(32, 8)>>>(Wq, wqh, wql, Dd, Dd);
    wsplit_kernel<<<dim3(8, 8, Ll), dim3(32, 8)>>>(Wk, wkh, wkl, Dd, Dd);
    wsplit_kernel<<<dim3(8, 8, Ll), dim3(32, 8)>>>(Wv, wvh, wvl, Dd, Dd);
    wsplit_kernel<<<dim3(8, 8, Ll), dim3(32, 8)>>>(Wo, woh, wol, Dd, Dd);
    wsplit_kernel<<<dim3(32, 8, Ll), dim3(32, 8)>>>(W1, w1h, w1l, Dd, DFFf);
    wsplit_kernel<<<dim3(8, 32, Ll), dim3(32, 8)>>>(W2, w2h, w2l, DFFf, Dd);

    for (int l = 0; l < Ll; l++) {
        size_t wo256 = (size_t)l * Dd * Dd;
        size_t woff1 = (size_t)l * Dd * DFFf;
        hmma_qkv_kernel<<<dim3(4, 16, 3), 256>>>(
            xh, xl, wqh + wo256, wql + wo256, wkh + wo256, wkl + wo256, wvh + wo256,
            wvl + wo256, q, k, v);

        attn_kernel<<<dim3(Nn / 64, Hh), 256>>>(q, k, v, e8, eb + l * NEDGEe * Hh, atth, attl);

        hmma_gemm_kernel<0, 2, 0><<<dim3(4, 16, 2), 256>>>(
            atth, attl, woh + wo256, wol + wo256, nullptr, part, nullptr, nullptr, Dd, Dd);
        addln_red_kernel<2><<<Nn, Dd>>>(x, part, bo + l * Dd, ln1g + l * Dd, ln1b + l * Dd, xh,
                                        xl);

        hmma_gemm_kernel<1, 1, 1><<<dim3(16, 16, 1), 256>>>(
            xh, xl, w1h + woff1, w1l + woff1, b1 + l * DFFf, nullptr, t1h, t1l, Dd, DFFf);

        hmma_gemm_kernel<0, 2, 0><<<dim3(4, 16, 2), 256>>>(
            t1h, t1l, w2h + woff1, w2l + woff1, nullptr, part, nullptr, nullptr, DFFf, Dd);
        addln_red_kernel<2><<<Nn, Dd>>>(x, part, b2 + l * Dd, ln2g + l * Dd, ln2b + l * Dd, xh,
                                        xl);
    }

    pool_kernel<<<Dd / 32, dim3(32, 8)>>>(x, pool);
    head_kernel<<<1, Dd>>>(pool, Wr, brr, out);
}

// round 9
// speedup vs baseline: 1.4551x; 1.2913x over previous
#include <cuda_runtime.h>
#include <cuda_bf16.h>
#include <stdint.h>
#include <math.h>

#define Nn 2048
#define Dd 256
#define Hh 8
#define DKk 32
#define Ll 4
#define DFFf 1024
#define NEDGEe 5

typedef __nv_bfloat16 bf16;

// ---------------- portable MMA helpers (validated in R8 GEMM) ----------------
__device__ __forceinline__ uint32_t smem_u32(const void* p) {
    uint32_t a;
    asm("{ .reg .u64 t; cvta.to.shared.u64 t, %1; cvt.u32.u64 %0, t; }" : "=r"(a) : "l"(p));
    return a;
}
__device__ __forceinline__ void ldsm4(uint32_t& r0, uint32_t& r1, uint32_t& r2, uint32_t& r3,
                                      uint32_t addr) {
    asm volatile("ldmatrix.sync.aligned.m8n8.x4.shared.b16 {%0,%1,%2,%3}, [%4];"
                 : "=r"(r0), "=r"(r1), "=r"(r2), "=r"(r3)
                 : "r"(addr));
}
__device__ __forceinline__ void mma_bf16(float* d, const uint32_t* a, const uint32_t* b) {
    asm volatile(
        "mma.sync.aligned.m16n8k16.row.col.f32.bf16.bf16.f32 "
        "{%0,%1,%2,%3}, {%4,%5,%6,%7}, {%8,%9}, {%0,%1,%2,%3};"
        : "+f"(d[0]), "+f"(d[1]), "+f"(d[2]), "+f"(d[3])
        : "r"(a[0]), "r"(a[1]), "r"(a[2]), "r"(a[3]), "r"(b[0]), "r"(b[1]));
}
__device__ __forceinline__ uint32_t pack2bf(float a, float b) {
    unsigned short lo = __bfloat16_as_ushort(__float2bfloat16(a));
    unsigned short hi = __bfloat16_as_ushort(__float2bfloat16(b));
    return ((uint32_t)hi << 16) | (uint32_t)lo;
}

// ---------------- scratch ----------------
__device__ float g_x[Nn * Dd];
__device__ float g_part[2 * Nn * Dd];
__device__ unsigned char g_e8[Nn * Nn];
__device__ float g_pool[2 * Dd];
__device__ bf16 g_xh[Nn * Dd], g_xl[Nn * Dd];
__device__ bf16 g_qh[Nn * Dd], g_ql[Nn * Dd];
__device__ bf16 g_kh[Nn * Dd], g_kl[Nn * Dd];
__device__ bf16 g_vh[Nn * Dd], g_vl[Nn * Dd];
__device__ bf16 g_atth[Nn * Dd], g_attl[Nn * Dd];
__device__ bf16 g_t1h[Nn * DFFf], g_t1l[Nn * DFFf];
__device__ bf16 g_wqh[Ll * Dd * Dd], g_wql[Ll * Dd * Dd];
__device__ bf16 g_wkh[Ll * Dd * Dd], g_wkl[Ll * Dd * Dd];
__device__ bf16 g_wvh[Ll * Dd * Dd], g_wvl[Ll * Dd * Dd];
__device__ bf16 g_woh[Ll * Dd * Dd], g_wol[Ll * Dd * Dd];
__device__ bf16 g_w1h[Ll * Dd * DFFf], g_w1l[Ll * Dd * DFFf];
__device__ bf16 g_w2h[Ll * DFFf * Dd], g_w2l[Ll * DFFf * Dd];

// ---------------- embedding gather (+split) ----------------
__global__ void embed_kernel(const int* __restrict__ nt, const float* __restrict__ emb,
                             float* __restrict__ x, bf16* __restrict__ xh, bf16* __restrict__ xl) {
    int i = blockIdx.x;
    int d = threadIdx.x;
    float v = emb[nt[i] * Dd + d];
    x[i * Dd + d] = v;
    bf16 h = __float2bfloat16(v);
    xh[i * Dd + d] = h;
    xl[i * Dd + d] = __float2bfloat16(v - __bfloat162float(h));
}

__global__ void cvt_e8_kernel(const int* __restrict__ e, unsigned char* __restrict__ o) {
    int i = blockIdx.x * blockDim.x + threadIdx.x;
    int4 v = ((const int4*)e)[i];
    uchar4 u;
    u.x = (unsigned char)v.x; u.y = (unsigned char)v.y;
    u.z = (unsigned char)v.z; u.w = (unsigned char)v.w;
    ((uchar4*)o)[i] = u;
}

// ---------------- weight transpose + split: W[L][Kd][Nc] -> T{h,l}[L][Nc][Kd] ----------------
__global__ void wsplit_kernel(const float* __restrict__ W, bf16* __restrict__ Th,
                              bf16* __restrict__ Tl, int Kd, int Nc) {
    __shared__ float sh[32][33], slo[32][33];
    const float* Wl = W + (size_t)blockIdx.z * Kd * Nc;
    bf16* Thl = Th + (size_t)blockIdx.z * Kd * Nc;
    bf16* Tll = Tl + (size_t)blockIdx.z * Kd * Nc;
    int n0 = blockIdx.x << 5, k0 = blockIdx.y << 5;
    int tx = threadIdx.x, ty = threadIdx.y;
#pragma unroll
    for (int r = 0; r < 4; r++) {
        int kk = ty + (r << 3);
        float v = Wl[(size_t)(k0 + kk) * Nc + n0 + tx];
        float h = __bfloat162float(__float2bfloat16(v));
        sh[kk][tx] = h;
        slo[kk][tx] = v - h;
    }
    __syncthreads();
#pragma unroll
    for (int r = 0; r < 4; r++) {
        int nn = ty + (r << 3);
        Thl[(size_t)(n0 + nn) * Kd + k0 + tx] = __float2bfloat16(sh[tx][nn]);
        Tll[(size_t)(n0 + nn) * Kd + k0 + tx] = __float2bfloat16(slo[tx][nn]);
    }
}

// ---------------- split-bf16 HMMA GEMM (mma.sync m16n8k16) ----------------
// OSPLIT: 0=float out (+opt bias), 1=bias(+opt gelu)+split out, 2=split out (no bias)
template <int ACT, int OSPLIT>
__device__ __forceinline__ void hmma_gemm_body(
    const bf16* __restrict__ Ah, const bf16* __restrict__ Al,
    const bf16* __restrict__ Bh, const bf16* __restrict__ Bl,
    const float* __restrict__ bias, float* __restrict__ Cf,
    bf16* __restrict__ Ch, bf16* __restrict__ Cl,
    int Kd, int kbeg, int kslice, int Nc) {
    __shared__ bf16 sAh[128][40], sAl[128][40], sBh[64][40], sBl[64][40];
    const int tid = threadIdx.x;
    const int wid = tid >> 5, lane = tid & 31;
    const int i0 = blockIdx.y << 7, j0 = blockIdx.x << 6;
    const int mw = (wid & 3) << 5;
    const int nw = (wid >> 2) << 5;

    float acc[2][4][4];
#pragma unroll
    for (int a = 0; a < 2; a++)
#pragma unroll
        for (int b = 0; b < 4; b++)
#pragma unroll
            for (int cc = 0; cc < 4; cc++) acc[a][b][cc] = 0.f;

    const int a_r = lane & 15;
    const int a_k = (lane >> 4) << 3;
    const int b_n = (lane & 7) + ((lane & 16) >> 1);
    const int b_k = lane & 8;

    const uint32_t uAh = smem_u32(&sAh[0][0]);
    const uint32_t uAl = smem_u32(&sAl[0][0]);
    const uint32_t uBh = smem_u32(&sBh[0][0]);
    const uint32_t uBl = smem_u32(&sBl[0][0]);

    const int r = tid >> 1, hf = (tid & 1) << 4;
    const int tb = tid & 127;
    const int rb = tb >> 1, hb = (tb & 1) << 4;

    const int nch = kslice >> 5;
    for (int c = 0; c < nch; c++) {
        int kt = kbeg + (c << 5);
        if (c) __syncthreads();
        {
            const bf16* pAh = Ah + (size_t)(i0 + r) * Kd + kt + hf;
            const bf16* pAl = Al + (size_t)(i0 + r) * Kd + kt + hf;
            *(uint4*)&sAh[r][hf] = *(const uint4*)pAh;
            *(uint4*)&sAh[r][hf + 8] = *(const uint4*)(pAh + 8);
            *(uint4*)&sAl[r][hf] = *(const uint4*)pAl;
            *(uint4*)&sAl[r][hf + 8] = *(const uint4*)(pAl + 8);
        }
        if (tid < 128) {
            const bf16* pBh = Bh + (size_t)(j0 + rb) * Kd + kt + hb;
            *(uint4*)&sBh[rb][hb] = *(const uint4*)pBh;
            *(uint4*)&sBh[rb][hb + 8] = *(const uint4*)(pBh + 8);
        } else {
            const bf16* pBl = Bl + (size_t)(j0 + rb) * Kd + kt + hb;
            *(uint4*)&sBl[rb][hb] = *(const uint4*)pBl;
            *(uint4*)&sBl[rb][hb + 8] = *(const uint4*)(pBl + 8);
        }
        __syncthreads();
#pragma unroll
        for (int ks = 0; ks < 2; ks++) {
            const int kk = ks << 4;
            uint32_t ah[2][4], al[2][4], bhf[2][4], blf[2][4];
#pragma unroll
            for (int mf = 0; mf < 2; mf++) {
                uint32_t off = (uint32_t)(((mw + (mf << 4) + a_r) * 40 + kk + a_k) << 1);
                ldsm4(ah[mf][0], ah[mf][1], ah[mf][2], ah[mf][3], uAh + off);
                ldsm4(al[mf][0], al[mf][1], al[mf][2], al[mf][3], uAl + off);
            }
#pragma unroll
            for (int g = 0; g < 2; g++) {
                uint32_t off = (uint32_t)(((nw + (g << 4) + b_n) * 40 + kk + b_k) << 1);
                ldsm4(bhf[g][0], bhf[g][1], bhf[g][2], bhf[g][3], uBh + off);
                ldsm4(blf[g][0], blf[g][1], blf[g][2], blf[g][3], uBl + off);
            }
#pragma unroll
            for (int mf = 0; mf < 2; mf++)
#pragma unroll
                for (int nf = 0; nf < 4; nf++) {
                    const uint32_t* ph = &bhf[nf >> 1][(nf & 1) << 1];
                    const uint32_t* pl = &blf[nf >> 1][(nf & 1) << 1];
                    mma_bf16(acc[mf][nf], ah[mf], ph);
                    mma_bf16(acc[mf][nf], ah[mf], pl);
                    mma_bf16(acc[mf][nf], al[mf], ph);
                }
        }
    }

    const int lr = lane >> 2, lc = (lane & 3) << 1;
#pragma unroll
    for (int mf = 0; mf < 2; mf++)
#pragma unroll
        for (int rp = 0; rp < 2; rp++) {
            int row = i0 + mw + (mf << 4) + lr + (rp << 3);
#pragma unroll
            for (int nf = 0; nf < 4; nf++) {
                float v0 = acc[mf][nf][(rp << 1) + 0];
                float v1 = acc[mf][nf][(rp << 1) + 1];
                int col = j0 + nw + (nf << 3) + lc;
                if (OSPLIT == 0) {
                    if (bias) {
                        v0 += bias[col];
                        v1 += bias[col + 1];
                    }
                    *(float2*)&Cf[(size_t)row * Nc + col] = make_float2(v0, v1);
                } else {
                    if (OSPLIT == 1) {
                        v0 += bias[col];
                        v1 += bias[col + 1];
                        if (ACT == 1) {
                            v0 = 0.5f * v0 * (1.0f + erff(v0 * 0.70710678118654752f));
                            v1 = 0.5f * v1 * (1.0f + erff(v1 * 0.70710678118654752f));
                        }
                    }
                    bf16 h0 = __float2bfloat16(v0), h1 = __float2bfloat16(v1);
                    Ch[(size_t)row * Nc + col] = h0;
                    Ch[(size_t)row * Nc + col + 1] = h1;
                    Cl[(size_t)row * Nc + col] = __float2bfloat16(v0 - __bfloat162float(h0));
                    Cl[(size_t)row * Nc + col + 1] = __float2bfloat16(v1 - __bfloat162float(h1));
                }
            }
        }
}

template <int ACT, int SPLIT, int OSPLIT>
__global__ void __launch_bounds__(256) hmma_gemm_kernel(
    const bf16* __restrict__ Ah, const bf16* __restrict__ Al,
    const bf16* __restrict__ Bh, const bf16* __restrict__ Bl,
    const float* __restrict__ bias, float* __restrict__ Cf,
    bf16* __restrict__ Ch, bf16* __restrict__ Cl, int Kd, int Nc) {
    int kslice = Kd / SPLIT;
    int kbeg = blockIdx.z * kslice;
    float* Cz = (SPLIT > 1) ? Cf + (size_t)blockIdx.z * Nn * Nc : Cf;
    hmma_gemm_body<ACT, OSPLIT>(Ah, Al, Bh, Bl, SPLIT > 1 ? nullptr : bias, Cz, Ch, Cl,
                                Kd, kbeg, kslice, Nc);
}

// QKV: split-bf16 outputs, grid.z selects q/k/v
__global__ void __launch_bounds__(256) hmma_qkv_kernel(
    const bf16* __restrict__ Ah, const bf16* __restrict__ Al,
    const bf16* __restrict__ Bh0, const bf16* __restrict__ Bl0,
    const bf16* __restrict__ Bh1, const bf16* __restrict__ Bl1,
    const bf16* __restrict__ Bh2, const bf16* __restrict__ Bl2,
    bf16* __restrict__ qh, bf16* __restrict__ ql, bf16* __restrict__ kh,
    bf16* __restrict__ kl, bf16* __restrict__ vh, bf16* __restrict__ vl) {
    int z = blockIdx.z;
    const bf16* Bh = (z == 0) ? Bh0 : (z == 1) ? Bh1 : Bh2;
    const bf16* Bl = (z == 0) ? Bl0 : (z == 1) ? Bl1 : Bl2;
    bf16* Ch = (z == 0) ? qh : (z == 1) ? kh : vh;
    bf16* Cl = (z == 0) ? ql : (z == 1) ? kl : vl;
    hmma_gemm_body<0, 2>(Ah, Al, Bh, Bl, nullptr, nullptr, Ch, Cl, Dd, 0, Dd, Dd);
}

// ---------------- HMMA flash attention with edge bias ----------------
// Block: 128 threads (4 warps x m16), 64 q-rows x one head. j-tiles of 64.
__global__ void __launch_bounds__(128) attn_hmma_kernel(
    const bf16* __restrict__ Qh, const bf16* __restrict__ Ql,
    const bf16* __restrict__ Kh, const bf16* __restrict__ Kl,
    const bf16* __restrict__ Vh, const bf16* __restrict__ Vl,
    const unsigned char* __restrict__ E8, const float* __restrict__ ebl,
    bf16* __restrict__ Oh, bf16* __restrict__ Ol) {
    __shared__ bf16 sQh[64][40], sQl[64][40], sKh[64][40], sKl[64][40];
    __shared__ bf16 sVh[32][72], sVl[32][72];
    __shared__ float s_eb[8];

    const int h = blockIdx.y;
    const int i0 = blockIdx.x << 6;
    const int tid = threadIdx.x;
    const int wid = tid >> 5, lane = tid & 31;
    const int mw = wid << 4;

    if (tid < NEDGEe) s_eb[tid] = ebl[tid * Hh + h];

    const int a_r = lane & 15, a_k = (lane >> 4) << 3;
    const int b_n = (lane & 7) + ((lane & 16) >> 1), b_k = lane & 8;
    const int lr = lane >> 2, lc = (lane & 3) << 1;

    const uint32_t uQh = smem_u32(&sQh[0][0]);
    const uint32_t uQl = smem_u32(&sQl[0][0]);
    const uint32_t uKh = smem_u32(&sKh[0][0]);
    const uint32_t uKl = smem_u32(&sKl[0][0]);
    const uint32_t uVh = smem_u32(&sVh[0][0]);
    const uint32_t uVl = smem_u32(&sVl[0][0]);

    // Q load: 2 threads/row, 16 bf16 each
    const int qr = tid >> 1, qh4 = (tid & 1) << 4;
    {
        const bf16* p = Qh + (size_t)(i0 + qr) * Dd + h * DKk + qh4;
        *(uint4*)&sQh[qr][qh4] = *(const uint4*)p;
        *(uint4*)&sQh[qr][qh4 + 8] = *(const uint4*)(p + 8);
        const bf16* p2 = Ql + (size_t)(i0 + qr) * Dd + h * DKk + qh4;
        *(uint4*)&sQl[qr][qh4] = *(const uint4*)p2;
        *(uint4*)&sQl[qr][qh4 + 8] = *(const uint4*)(p2 + 8);
    }

    float of[4][4];
#pragma unroll
    for (int a = 0; a < 4; a++)
#pragma unroll
        for (int b = 0; b < 4; b++) of[a][b] = 0.f;
    float m0 = -1e30f, m1 = -1e30f, l0 = 0.f, l1 = 0.f;
    const float scale = 0.17677669529663687f;  // 1/sqrt(32)
    const size_t r0e = (size_t)(i0 + mw + lr) * Nn;
    const size_t r1e = (size_t)(i0 + mw + lr + 8) * Nn;

    for (int jt = 0; jt < Nn; jt += 64) {
        __syncthreads();
        // K tile + V transposed tile
        {
            const bf16* pk = Kh + (size_t)(jt + qr) * Dd + h * DKk + qh4;
            *(uint4*)&sKh[qr][qh4] = *(const uint4*)pk;
            *(uint4*)&sKh[qr][qh4 + 8] = *(const uint4*)(pk + 8);
            const bf16* pk2 = Kl + (size_t)(jt + qr) * Dd + h * DKk + qh4;
            *(uint4*)&sKl[qr][qh4] = *(const uint4*)pk2;
            *(uint4*)&sKl[qr][qh4 + 8] = *(const uint4*)(pk2 + 8);
            bf16 tv[16];
            *(uint4*)&tv[0] = *(const uint4*)(Vh + (size_t)(jt + qr) * Dd + h * DKk + qh4);
            *(uint4*)&tv[8] = *(const uint4*)(Vh + (size_t)(jt + qr) * Dd + h * DKk + qh4 + 8);
#pragma unroll
            for (int i = 0; i < 16; i++) sVh[qh4 + i][qr] = tv[i];
            *(uint4*)&tv[0] = *(const uint4*)(Vl + (size_t)(jt + qr) * Dd + h * DKk + qh4);
            *(uint4*)&tv[8] = *(const uint4*)(Vl + (size_t)(jt + qr) * Dd + h * DKk + qh4 + 8);
#pragma unroll
            for (int i = 0; i < 16; i++) sVl[qh4 + i][qr] = tv[i];
        }
        __syncthreads();

        // ---- S = Q K^T (split, 3 MMAs per frag) ----
        float sf[8][4];
#pragma unroll
        for (int nf = 0; nf < 8; nf++)
#pragma unroll
            for (int cc = 0; cc < 4; cc++) sf[nf][cc] = 0.f;
#pragma unroll
        for (int ks = 0; ks < 2; ks++) {
            const int kk = ks << 4;
            uint32_t aqh[4], aql[4];
            uint32_t offa = (uint32_t)(((mw + a_r) * 40 + kk + a_k) << 1);
            ldsm4(aqh[0], aqh[1], aqh[2], aqh[3], uQh + offa);
            ldsm4(aql[0], aql[1], aql[2], aql[3], uQl + offa);
#pragma unroll
            for (int g = 0; g < 4; g++) {
                uint32_t bkh[4], bkl[4];
                uint32_t offb = (uint32_t)((((g << 4) + b_n) * 40 + kk + b_k) << 1);
                ldsm4(bkh[0], bkh[1], bkh[2], bkh[3], uKh + offb);
                ldsm4(bkl[0], bkl[1], bkl[2], bkl[3], uKl + offb);
#pragma unroll
                for (int sub = 0; sub < 2; sub++) {
                    int nf = (g << 1) + sub;
                    const uint32_t* ph = &bkh[sub << 1];
                    const uint32_t* pl = &bkl[sub << 1];
                    mma_bf16(sf[nf], aqh, ph);
                    mma_bf16(sf[nf], aqh, pl);
                    mma_bf16(sf[nf], aql, ph);
                }
            }
        }

        // ---- scale + edge bias + row max ----
        float mx0 = -1e30f, mx1 = -1e30f;
#pragma unroll
        for (int nf = 0; nf < 8; nf++) {
            unsigned short e0 = *(const unsigned short*)&E8[r0e + jt + (nf << 3) + lc];
            unsigned short e1 = *(const unsigned short*)&E8[r1e + jt + (nf << 3) + lc];
            sf[nf][0] = fmaf(sf[nf][0], scale, s_eb[e0 & 0xffu]);
            sf[nf][1] = fmaf(sf[nf][1], scale, s_eb[e0 >> 8]);
            sf[nf][2] = fmaf(sf[nf][2], scale, s_eb[e1 & 0xffu]);
            sf[nf][3] = fmaf(sf[nf][3], scale, s_eb[e1 >> 8]);
            mx0 = fmaxf(mx0, fmaxf(sf[nf][0], sf[nf][1]));
            mx1 = fmaxf(mx1, fmaxf(sf[nf][2], sf[nf][3]));
        }
        mx0 = fmaxf(mx0, __shfl_xor_sync(0xffffffffu, mx0, 1));
        mx0 = fmaxf(mx0, __shfl_xor_sync(0xffffffffu, mx0, 2));
        mx1 = fmaxf(mx1, __shfl_xor_sync(0xffffffffu, mx1, 1));
        mx1 = fmaxf(mx1, __shfl_xor_sync(0xffffffffu, mx1, 2));
        float mn0 = fmaxf(m0, mx0), mn1 = fmaxf(m1, mx1);
        float al0 = __expf(m0 - mn0), al1 = __expf(m1 - mn1);
        m0 = mn0;
        m1 = mn1;
#pragma unroll
        for (int nf = 0; nf < 4; nf++) {
            of[nf][0] *= al0;
            of[nf][1] *= al0;
            of[nf][2] *= al1;
            of[nf][3] *= al1;
        }

        // ---- P = exp(S - m); pack into A-fragments (hi/lo) ----
        float ps0 = 0.f, ps1 = 0.f;
        uint32_t aph[4][4], apl[4][4];
#pragma unroll
        for (int nf = 0; nf < 8; nf++) {
            float p0 = __expf(sf[nf][0] - mn0);
            float p1 = __expf(sf[nf][1] - mn0);
            float p2 = __expf(sf[nf][2] - mn1);
            float p3 = __expf(sf[nf][3] - mn1);
            ps0 += p0 + p1;
            ps1 += p2 + p3;
            float h0 = __bfloat162float(__float2bfloat16(p0));
            float h1 = __bfloat162float(__float2bfloat16(p1));
            float h2 = __bfloat162float(__float2bfloat16(p2));
            float h3 = __bfloat162float(__float2bfloat16(p3));
            int ks = nf >> 1, base = (nf & 1) << 1;
            aph[ks][base + 0] = pack2bf(h0, h1);
            aph[ks][base + 1] = pack2bf(h2, h3);
            apl[ks][base + 0] = pack2bf(p0 - h0, p1 - h1);
            apl[ks][base + 1] = pack2bf(p2 - h2, p3 - h3);
        }
        ps0 += __shfl_xor_sync(0xffffffffu, ps0, 1);
        ps0 += __shfl_xor_sync(0xffffffffu, ps0, 2);
        ps1 += __shfl_xor_sync(0xffffffffu, ps1, 1);
        ps1 += __shfl_xor_sync(0xffffffffu, ps1, 2);
        l0 = l0 * al0 + ps0;
        l1 = l1 * al1 + ps1;

        // ---- O += P V (split, 3 MMAs per frag) ----
#pragma unroll
        for (int ks = 0; ks < 4; ks++) {
            const int kk = ks << 4;
#pragma unroll
            for (int dg = 0; dg < 2; dg++) {
                uint32_t bvh[4], bvl[4];
                uint32_t offv = (uint32_t)((((dg << 4) + b_n) * 72 + kk + b_k) << 1);
                ldsm4(bvh[0], bvh[1], bvh[2], bvh[3], uVh + offv);
                ldsm4(bvl[0], bvl[1], bvl[2], bvl[3], uVl + offv);
#pragma unroll
                for (int sub = 0; sub < 2; sub++) {
                    int nf = (dg << 1) + sub;
                    const uint32_t* ph = &bvh[sub << 1];
                    const uint32_t* pl = &bvl[sub << 1];
                    mma_bf16(of[nf], aph[ks], ph);
                    mma_bf16(of[nf], apl[ks], ph);
                    mma_bf16(of[nf], aph[ks], pl);
                }
            }
        }
    }

    // ---- normalize + split-bf16 write ----
    float inv0 = 1.0f / l0, inv1 = 1.0f / l1;
    int row0 = i0 + mw + lr, row1 = row0 + 8;
#pragma unroll
    for (int nf = 0; nf < 4; nf++) {
        int col = h * DKk + (nf << 3) + lc;
        float v0 = of[nf][0] * inv0, v1 = of[nf][1] * inv0;
        float v2 = of[nf][2] * inv1, v3 = of[nf][3] * inv1;
        float h0 = __bfloat162float(__float2bfloat16(v0));
        float h1 = __bfloat162float(__float2bfloat16(v1));
        float h2 = __bfloat162float(__float2bfloat16(v2));
        float h3 = __bfloat162float(__float2bfloat16(v3));
        *(uint32_t*)&Oh[(size_t)row0 * Dd + col] = pack2bf(h0, h1);
        *(uint32_t*)&Oh[(size_t)row1 * Dd + col] = pack2bf(h2, h3);
        *(uint32_t*)&Ol[(size_t)row0 * Dd + col] = pack2bf(v0 - h0, v1 - h1);
        *(uint32_t*)&Ol[(size_t)row1 * Dd + col] = pack2bf(v2 - h2, v3 - h3);
    }
}

// ---------------- partial reduce + bias + residual + LayerNorm (+split out) ----------------
template <int S>
__global__ void addln_red_kernel(float* __restrict__ x, const float* __restrict__ part,
                                 const float* __restrict__ bias, const float* __restrict__ g,
                                 const float* __restrict__ b, bf16* __restrict__ xh,
                                 bf16* __restrict__ xl) {
    int i = blockIdx.x, d = threadIdx.x;
    __shared__ float red[256];
    float v = x[i * Dd + d] + bias[d];
#pragma unroll
    for (int s = 0; s < S; s++) v += part[(size_t)s * Nn * Dd + (size_t)i * Dd + d];
    red[d] = v;
    __syncthreads();
    for (int s = 128; s > 0; s >>= 1) {
        if (d < s) red[d] += red[d + s];
        __syncthreads();
    }
    float mean = red[0] * (1.0f / Dd);
    __syncthreads();
    float dv = v - mean;
    red[d] = dv * dv;
    __syncthreads();
    for (int s = 128; s > 0; s >>= 1) {
        if (d < s) red[d] += red[d + s];
        __syncthreads();
    }
    float var = red[0] * (1.0f / Dd);
    float outv = dv * rsqrtf(var + 1e-5f) * g[d] + b[d];
    x[i * Dd + d] = outv;
    bf16 h = __float2bfloat16(outv);
    xh[i * Dd + d] = h;
    xl[i * Dd + d] = __float2bfloat16(outv - __bfloat162float(h));
}

__global__ void pool_kernel(const float* __restrict__ x, float* __restrict__ p) {
    int j = blockIdx.x * 32 + threadIdx.x;
    int yy = threadIdx.y;
    float s = 0.f, mx = -1e30f;
    for (int i = yy; i < Nn; i += 8) {
        float v = x[(size_t)i * Dd + j];
        s += v;
        mx = fmaxf(mx, v);
    }
    __shared__ float ss[8][33], sm[8][33];
    ss[yy][threadIdx.x] = s;
    sm[yy][threadIdx.x] = mx;
    __syncthreads();
    if (yy == 0) {
        for (int k2 = 1; k2 < 8; k2++) {
            s += ss[k2][threadIdx.x];
            mx = fmaxf(mx, sm[k2][threadIdx.x]);
        }
        p[j] = s * (1.0f / Nn);
        p[Dd + j] = mx;
    }
}

__global__ void head_kernel(const float* __restrict__ pooled, const float* __restrict__ Wr,
                            const float* __restrict__ br, float* __restrict__ out) {
    __shared__ float sp[2 * Dd];
    int d = threadIdx.x;
    sp[d] = pooled[d];
    sp[d + Dd] = pooled[d + Dd];
    __syncthreads();
    float acc = br[d];
#pragma unroll 8
    for (int k2 = 0; k2 < 2 * Dd; k2++) acc = fmaf(sp[k2], Wr[(size_t)k2 * Dd + d], acc);
    out[d] = acc;
}

// ---------------- host launcher ----------------
extern "C" void kernel_launch(void* const* d_in, const int* in_sizes, int n_in,
                              void* d_out, int out_size) {
    const int* node_types = (const int*)d_in[0];
    const int* edge_idx = (const int*)d_in[1];
    const float* node_emb = (const float*)d_in[2];
    const float* Wq = (const float*)d_in[3];
    const float* Wk = (const float*)d_in[4];
    const float* Wv = (const float*)d_in[5];
    const float* Wo = (const float*)d_in[6];
    const float* bo = (const float*)d_in[7];
    const float* eb = (const float*)d_in[8];
    const float* W1 = (const float*)d_in[9];
    const float* b1 = (const float*)d_in[10];
    const float* W2 = (const float*)d_in[11];
    const float* b2 = (const float*)d_in[12];
    const float* ln1g = (const float*)d_in[13];
    const float* ln1b = (const float*)d_in[14];
    const float* ln2g = (const float*)d_in[15];
    const float* ln2b = (const float*)d_in[16];
    const float* Wr = (const float*)d_in[17];
    const float* brr = (const float*)d_in[18];
    float* out = (float*)d_out;

    float *x, *part, *pool;
    unsigned char* e8;
    bf16 *xh, *xl, *qh, *ql, *kh, *kl, *vh, *vl, *atth, *attl, *t1h, *t1l;
    bf16 *wqh, *wql, *wkh, *wkl, *wvh, *wvl, *woh, *wol, *w1h, *w1l, *w2h, *w2l;
    cudaGetSymbolAddress((void**)&x, g_x);
    cudaGetSymbolAddress((void**)&part, g_part);
    cudaGetSymbolAddress((void**)&pool, g_pool);
    cudaGetSymbolAddress((void**)&e8, g_e8);
    cudaGetSymbolAddress((void**)&xh, g_xh);
    cudaGetSymbolAddress((void**)&xl, g_xl);
    cudaGetSymbolAddress((void**)&qh, g_qh);
    cudaGetSymbolAddress((void**)&ql, g_ql);
    cudaGetSymbolAddress((void**)&kh, g_kh);
    cudaGetSymbolAddress((void**)&kl, g_kl);
    cudaGetSymbolAddress((void**)&vh, g_vh);
    cudaGetSymbolAddress((void**)&vl, g_vl);
    cudaGetSymbolAddress((void**)&atth, g_atth);
    cudaGetSymbolAddress((void**)&attl, g_attl);
    cudaGetSymbolAddress((void**)&t1h, g_t1h);
    cudaGetSymbolAddress((void**)&t1l, g_t1l);
    cudaGetSymbolAddress((void**)&wqh, g_wqh);
    cudaGetSymbolAddress((void**)&wql, g_wql);
    cudaGetSymbolAddress((void**)&wkh, g_wkh);
    cudaGetSymbolAddress((void**)&wkl, g_wkl);
    cudaGetSymbolAddress((void**)&wvh, g_wvh);
    cudaGetSymbolAddress((void**)&wvl, g_wvl);
    cudaGetSymbolAddress((void**)&woh, g_woh);
    cudaGetSymbolAddress((void**)&wol, g_wol);
    cudaGetSymbolAddress((void**)&w1h, g_w1h);
    cudaGetSymbolAddress((void**)&w1l, g_w1l);
    cudaGetSymbolAddress((void**)&w2h, g_w2h);
    cudaGetSymbolAddress((void**)&w2l, g_w2l);

    embed_kernel<<<Nn, Dd>>>(node_types, node_emb, x, xh, xl);
    cvt_e8_kernel<<<(Nn * Nn / 4) / 256, 256>>>(edge_idx, e8);

    wsplit_kernel<<<dim3(8, 8, Ll), dim3(32, 8)>>>(Wq, wqh, wql, Dd, Dd);
    wsplit_kernel<<<dim3(8, 8, Ll), dim3(32, 8)>>>(Wk, wkh, wkl, Dd, Dd);
    wsplit_kernel<<<dim3(8, 8, Ll), dim3(32, 8)>>>(Wv, wvh, wvl, Dd, Dd);
    wsplit_kernel<<<dim3(8, 8, Ll), dim3(32, 8)>>>(Wo, woh, wol, Dd, Dd);
    wsplit_kernel<<<dim3(32, 8, Ll), dim3(32, 8)>>>(W1, w1h, w1l, Dd, DFFf);
    wsplit_kernel<<<dim3(8, 32, Ll), dim3(32, 8)>>>(W2, w2h, w2l, DFFf, Dd);

    for (int l = 0; l < Ll; l++) {
        size_t wo256 = (size_t)l * Dd * Dd;
        size_t woff1 = (size_t)l * Dd * DFFf;
        hmma_qkv_kernel<<<dim3(4, 16, 3), 256>>>(
            xh, xl, wqh + wo256, wql + wo256, wkh + wo256, wkl + wo256, wvh + wo256,
            wvl + wo256, qh, ql, kh, kl, vh, vl);

        attn_hmma_kernel<<<dim3(Nn / 64, Hh), 128>>>(qh, ql, kh, kl, vh, vl, e8,
                                                     eb + l * NEDGEe * Hh, atth, attl);

        hmma_gemm_kernel<0, 2, 0><<<dim3(4, 16, 2), 256>>>(
            atth, attl, woh + wo256, wol + wo256, nullptr, part, nullptr, nullptr, Dd, Dd);
        addln_red_kernel<2><<<Nn, Dd>>>(x, part, bo + l * Dd, ln1g + l * Dd, ln1b + l * Dd, xh,
                                        xl);

        hmma_gemm_kernel<1, 1, 1><<<dim3(16, 16, 1), 256>>>(
            xh, xl, w1h + woff1, w1l + woff1, b1 + l * DFFf, nullptr, t1h, t1l, Dd, DFFf);

        hmma_gemm_kernel<0, 2, 0><<<dim3(4, 16, 2), 256>>>(
            t1h, t1l, w2h + woff1, w2l + woff1, nullptr, part, nullptr, nullptr, DFFf, Dd);
        addln_red_kernel<2><<<Nn, Dd>>>(x, part, b2 + l * Dd, ln2g + l * Dd, ln2b + l * Dd, xh,
                                        xl);
    }

    pool_kernel<<<Dd / 32, dim3(32, 8)>>>(x, pool);
    head_kernel<<<1, Dd>>>(pool, Wr, brr, out);
}

// round 10
// speedup vs baseline: 1.7571x; 1.2075x over previous
#include <cuda_runtime.h>
#include <cuda_bf16.h>
#include <stdint.h>
#include <math.h>

#define Nn 2048
#define Dd 256
#define Hh 8
#define DKk 32
#define Ll 4
#define DFFf 1024
#define NEDGEe 5

typedef __nv_bfloat16 bf16;

// ---------------- portable MMA helpers (validated R8/R9) ----------------
__device__ __forceinline__ uint32_t smem_u32(const void* p) {
    uint32_t a;
    asm("{ .reg .u64 t; cvta.to.shared.u64 t, %1; cvt.u32.u64 %0, t; }" : "=r"(a) : "l"(p));
    return a;
}
__device__ __forceinline__ void ldsm4(uint32_t& r0, uint32_t& r1, uint32_t& r2, uint32_t& r3,
                                      uint32_t addr) {
    asm volatile("ldmatrix.sync.aligned.m8n8.x4.shared.b16 {%0,%1,%2,%3}, [%4];"
                 : "=r"(r0), "=r"(r1), "=r"(r2), "=r"(r3)
                 : "r"(addr));
}
__device__ __forceinline__ void ldsm4t(uint32_t& r0, uint32_t& r1, uint32_t& r2, uint32_t& r3,
                                       uint32_t addr) {
    asm volatile("ldmatrix.sync.aligned.m8n8.x4.trans.shared.b16 {%0,%1,%2,%3}, [%4];"
                 : "=r"(r0), "=r"(r1), "=r"(r2), "=r"(r3)
                 : "r"(addr));
}
__device__ __forceinline__ void mma_bf16(float* d, const uint32_t* a, const uint32_t* b) {
    asm volatile(
        "mma.sync.aligned.m16n8k16.row.col.f32.bf16.bf16.f32 "
        "{%0,%1,%2,%3}, {%4,%5,%6,%7}, {%8,%9}, {%0,%1,%2,%3};"
        : "+f"(d[0]), "+f"(d[1]), "+f"(d[2]), "+f"(d[3])
        : "r"(a[0]), "r"(a[1]), "r"(a[2]), "r"(a[3]), "r"(b[0]), "r"(b[1]));
}
// {lo=a, hi=b} in one CVT
__device__ __forceinline__ uint32_t pack2bf(float a, float b) {
    uint32_t r;
    asm("cvt.rn.bf16x2.f32 %0, %1, %2;" : "=r"(r) : "f"(b), "f"(a));
    return r;
}
__device__ __forceinline__ float ex2f(float x) {
    float y;
    asm("ex2.approx.f32 %0, %1;" : "=f"(y) : "f"(x));
    return y;
}
__device__ __forceinline__ void cpa16(uint32_t dst, const void* src) {
    asm volatile("cp.async.cg.shared.global [%0], [%1], 16;" :: "r"(dst), "l"(src));
}
#define CP_COMMIT() asm volatile("cp.async.commit_group;" ::: "memory")
#define CP_WAIT(n) asm volatile("cp.async.wait_group %0;" :: "n"(n) : "memory")

// ---------------- scratch ----------------
__device__ float g_x[Nn * Dd];
__device__ float g_part[2 * Nn * Dd];
__device__ unsigned char g_e8[Nn * Nn];
__device__ float g_pool[2 * Dd];
__device__ bf16 g_xh[Nn * Dd], g_xl[Nn * Dd];
__device__ bf16 g_qh[Nn * Dd], g_ql[Nn * Dd];
__device__ bf16 g_kh[Nn * Dd], g_kl[Nn * Dd];
__device__ bf16 g_vh[Nn * Dd], g_vl[Nn * Dd];
__device__ bf16 g_atth[Nn * Dd], g_attl[Nn * Dd];
__device__ bf16 g_t1h[Nn * DFFf], g_t1l[Nn * DFFf];
__device__ bf16 g_wqh[Ll * Dd * Dd], g_wql[Ll * Dd * Dd];
__device__ bf16 g_wkh[Ll * Dd * Dd], g_wkl[Ll * Dd * Dd];
__device__ bf16 g_wvh[Ll * Dd * Dd], g_wvl[Ll * Dd * Dd];
__device__ bf16 g_woh[Ll * Dd * Dd], g_wol[Ll * Dd * Dd];
__device__ bf16 g_w1h[Ll * Dd * DFFf], g_w1l[Ll * Dd * DFFf];
__device__ bf16 g_w2h[Ll * DFFf * Dd], g_w2l[Ll * DFFf * Dd];

// ---------------- embedding gather (+split) ----------------
__global__ void embed_kernel(const int* __restrict__ nt, const float* __restrict__ emb,
                             float* __restrict__ x, bf16* __restrict__ xh, bf16* __restrict__ xl) {
    int i = blockIdx.x;
    int d = threadIdx.x;
    float v = emb[nt[i] * Dd + d];
    x[i * Dd + d] = v;
    bf16 h = __float2bfloat16(v);
    xh[i * Dd + d] = h;
    xl[i * Dd + d] = __float2bfloat16(v - __bfloat162float(h));
}

__global__ void cvt_e8_kernel(const int* __restrict__ e, unsigned char* __restrict__ o) {
    int i = blockIdx.x * blockDim.x + threadIdx.x;
    int4 v = ((const int4*)e)[i];
    uchar4 u;
    u.x = (unsigned char)v.x; u.y = (unsigned char)v.y;
    u.z = (unsigned char)v.z; u.w = (unsigned char)v.w;
    ((uchar4*)o)[i] = u;
}

// ---------------- weight transpose + split ----------------
__global__ void wsplit_kernel(const float* __restrict__ W, bf16* __restrict__ Th,
                              bf16* __restrict__ Tl, int Kd, int Nc) {
    __shared__ float sh[32][33], slo[32][33];
    const float* Wl = W + (size_t)blockIdx.z * Kd * Nc;
    bf16* Thl = Th + (size_t)blockIdx.z * Kd * Nc;
    bf16* Tll = Tl + (size_t)blockIdx.z * Kd * Nc;
    int n0 = blockIdx.x << 5, k0 = blockIdx.y << 5;
    int tx = threadIdx.x, ty = threadIdx.y;
#pragma unroll
    for (int r = 0; r < 4; r++) {
        int kk = ty + (r << 3);
        float v = Wl[(size_t)(k0 + kk) * Nc + n0 + tx];
        float h = __bfloat162float(__float2bfloat16(v));
        sh[kk][tx] = h;
        slo[kk][tx] = v - h;
    }
    __syncthreads();
#pragma unroll
    for (int r = 0; r < 4; r++) {
        int nn = ty + (r << 3);
        Thl[(size_t)(n0 + nn) * Kd + k0 + tx] = __float2bfloat16(sh[tx][nn]);
        Tll[(size_t)(n0 + nn) * Kd + k0 + tx] = __float2bfloat16(slo[tx][nn]);
    }
}

// ---------------- split-bf16 HMMA GEMM (unchanged, validated) ----------------
template <int ACT, int OSPLIT>
__device__ __forceinline__ void hmma_gemm_body(
    const bf16* __restrict__ Ah, const bf16* __restrict__ Al,
    const bf16* __restrict__ Bh, const bf16* __restrict__ Bl,
    const float* __restrict__ bias, float* __restrict__ Cf,
    bf16* __restrict__ Ch, bf16* __restrict__ Cl,
    int Kd, int kbeg, int kslice, int Nc) {
    __shared__ bf16 sAh[128][40], sAl[128][40], sBh[64][40], sBl[64][40];
    const int tid = threadIdx.x;
    const int wid = tid >> 5, lane = tid & 31;
    const int i0 = blockIdx.y << 7, j0 = blockIdx.x << 6;
    const int mw = (wid & 3) << 5;
    const int nw = (wid >> 2) << 5;

    float acc[2][4][4];
#pragma unroll
    for (int a = 0; a < 2; a++)
#pragma unroll
        for (int b = 0; b < 4; b++)
#pragma unroll
            for (int cc = 0; cc < 4; cc++) acc[a][b][cc] = 0.f;

    const int a_r = lane & 15;
    const int a_k = (lane >> 4) << 3;
    const int b_n = (lane & 7) + ((lane & 16) >> 1);
    const int b_k = lane & 8;

    const uint32_t uAh = smem_u32(&sAh[0][0]);
    const uint32_t uAl = smem_u32(&sAl[0][0]);
    const uint32_t uBh = smem_u32(&sBh[0][0]);
    const uint32_t uBl = smem_u32(&sBl[0][0]);

    const int r = tid >> 1, hf = (tid & 1) << 4;
    const int tb = tid & 127;
    const int rb = tb >> 1, hb = (tb & 1) << 4;

    const int nch = kslice >> 5;
    for (int c = 0; c < nch; c++) {
        int kt = kbeg + (c << 5);
        if (c) __syncthreads();
        {
            const bf16* pAh = Ah + (size_t)(i0 + r) * Kd + kt + hf;
            const bf16* pAl = Al + (size_t)(i0 + r) * Kd + kt + hf;
            *(uint4*)&sAh[r][hf] = *(const uint4*)pAh;
            *(uint4*)&sAh[r][hf + 8] = *(const uint4*)(pAh + 8);
            *(uint4*)&sAl[r][hf] = *(const uint4*)pAl;
            *(uint4*)&sAl[r][hf + 8] = *(const uint4*)(pAl + 8);
        }
        if (tid < 128) {
            const bf16* pBh = Bh + (size_t)(j0 + rb) * Kd + kt + hb;
            *(uint4*)&sBh[rb][hb] = *(const uint4*)pBh;
            *(uint4*)&sBh[rb][hb + 8] = *(const uint4*)(pBh + 8);
        } else {
            const bf16* pBl = Bl + (size_t)(j0 + rb) * Kd + kt + hb;
            *(uint4*)&sBl[rb][hb] = *(const uint4*)pBl;
            *(uint4*)&sBl[rb][hb + 8] = *(const uint4*)(pBl + 8);
        }
        __syncthreads();
#pragma unroll
        for (int ks = 0; ks < 2; ks++) {
            const int kk = ks << 4;
            uint32_t ah[2][4], al[2][4], bhf[2][4], blf[2][4];
#pragma unroll
            for (int mf = 0; mf < 2; mf++) {
                uint32_t off = (uint32_t)(((mw + (mf << 4) + a_r) * 40 + kk + a_k) << 1);
                ldsm4(ah[mf][0], ah[mf][1], ah[mf][2], ah[mf][3], uAh + off);
                ldsm4(al[mf][0], al[mf][1], al[mf][2], al[mf][3], uAl + off);
            }
#pragma unroll
            for (int g = 0; g < 2; g++) {
                uint32_t off = (uint32_t)(((nw + (g << 4) + b_n) * 40 + kk + b_k) << 1);
                ldsm4(bhf[g][0], bhf[g][1], bhf[g][2], bhf[g][3], uBh + off);
                ldsm4(blf[g][0], blf[g][1], blf[g][2], blf[g][3], uBl + off);
            }
#pragma unroll
            for (int mf = 0; mf < 2; mf++)
#pragma unroll
                for (int nf = 0; nf < 4; nf++) {
                    const uint32_t* ph = &bhf[nf >> 1][(nf & 1) << 1];
                    const uint32_t* pl = &blf[nf >> 1][(nf & 1) << 1];
                    mma_bf16(acc[mf][nf], ah[mf], ph);
                    mma_bf16(acc[mf][nf], ah[mf], pl);
                    mma_bf16(acc[mf][nf], al[mf], ph);
                }
        }
    }

    const int lr = lane >> 2, lc = (lane & 3) << 1;
#pragma unroll
    for (int mf = 0; mf < 2; mf++)
#pragma unroll
        for (int rp = 0; rp < 2; rp++) {
            int row = i0 + mw + (mf << 4) + lr + (rp << 3);
#pragma unroll
            for (int nf = 0; nf < 4; nf++) {
                float v0 = acc[mf][nf][(rp << 1) + 0];
                float v1 = acc[mf][nf][(rp << 1) + 1];
                int col = j0 + nw + (nf << 3) + lc;
                if (OSPLIT == 0) {
                    if (bias) {
                        v0 += bias[col];
                        v1 += bias[col + 1];
                    }
                    *(float2*)&Cf[(size_t)row * Nc + col] = make_float2(v0, v1);
                } else {
                    if (OSPLIT == 1) {
                        v0 += bias[col];
                        v1 += bias[col + 1];
                        if (ACT == 1) {
                            v0 = 0.5f * v0 * (1.0f + erff(v0 * 0.70710678118654752f));
                            v1 = 0.5f * v1 * (1.0f + erff(v1 * 0.70710678118654752f));
                        }
                    }
                    bf16 h0 = __float2bfloat16(v0), h1 = __float2bfloat16(v1);
                    Ch[(size_t)row * Nc + col] = h0;
                    Ch[(size_t)row * Nc + col + 1] = h1;
                    Cl[(size_t)row * Nc + col] = __float2bfloat16(v0 - __bfloat162float(h0));
                    Cl[(size_t)row * Nc + col + 1] = __float2bfloat16(v1 - __bfloat162float(h1));
                }
            }
        }
}

template <int ACT, int SPLIT, int OSPLIT>
__global__ void __launch_bounds__(256) hmma_gemm_kernel(
    const bf16* __restrict__ Ah, const bf16* __restrict__ Al,
    const bf16* __restrict__ Bh, const bf16* __restrict__ Bl,
    const float* __restrict__ bias, float* __restrict__ Cf,
    bf16* __restrict__ Ch, bf16* __restrict__ Cl, int Kd, int Nc) {
    int kslice = Kd / SPLIT;
    int kbeg = blockIdx.z * kslice;
    float* Cz = (SPLIT > 1) ? Cf + (size_t)blockIdx.z * Nn * Nc : Cf;
    hmma_gemm_body<ACT, OSPLIT>(Ah, Al, Bh, Bl, SPLIT > 1 ? nullptr : bias, Cz, Ch, Cl,
                                Kd, kbeg, kslice, Nc);
}

__global__ void __launch_bounds__(256) hmma_qkv_kernel(
    const bf16* __restrict__ Ah, const bf16* __restrict__ Al,
    const bf16* __restrict__ Bh0, const bf16* __restrict__ Bl0,
    const bf16* __restrict__ Bh1, const bf16* __restrict__ Bl1,
    const bf16* __restrict__ Bh2, const bf16* __restrict__ Bl2,
    bf16* __restrict__ qh, bf16* __restrict__ ql, bf16* __restrict__ kh,
    bf16* __restrict__ kl, bf16* __restrict__ vh, bf16* __restrict__ vl) {
    int z = blockIdx.z;
    const bf16* Bh = (z == 0) ? Bh0 : (z == 1) ? Bh1 : Bh2;
    const bf16* Bl = (z == 0) ? Bl0 : (z == 1) ? Bl1 : Bl2;
    bf16* Ch = (z == 0) ? qh : (z == 1) ? kh : vh;
    bf16* Cl = (z == 0) ? ql : (z == 1) ? kl : vl;
    hmma_gemm_body<0, 2>(Ah, Al, Bh, Bl, nullptr, nullptr, Ch, Cl, Dd, 0, Dd, Dd);
}

// ---------------- HMMA flash attention v2 ----------------
// 128 thr, 64 q-rows x head. K double-buffered cp.async; V natural + ldmatrix.trans;
// P hi-only bf16 (2-term PV); ex2-domain softmax.
__global__ void __launch_bounds__(128) attn_hmma_kernel(
    const bf16* __restrict__ Qh, const bf16* __restrict__ Ql,
    const bf16* __restrict__ Kh, const bf16* __restrict__ Kl,
    const bf16* __restrict__ Vh, const bf16* __restrict__ Vl,
    const unsigned char* __restrict__ E8, const float* __restrict__ ebl,
    bf16* __restrict__ Oh, bf16* __restrict__ Ol) {
    __shared__ bf16 sQh[64][40], sQl[64][40];
    __shared__ bf16 sKh[2][64][40], sKl[2][64][40];
    __shared__ bf16 sVh[64][40], sVl[64][40];
    __shared__ float s_eb[8];

    const int h = blockIdx.y;
    const int i0 = blockIdx.x << 6;
    const int tid = threadIdx.x;
    const int wid = tid >> 5, lane = tid & 31;
    const int mw = wid << 4;

    if (tid < NEDGEe) s_eb[tid] = ebl[tid * Hh + h] * 1.4426950408889634f;

    const int a_r = lane & 15, a_k = (lane >> 4) << 3;
    const int b_n = (lane & 7) + ((lane & 16) >> 1), b_k = lane & 8;
    const int lr = lane >> 2, lc = (lane & 3) << 1;

    const uint32_t uQh = smem_u32(&sQh[0][0]);
    const uint32_t uQl = smem_u32(&sQl[0][0]);
    const uint32_t uKhb[2] = {smem_u32(&sKh[0][0][0]), smem_u32(&sKh[1][0][0])};
    const uint32_t uKlb[2] = {smem_u32(&sKl[0][0][0]), smem_u32(&sKl[1][0][0])};
    const uint32_t uVh = smem_u32(&sVh[0][0]);
    const uint32_t uVl = smem_u32(&sVl[0][0]);

    const int qr = tid >> 1, qh4 = (tid & 1) << 4;
    const uint32_t soff0 = (uint32_t)((qr * 40 + qh4) << 1);   // smem byte offset
    const size_t ghead = (size_t)h * DKk + qh4;

    // Q load (plain)
    {
        const bf16* p = Qh + (size_t)(i0 + qr) * Dd + ghead;
        *(uint4*)&sQh[qr][qh4] = *(const uint4*)p;
        *(uint4*)&sQh[qr][qh4 + 8] = *(const uint4*)(p + 8);
        const bf16* p2 = Ql + (size_t)(i0 + qr) * Dd + ghead;
        *(uint4*)&sQl[qr][qh4] = *(const uint4*)p2;
        *(uint4*)&sQl[qr][qh4 + 8] = *(const uint4*)(p2 + 8);
    }

    float of[4][4];
#pragma unroll
    for (int a = 0; a < 4; a++)
#pragma unroll
        for (int b = 0; b < 4; b++) of[a][b] = 0.f;
    float m0 = -1e30f, m1 = -1e30f, l0 = 0.f, l1 = 0.f;
    const float scale2 = 0.17677669529663687f * 1.4426950408889634f;  // 1/sqrt(32)*log2(e)
    const size_t r0e = (size_t)(i0 + mw + lr) * Nn;
    const size_t r1e = (size_t)(i0 + mw + lr + 8) * Nn;

    // prologue: prefetch K tile 0 into buf 0
    {
        const bf16* pk = Kh + (size_t)qr * Dd + ghead;
        cpa16(uKhb[0] + soff0, pk);
        cpa16(uKhb[0] + soff0 + 16, pk + 8);
        const bf16* pk2 = Kl + (size_t)qr * Dd + ghead;
        cpa16(uKlb[0] + soff0, pk2);
        cpa16(uKlb[0] + soff0 + 16, pk2 + 8);
    }
    CP_COMMIT();

    for (int t = 0; t < Nn / 64; t++) {
        const int jt = t << 6;
        const int buf = t & 1;
        CP_WAIT(0);  // K(t) arrived
        __syncthreads();

        // issue V(t) (single-buffer; consumed after softmax)
        {
            const bf16* pv = Vh + (size_t)(jt + qr) * Dd + ghead;
            cpa16(uVh + soff0, pv);
            cpa16(uVh + soff0 + 16, pv + 8);
            const bf16* pv2 = Vl + (size_t)(jt + qr) * Dd + ghead;
            cpa16(uVl + soff0, pv2);
            cpa16(uVl + soff0 + 16, pv2 + 8);
        }
        CP_COMMIT();
        // issue K(t+1)
        if (t + 1 < Nn / 64) {
            const bf16* pk = Kh + (size_t)(jt + 64 + qr) * Dd + ghead;
            cpa16(uKhb[buf ^ 1] + soff0, pk);
            cpa16(uKhb[buf ^ 1] + soff0 + 16, pk + 8);
            const bf16* pk2 = Kl + (size_t)(jt + 64 + qr) * Dd + ghead;
            cpa16(uKlb[buf ^ 1] + soff0, pk2);
            cpa16(uKlb[buf ^ 1] + soff0 + 16, pk2 + 8);
        }
        CP_COMMIT();

        // edge-bias prefetch (hidden behind S MMAs)
        unsigned short eu0[8], eu1[8];
#pragma unroll
        for (int nf = 0; nf < 8; nf++) {
            eu0[nf] = *(const unsigned short*)&E8[r0e + jt + (nf << 3) + lc];
            eu1[nf] = *(const unsigned short*)&E8[r1e + jt + (nf << 3) + lc];
        }

        // ---- S = Q K^T (3-term split) ----
        float sf[8][4];
#pragma unroll
        for (int nf = 0; nf < 8; nf++)
#pragma unroll
            for (int cc = 0; cc < 4; cc++) sf[nf][cc] = 0.f;
#pragma unroll
        for (int ks = 0; ks < 2; ks++) {
            const int kk = ks << 4;
            uint32_t aqh[4], aql[4];
            uint32_t offa = (uint32_t)(((mw + a_r) * 40 + kk + a_k) << 1);
            ldsm4(aqh[0], aqh[1], aqh[2], aqh[3], uQh + offa);
            ldsm4(aql[0], aql[1], aql[2], aql[3], uQl + offa);
#pragma unroll
            for (int g = 0; g < 4; g++) {
                uint32_t bkh[4], bkl[4];
                uint32_t offb = (uint32_t)((((g << 4) + b_n) * 40 + kk + b_k) << 1);
                ldsm4(bkh[0], bkh[1], bkh[2], bkh[3], uKhb[buf] + offb);
                ldsm4(bkl[0], bkl[1], bkl[2], bkl[3], uKlb[buf] + offb);
#pragma unroll
                for (int sub = 0; sub < 2; sub++) {
                    int nf = (g << 1) + sub;
                    const uint32_t* ph = &bkh[sub << 1];
                    const uint32_t* pl = &bkl[sub << 1];
                    mma_bf16(sf[nf], aqh, ph);
                    mma_bf16(sf[nf], aqh, pl);
                    mma_bf16(sf[nf], aql, ph);
                }
            }
        }

        // ---- scale*log2e + edge bias + row max (log2 domain) ----
        float mx0 = -1e30f, mx1 = -1e30f;
#pragma unroll
        for (int nf = 0; nf < 8; nf++) {
            sf[nf][0] = fmaf(sf[nf][0], scale2, s_eb[eu0[nf] & 0xffu]);
            sf[nf][1] = fmaf(sf[nf][1], scale2, s_eb[eu0[nf] >> 8]);
            sf[nf][2] = fmaf(sf[nf][2], scale2, s_eb[eu1[nf] & 0xffu]);
            sf[nf][3] = fmaf(sf[nf][3], scale2, s_eb[eu1[nf] >> 8]);
            mx0 = fmaxf(mx0, fmaxf(sf[nf][0], sf[nf][1]));
            mx1 = fmaxf(mx1, fmaxf(sf[nf][2], sf[nf][3]));
        }
        mx0 = fmaxf(mx0, __shfl_xor_sync(0xffffffffu, mx0, 1));
        mx0 = fmaxf(mx0, __shfl_xor_sync(0xffffffffu, mx0, 2));
        mx1 = fmaxf(mx1, __shfl_xor_sync(0xffffffffu, mx1, 1));
        mx1 = fmaxf(mx1, __shfl_xor_sync(0xffffffffu, mx1, 2));
        float mn0 = fmaxf(m0, mx0), mn1 = fmaxf(m1, mx1);
        float al0 = ex2f(m0 - mn0), al1 = ex2f(m1 - mn1);
        m0 = mn0;
        m1 = mn1;
#pragma unroll
        for (int nf = 0; nf < 4; nf++) {
            of[nf][0] *= al0;
            of[nf][1] *= al0;
            of[nf][2] *= al1;
            of[nf][3] *= al1;
        }

        // ---- P = 2^(S - m), hi-only bf16 A-fragments ----
        float ps0 = 0.f, ps1 = 0.f;
        uint32_t aph[4][4];
#pragma unroll
        for (int nf = 0; nf < 8; nf++) {
            float p0 = ex2f(sf[nf][0] - mn0);
            float p1 = ex2f(sf[nf][1] - mn0);
            float p2 = ex2f(sf[nf][2] - mn1);
            float p3 = ex2f(sf[nf][3] - mn1);
            ps0 += p0 + p1;
            ps1 += p2 + p3;
            int ks = nf >> 1, base = (nf & 1) << 1;
            aph[ks][base + 0] = pack2bf(p0, p1);
            aph[ks][base + 1] = pack2bf(p2, p3);
        }
        ps0 += __shfl_xor_sync(0xffffffffu, ps0, 1);
        ps0 += __shfl_xor_sync(0xffffffffu, ps0, 2);
        ps1 += __shfl_xor_sync(0xffffffffu, ps1, 1);
        ps1 += __shfl_xor_sync(0xffffffffu, ps1, 2);
        l0 = l0 * al0 + ps0;
        l1 = l1 * al1 + ps1;

        // ---- wait V(t), then O += P V (2-term: Ph*Vh + Ph*Vl) ----
        CP_WAIT(1);  // V done; K(t+1) may still fly
        __syncthreads();
#pragma unroll
        for (int ks = 0; ks < 4; ks++) {
            const int kk = ks << 4;
#pragma unroll
            for (int dg = 0; dg < 2; dg++) {
                uint32_t bvh[4], bvl[4];
                uint32_t offv = (uint32_t)(((kk + a_r) * 40 + (dg << 4) + a_k) << 1);
                ldsm4t(bvh[0], bvh[1], bvh[2], bvh[3], uVh + offv);
                ldsm4t(bvl[0], bvl[1], bvl[2], bvl[3], uVl + offv);
#pragma unroll
                for (int sub = 0; sub < 2; sub++) {
                    int nf = (dg << 1) + sub;
                    mma_bf16(of[nf], aph[ks], &bvh[sub << 1]);
                    mma_bf16(of[nf], aph[ks], &bvl[sub << 1]);
                }
            }
        }
    }

    // ---- normalize + split-bf16 write ----
    float inv0 = 1.0f / l0, inv1 = 1.0f / l1;
    int row0 = i0 + mw + lr, row1 = row0 + 8;
#pragma unroll
    for (int nf = 0; nf < 4; nf++) {
        int col = h * DKk + (nf << 3) + lc;
        float v0 = of[nf][0] * inv0, v1 = of[nf][1] * inv0;
        float v2 = of[nf][2] * inv1, v3 = of[nf][3] * inv1;
        float h0 = __bfloat162float(__float2bfloat16(v0));
        float h1 = __bfloat162float(__float2bfloat16(v1));
        float h2 = __bfloat162float(__float2bfloat16(v2));
        float h3 = __bfloat162float(__float2bfloat16(v3));
        *(uint32_t*)&Oh[(size_t)row0 * Dd + col] = pack2bf(h0, h1);
        *(uint32_t*)&Oh[(size_t)row1 * Dd + col] = pack2bf(h2, h3);
        *(uint32_t*)&Ol[(size_t)row0 * Dd + col] = pack2bf(v0 - h0, v1 - h1);
        *(uint32_t*)&Ol[(size_t)row1 * Dd + col] = pack2bf(v2 - h2, v3 - h3);
    }
}

// ---------------- partial reduce + bias + residual + LayerNorm (+split out) ----------------
template <int S>
__global__ void addln_red_kernel(float* __restrict__ x, const float* __restrict__ part,
                                 const float* __restrict__ bias, const float* __restrict__ g,
                                 const float* __restrict__ b, bf16* __restrict__ xh,
                                 bf16* __restrict__ xl) {
    int i = blockIdx.x, d = threadIdx.x;
    __shared__ float red[256];
    float v = x[i * Dd + d] + bias[d];
#pragma unroll
    for (int s = 0; s < S; s++) v += part[(size_t)s * Nn * Dd + (size_t)i * Dd + d];
    red[d] = v;
    __syncthreads();
    for (int s = 128; s > 0; s >>= 1) {
        if (d < s) red[d] += red[d + s];
        __syncthreads();
    }
    float mean = red[0] * (1.0f / Dd);
    __syncthreads();
    float dv = v - mean;
    red[d] = dv * dv;
    __syncthreads();
    for (int s = 128; s > 0; s >>= 1) {
        if (d < s) red[d] += red[d + s];
        __syncthreads();
    }
    float var = red[0] * (1.0f / Dd);
    float outv = dv * rsqrtf(var + 1e-5f) * g[d] + b[d];
    x[i * Dd + d] = outv;
    bf16 h = __float2bfloat16(outv);
    xh[i * Dd + d] = h;
    xl[i * Dd + d] = __float2bfloat16(outv - __bfloat162float(h));
}

__global__ void pool_kernel(const float* __restrict__ x, float* __restrict__ p) {
    int j = blockIdx.x * 32 + threadIdx.x;
    int yy = threadIdx.y;
    float s = 0.f, mx = -1e30f;
    for (int i = yy; i < Nn; i += 8) {
        float v = x[(size_t)i * Dd + j];
        s += v;
        mx = fmaxf(mx, v);
    }
    __shared__ float ss[8][33], sm[8][33];
    ss[yy][threadIdx.x] = s;
    sm[yy][threadIdx.x] = mx;
    __syncthreads();
    if (yy == 0) {
        for (int k2 = 1; k2 < 8; k2++) {
            s += ss[k2][threadIdx.x];
            mx = fmaxf(mx, sm[k2][threadIdx.x]);
        }
        p[j] = s * (1.0f / Nn);
        p[Dd + j] = mx;
    }
}

__global__ void head_kernel(const float* __restrict__ pooled, const float* __restrict__ Wr,
                            const float* __restrict__ br, float* __restrict__ out) {
    __shared__ float sp[2 * Dd];
    int d = threadIdx.x;
    sp[d] = pooled[d];
    sp[d + Dd] = pooled[d + Dd];
    __syncthreads();
    float acc = br[d];
#pragma unroll 8
    for (int k2 = 0; k2 < 2 * Dd; k2++) acc = fmaf(sp[k2], Wr[(size_t)k2 * Dd + d], acc);
    out[d] = acc;
}

// ---------------- host launcher ----------------
extern "C" void kernel_launch(void* const* d_in, const int* in_sizes, int n_in,
                              void* d_out, int out_size) {
    const int* node_types = (const int*)d_in[0];
    const int* edge_idx = (const int*)d_in[1];
    const float* node_emb = (const float*)d_in[2];
    const float* Wq = (const float*)d_in[3];
    const float* Wk = (const float*)d_in[4];
    const float* Wv = (const float*)d_in[5];
    const float* Wo = (const float*)d_in[6];
    const float* bo = (const float*)d_in[7];
    const float* eb = (const float*)d_in[8];
    const float* W1 = (const float*)d_in[9];
    const float* b1 = (const float*)d_in[10];
    const float* W2 = (const float*)d_in[11];
    const float* b2 = (const float*)d_in[12];
    const float* ln1g = (const float*)d_in[13];
    const float* ln1b = (const float*)d_in[14];
    const float* ln2g = (const float*)d_in[15];
    const float* ln2b = (const float*)d_in[16];
    const float* Wr = (const float*)d_in[17];
    const float* brr = (const float*)d_in[18];
    float* out = (float*)d_out;

    float *x, *part, *pool;
    unsigned char* e8;
    bf16 *xh, *xl, *qh, *ql, *kh, *kl, *vh, *vl, *atth, *attl, *t1h, *t1l;
    bf16 *wqh, *wql, *wkh, *wkl, *wvh, *wvl, *woh, *wol, *w1h, *w1l, *w2h, *w2l;
    cudaGetSymbolAddress((void**)&x, g_x);
    cudaGetSymbolAddress((void**)&part, g_part);
    cudaGetSymbolAddress((void**)&pool, g_pool);
    cudaGetSymbolAddress((void**)&e8, g_e8);
    cudaGetSymbolAddress((void**)&xh, g_xh);
    cudaGetSymbolAddress((void**)&xl, g_xl);
    cudaGetSymbolAddress((void**)&qh, g_qh);
    cudaGetSymbolAddress((void**)&ql, g_ql);
    cudaGetSymbolAddress((void**)&kh, g_kh);
    cudaGetSymbolAddress((void**)&kl, g_kl);
    cudaGetSymbolAddress((void**)&vh, g_vh);
    cudaGetSymbolAddress((void**)&vl, g_vl);
    cudaGetSymbolAddress((void**)&atth, g_atth);
    cudaGetSymbolAddress((void**)&attl, g_attl);
    cudaGetSymbolAddress((void**)&t1h, g_t1h);
    cudaGetSymbolAddress((void**)&t1l, g_t1l);
    cudaGetSymbolAddress((void**)&wqh, g_wqh);
    cudaGetSymbolAddress((void**)&wql, g_wql);
    cudaGetSymbolAddress((void**)&wkh, g_wkh);
    cudaGetSymbolAddress((void**)&wkl, g_wkl);
    cudaGetSymbolAddress((void**)&wvh, g_wvh);
    cudaGetSymbolAddress((void**)&wvl, g_wvl);
    cudaGetSymbolAddress((void**)&woh, g_woh);
    cudaGetSymbolAddress((void**)&wol, g_wol);
    cudaGetSymbolAddress((void**)&w1h, g_w1h);
    cudaGetSymbolAddress((void**)&w1l, g_w1l);
    cudaGetSymbolAddress((void**)&w2h, g_w2h);
    cudaGetSymbolAddress((void**)&w2l, g_w2l);

    embed_kernel<<<Nn, Dd>>>(node_types, node_emb, x, xh, xl);
    cvt_e8_kernel<<<(Nn * Nn / 4) / 256, 256>>>(edge_idx, e8);

    wsplit_kernel<<<dim3(8, 8, Ll), dim3(32, 8)>>>(Wq, wqh, wql, Dd, Dd);
    wsplit_kernel<<<dim3(8, 8, Ll), dim3(32, 8)>>>(Wk, wkh, wkl, Dd, Dd);
    wsplit_kernel<<<dim3(8, 8, Ll), dim3(32, 8)>>>(Wv, wvh, wvl, Dd, Dd);
    wsplit_kernel<<<dim3(8, 8, Ll), dim3(32, 8)>>>(Wo, woh, wol, Dd, Dd);
    wsplit_kernel<<<dim3(32, 8, Ll), dim3(32, 8)>>>(W1, w1h, w1l, Dd, DFFf);
    wsplit_kernel<<<dim3(8, 32, Ll), dim3(32, 8)>>>(W2, w2h, w2l, DFFf, Dd);

    for (int l = 0; l < Ll; l++) {
        size_t wo256 = (size_t)l * Dd * Dd;
        size_t woff1 = (size_t)l * Dd * DFFf;
        hmma_qkv_kernel<<<dim3(4, 16, 3), 256>>>(
            xh, xl, wqh + wo256, wql + wo256, wkh + wo256, wkl + wo256, wvh + wo256,
            wvl + wo256, qh, ql, kh, kl, vh, vl);

        attn_hmma_kernel<<<dim3(Nn / 64, Hh), 128>>>(qh, ql, kh, kl, vh, vl, e8,
                                                     eb + l * NEDGEe * Hh, atth, attl);

        hmma_gemm_kernel<0, 2, 0><<<dim3(4, 16, 2), 256>>>(
            atth, attl, woh + wo256, wol + wo256, nullptr, part, nullptr, nullptr, Dd, Dd);
        addln_red_kernel<2><<<Nn, Dd>>>(x, part, bo + l * Dd, ln1g + l * Dd, ln1b + l * Dd, xh,
                                        xl);

        hmma_gemm_kernel<1, 1, 1><<<dim3(16, 16, 1), 256>>>(
            xh, xl, w1h + woff1, w1l + woff1, b1 + l * DFFf, nullptr, t1h, t1l, Dd, DFFf);

        hmma_gemm_kernel<0, 2, 0><<<dim3(4, 16, 2), 256>>>(
            t1h, t1l, w2h + woff1, w2l + woff1, nullptr, part, nullptr, nullptr, DFFf, Dd);
        addln_red_kernel<2><<<Nn, Dd>>>(x, part, b2 + l * Dd, ln2g + l * Dd, ln2b + l * Dd, xh,
                                        xl);
    }

    pool_kernel<<<Dd / 32, dim3(32, 8)>>>(x, pool);
    head_kernel<<<1, Dd>>>(pool, Wr, brr, out);
}

// round 11
// speedup vs baseline: 1.8724x; 1.0657x over previous
#include <cuda_runtime.h>
#include <cuda_bf16.h>
#include <stdint.h>
#include <math.h>

#define Nn 2048
#define Dd 256
#define Hh 8
#define DKk 32
#define Ll 4
#define DFFf 1024
#define NEDGEe 5

typedef __nv_bfloat16 bf16;

// ---------------- portable MMA helpers (validated R8-R10) ----------------
__device__ __forceinline__ uint32_t smem_u32(const void* p) {
    uint32_t a;
    asm("{ .reg .u64 t; cvta.to.shared.u64 t, %1; cvt.u32.u64 %0, t; }" : "=r"(a) : "l"(p));
    return a;
}
__device__ __forceinline__ void ldsm4(uint32_t& r0, uint32_t& r1, uint32_t& r2, uint32_t& r3,
                                      uint32_t addr) {
    asm volatile("ldmatrix.sync.aligned.m8n8.x4.shared.b16 {%0,%1,%2,%3}, [%4];"
                 : "=r"(r0), "=r"(r1), "=r"(r2), "=r"(r3)
                 : "r"(addr));
}
__device__ __forceinline__ void ldsm4t(uint32_t& r0, uint32_t& r1, uint32_t& r2, uint32_t& r3,
                                       uint32_t addr) {
    asm volatile("ldmatrix.sync.aligned.m8n8.x4.trans.shared.b16 {%0,%1,%2,%3}, [%4];"
                 : "=r"(r0), "=r"(r1), "=r"(r2), "=r"(r3)
                 : "r"(addr));
}
__device__ __forceinline__ void mma_bf16(float* d, const uint32_t* a, const uint32_t* b) {
    asm volatile(
        "mma.sync.aligned.m16n8k16.row.col.f32.bf16.bf16.f32 "
        "{%0,%1,%2,%3}, {%4,%5,%6,%7}, {%8,%9}, {%0,%1,%2,%3};"
        : "+f"(d[0]), "+f"(d[1]), "+f"(d[2]), "+f"(d[3])
        : "r"(a[0]), "r"(a[1]), "r"(a[2]), "r"(a[3]), "r"(b[0]), "r"(b[1]));
}
__device__ __forceinline__ uint32_t pack2bf(float a, float b) {
    uint32_t r;
    asm("cvt.rn.bf16x2.f32 %0, %1, %2;" : "=r"(r) : "f"(b), "f"(a));
    return r;
}
__device__ __forceinline__ float ex2f(float x) {
    float y;
    asm("ex2.approx.f32 %0, %1;" : "=f"(y) : "f"(x));
    return y;
}
__device__ __forceinline__ void cpa16(uint32_t dst, const void* src) {
    asm volatile("cp.async.cg.shared.global [%0], [%1], 16;" :: "r"(dst), "l"(src));
}
#define CP_COMMIT() asm volatile("cp.async.commit_group;" ::: "memory")
#define CP_WAIT(n) asm volatile("cp.async.wait_group %0;" :: "n"(n) : "memory")

// ---------------- scratch ----------------
__device__ float g_x[Nn * Dd];
__device__ float g_part[2 * Nn * Dd];
__device__ unsigned char g_e8[Nn * Nn];
__device__ float g_pool[2 * Dd];
__device__ bf16 g_xh[Nn * Dd], g_xl[Nn * Dd];
__device__ bf16 g_qh[Nn * Dd], g_ql[Nn * Dd];
__device__ bf16 g_kh[Nn * Dd], g_kl[Nn * Dd];
__device__ bf16 g_vh[Nn * Dd], g_vl[Nn * Dd];
__device__ bf16 g_atth[Nn * Dd], g_attl[Nn * Dd];
__device__ bf16 g_t1h[Nn * DFFf], g_t1l[Nn * DFFf];
__device__ bf16 g_wqh[Ll * Dd * Dd], g_wql[Ll * Dd * Dd];
__device__ bf16 g_wkh[Ll * Dd * Dd], g_wkl[Ll * Dd * Dd];
__device__ bf16 g_wvh[Ll * Dd * Dd], g_wvl[Ll * Dd * Dd];
__device__ bf16 g_woh[Ll * Dd * Dd], g_wol[Ll * Dd * Dd];
__device__ bf16 g_w1h[Ll * Dd * DFFf], g_w1l[Ll * Dd * DFFf];
__device__ bf16 g_w2h[Ll * DFFf * Dd], g_w2l[Ll * DFFf * Dd];

// ---------------- embedding gather (+split) ----------------
__global__ void embed_kernel(const int* __restrict__ nt, const float* __restrict__ emb,
                             float* __restrict__ x, bf16* __restrict__ xh, bf16* __restrict__ xl) {
    int i = blockIdx.x;
    int d = threadIdx.x;
    float v = emb[nt[i] * Dd + d];
    x[i * Dd + d] = v;
    bf16 h = __float2bfloat16(v);
    xh[i * Dd + d] = h;
    xl[i * Dd + d] = __float2bfloat16(v - __bfloat162float(h));
}

__global__ void cvt_e8_kernel(const int* __restrict__ e, unsigned char* __restrict__ o) {
    int i = blockIdx.x * blockDim.x + threadIdx.x;
    int4 v = ((const int4*)e)[i];
    uchar4 u;
    u.x = (unsigned char)v.x; u.y = (unsigned char)v.y;
    u.z = (unsigned char)v.z; u.w = (unsigned char)v.w;
    ((uchar4*)o)[i] = u;
}

// ---------------- weight transpose + split ----------------
__global__ void wsplit_kernel(const float* __restrict__ W, bf16* __restrict__ Th,
                              bf16* __restrict__ Tl, int Kd, int Nc) {
    __shared__ float sh[32][33], slo[32][33];
    const float* Wl = W + (size_t)blockIdx.z * Kd * Nc;
    bf16* Thl = Th + (size_t)blockIdx.z * Kd * Nc;
    bf16* Tll = Tl + (size_t)blockIdx.z * Kd * Nc;
    int n0 = blockIdx.x << 5, k0 = blockIdx.y << 5;
    int tx = threadIdx.x, ty = threadIdx.y;
#pragma unroll
    for (int r = 0; r < 4; r++) {
        int kk = ty + (r << 3);
        float v = Wl[(size_t)(k0 + kk) * Nc + n0 + tx];
        float h = __bfloat162float(__float2bfloat16(v));
        sh[kk][tx] = h;
        slo[kk][tx] = v - h;
    }
    __syncthreads();
#pragma unroll
    for (int r = 0; r < 4; r++) {
        int nn = ty + (r << 3);
        Thl[(size_t)(n0 + nn) * Kd + k0 + tx] = __float2bfloat16(sh[tx][nn]);
        Tll[(size_t)(n0 + nn) * Kd + k0 + tx] = __float2bfloat16(slo[tx][nn]);
    }
}

// ---------------- split-bf16 HMMA GEMM with register prefetch ----------------
template <int ACT, int OSPLIT>
__device__ __forceinline__ void hmma_gemm_body(
    const bf16* __restrict__ Ah, const bf16* __restrict__ Al,
    const bf16* __restrict__ Bh, const bf16* __restrict__ Bl,
    const float* __restrict__ bias, float* __restrict__ Cf,
    bf16* __restrict__ Ch, bf16* __restrict__ Cl,
    int Kd, int kbeg, int kslice, int Nc) {
    __shared__ bf16 sAh[128][40], sAl[128][40], sBh[64][40], sBl[64][40];
    const int tid = threadIdx.x;
    const int wid = tid >> 5, lane = tid & 31;
    const int i0 = blockIdx.y << 7, j0 = blockIdx.x << 6;
    const int mw = (wid & 3) << 5;
    const int nw = (wid >> 2) << 5;

    float acc[2][4][4];
#pragma unroll
    for (int a = 0; a < 2; a++)
#pragma unroll
        for (int b = 0; b < 4; b++)
#pragma unroll
            for (int cc = 0; cc < 4; cc++) acc[a][b][cc] = 0.f;

    const int a_r = lane & 15;
    const int a_k = (lane >> 4) << 3;
    const int b_n = (lane & 7) + ((lane & 16) >> 1);
    const int b_k = lane & 8;

    const uint32_t uAh = smem_u32(&sAh[0][0]);
    const uint32_t uAl = smem_u32(&sAl[0][0]);
    const uint32_t uBh = smem_u32(&sBh[0][0]);
    const uint32_t uBl = smem_u32(&sBl[0][0]);

    const int r = tid >> 1, hf = (tid & 1) << 4;
    const int tb = tid & 127;
    const int rb = tb >> 1, hb = (tb & 1) << 4;
    const bf16* Bsel = (tid < 128) ? Bh : Bl;

    uint4 rA0, rA1, rA2, rA3, rB0, rB1;
    // prologue: load chunk 0 into registers
    {
        const bf16* pAh = Ah + (size_t)(i0 + r) * Kd + kbeg + hf;
        const bf16* pAl = Al + (size_t)(i0 + r) * Kd + kbeg + hf;
        rA0 = *(const uint4*)pAh;
        rA1 = *(const uint4*)(pAh + 8);
        rA2 = *(const uint4*)pAl;
        rA3 = *(const uint4*)(pAl + 8);
        const bf16* pB = Bsel + (size_t)(j0 + rb) * Kd + kbeg + hb;
        rB0 = *(const uint4*)pB;
        rB1 = *(const uint4*)(pB + 8);
    }

    const int nch = kslice >> 5;
    for (int c = 0; c < nch; c++) {
        // store regs -> smem
        *(uint4*)&sAh[r][hf] = rA0;
        *(uint4*)&sAh[r][hf + 8] = rA1;
        *(uint4*)&sAl[r][hf] = rA2;
        *(uint4*)&sAl[r][hf + 8] = rA3;
        if (tid < 128) {
            *(uint4*)&sBh[rb][hb] = rB0;
            *(uint4*)&sBh[rb][hb + 8] = rB1;
        } else {
            *(uint4*)&sBl[rb][hb] = rB0;
            *(uint4*)&sBl[rb][hb + 8] = rB1;
        }
        __syncthreads();

        // prefetch next chunk (LDG issues before the MMA block; consumed after)
        if (c + 1 < nch) {
            int kt = kbeg + ((c + 1) << 5);
            const bf16* pAh = Ah + (size_t)(i0 + r) * Kd + kt + hf;
            const bf16* pAl = Al + (size_t)(i0 + r) * Kd + kt + hf;
            rA0 = *(const uint4*)pAh;
            rA1 = *(const uint4*)(pAh + 8);
            rA2 = *(const uint4*)pAl;
            rA3 = *(const uint4*)(pAl + 8);
            const bf16* pB = Bsel + (size_t)(j0 + rb) * Kd + kt + hb;
            rB0 = *(const uint4*)pB;
            rB1 = *(const uint4*)(pB + 8);
        }

#pragma unroll
        for (int ks = 0; ks < 2; ks++) {
            const int kk = ks << 4;
            uint32_t ah[2][4], al[2][4], bhf[2][4], blf[2][4];
#pragma unroll
            for (int mf = 0; mf < 2; mf++) {
                uint32_t off = (uint32_t)(((mw + (mf << 4) + a_r) * 40 + kk + a_k) << 1);
                ldsm4(ah[mf][0], ah[mf][1], ah[mf][2], ah[mf][3], uAh + off);
                ldsm4(al[mf][0], al[mf][1], al[mf][2], al[mf][3], uAl + off);
            }
#pragma unroll
            for (int g = 0; g < 2; g++) {
                uint32_t off = (uint32_t)(((nw + (g << 4) + b_n) * 40 + kk + b_k) << 1);
                ldsm4(bhf[g][0], bhf[g][1], bhf[g][2], bhf[g][3], uBh + off);
                ldsm4(blf[g][0], blf[g][1], blf[g][2], blf[g][3], uBl + off);
            }
#pragma unroll
            for (int mf = 0; mf < 2; mf++)
#pragma unroll
                for (int nf = 0; nf < 4; nf++) {
                    const uint32_t* ph = &bhf[nf >> 1][(nf & 1) << 1];
                    const uint32_t* pl = &blf[nf >> 1][(nf & 1) << 1];
                    mma_bf16(acc[mf][nf], ah[mf], ph);
                    mma_bf16(acc[mf][nf], ah[mf], pl);
                    mma_bf16(acc[mf][nf], al[mf], ph);
                }
        }
        if (c + 1 < nch) __syncthreads();  // smem reads done before next store
    }

    const int lr = lane >> 2, lc = (lane & 3) << 1;
#pragma unroll
    for (int mf = 0; mf < 2; mf++)
#pragma unroll
        for (int rp = 0; rp < 2; rp++) {
            int row = i0 + mw + (mf << 4) + lr + (rp << 3);
#pragma unroll
            for (int nf = 0; nf < 4; nf++) {
                float v0 = acc[mf][nf][(rp << 1) + 0];
                float v1 = acc[mf][nf][(rp << 1) + 1];
                int col = j0 + nw + (nf << 3) + lc;
                if (OSPLIT == 0) {
                    if (bias) {
                        v0 += bias[col];
                        v1 += bias[col + 1];
                    }
                    *(float2*)&Cf[(size_t)row * Nc + col] = make_float2(v0, v1);
                } else {
                    if (OSPLIT == 1) {
                        v0 += bias[col];
                        v1 += bias[col + 1];
                        if (ACT == 1) {
                            v0 = 0.5f * v0 * (1.0f + erff(v0 * 0.70710678118654752f));
                            v1 = 0.5f * v1 * (1.0f + erff(v1 * 0.70710678118654752f));
                        }
                    }
                    bf16 h0 = __float2bfloat16(v0), h1 = __float2bfloat16(v1);
                    Ch[(size_t)row * Nc + col] = h0;
                    Ch[(size_t)row * Nc + col + 1] = h1;
                    Cl[(size_t)row * Nc + col] = __float2bfloat16(v0 - __bfloat162float(h0));
                    Cl[(size_t)row * Nc + col + 1] = __float2bfloat16(v1 - __bfloat162float(h1));
                }
            }
        }
}

template <int ACT, int SPLIT, int OSPLIT>
__global__ void __launch_bounds__(256) hmma_gemm_kernel(
    const bf16* __restrict__ Ah, const bf16* __restrict__ Al,
    const bf16* __restrict__ Bh, const bf16* __restrict__ Bl,
    const float* __restrict__ bias, float* __restrict__ Cf,
    bf16* __restrict__ Ch, bf16* __restrict__ Cl, int Kd, int Nc) {
    int kslice = Kd / SPLIT;
    int kbeg = blockIdx.z * kslice;
    float* Cz = (SPLIT > 1) ? Cf + (size_t)blockIdx.z * Nn * Nc : Cf;
    hmma_gemm_body<ACT, OSPLIT>(Ah, Al, Bh, Bl, SPLIT > 1 ? nullptr : bias, Cz, Ch, Cl,
                                Kd, kbeg, kslice, Nc);
}

__global__ void __launch_bounds__(256) hmma_qkv_kernel(
    const bf16* __restrict__ Ah, const bf16* __restrict__ Al,
    const bf16* __restrict__ Bh0, const bf16* __restrict__ Bl0,
    const bf16* __restrict__ Bh1, const bf16* __restrict__ Bl1,
    const bf16* __restrict__ Bh2, const bf16* __restrict__ Bl2,
    bf16* __restrict__ qh, bf16* __restrict__ ql, bf16* __restrict__ kh,
    bf16* __restrict__ kl, bf16* __restrict__ vh, bf16* __restrict__ vl) {
    int z = blockIdx.z;
    const bf16* Bh = (z == 0) ? Bh0 : (z == 1) ? Bh1 : Bh2;
    const bf16* Bl = (z == 0) ? Bl0 : (z == 1) ? Bl1 : Bl2;
    bf16* Ch = (z == 0) ? qh : (z == 1) ? kh : vh;
    bf16* Cl = (z == 0) ? ql : (z == 1) ? kl : vl;
    hmma_gemm_body<0, 2>(Ah, Al, Bh, Bl, nullptr, nullptr, Ch, Cl, Dd, 0, Dd, Dd);
}

// ---------------- HMMA flash attention v2 (unchanged from R10) ----------------
__global__ void __launch_bounds__(128) attn_hmma_kernel(
    const bf16* __restrict__ Qh, const bf16* __restrict__ Ql,
    const bf16* __restrict__ Kh, const bf16* __restrict__ Kl,
    const bf16* __restrict__ Vh, const bf16* __restrict__ Vl,
    const unsigned char* __restrict__ E8, const float* __restrict__ ebl,
    bf16* __restrict__ Oh, bf16* __restrict__ Ol) {
    __shared__ bf16 sQh[64][40], sQl[64][40];
    __shared__ bf16 sKh[2][64][40], sKl[2][64][40];
    __shared__ bf16 sVh[64][40], sVl[64][40];
    __shared__ float s_eb[8];

    const int h = blockIdx.y;
    const int i0 = blockIdx.x << 6;
    const int tid = threadIdx.x;
    const int wid = tid >> 5, lane = tid & 31;
    const int mw = wid << 4;

    if (tid < NEDGEe) s_eb[tid] = ebl[tid * Hh + h] * 1.4426950408889634f;

    const int a_r = lane & 15, a_k = (lane >> 4) << 3;
    const int b_n = (lane & 7) + ((lane & 16) >> 1), b_k = lane & 8;
    const int lr = lane >> 2, lc = (lane & 3) << 1;

    const uint32_t uQh = smem_u32(&sQh[0][0]);
    const uint32_t uQl = smem_u32(&sQl[0][0]);
    const uint32_t uKhb[2] = {smem_u32(&sKh[0][0][0]), smem_u32(&sKh[1][0][0])};
    const uint32_t uKlb[2] = {smem_u32(&sKl[0][0][0]), smem_u32(&sKl[1][0][0])};
    const uint32_t uVh = smem_u32(&sVh[0][0]);
    const uint32_t uVl = smem_u32(&sVl[0][0]);

    const int qr = tid >> 1, qh4 = (tid & 1) << 4;
    const uint32_t soff0 = (uint32_t)((qr * 40 + qh4) << 1);
    const size_t ghead = (size_t)h * DKk + qh4;

    {
        const bf16* p = Qh + (size_t)(i0 + qr) * Dd + ghead;
        *(uint4*)&sQh[qr][qh4] = *(const uint4*)p;
        *(uint4*)&sQh[qr][qh4 + 8] = *(const uint4*)(p + 8);
        const bf16* p2 = Ql + (size_t)(i0 + qr) * Dd + ghead;
        *(uint4*)&sQl[qr][qh4] = *(const uint4*)p2;
        *(uint4*)&sQl[qr][qh4 + 8] = *(const uint4*)(p2 + 8);
    }

    float of[4][4];
#pragma unroll
    for (int a = 0; a < 4; a++)
#pragma unroll
        for (int b = 0; b < 4; b++) of[a][b] = 0.f;
    float m0 = -1e30f, m1 = -1e30f, l0 = 0.f, l1 = 0.f;
    const float scale2 = 0.17677669529663687f * 1.4426950408889634f;
    const size_t r0e = (size_t)(i0 + mw + lr) * Nn;
    const size_t r1e = (size_t)(i0 + mw + lr + 8) * Nn;

    {
        const bf16* pk = Kh + (size_t)qr * Dd + ghead;
        cpa16(uKhb[0] + soff0, pk);
        cpa16(uKhb[0] + soff0 + 16, pk + 8);
        const bf16* pk2 = Kl + (size_t)qr * Dd + ghead;
        cpa16(uKlb[0] + soff0, pk2);
        cpa16(uKlb[0] + soff0 + 16, pk2 + 8);
    }
    CP_COMMIT();

    for (int t = 0; t < Nn / 64; t++) {
        const int jt = t << 6;
        const int buf = t & 1;
        CP_WAIT(0);
        __syncthreads();

        {
            const bf16* pv = Vh + (size_t)(jt + qr) * Dd + ghead;
            cpa16(uVh + soff0, pv);
            cpa16(uVh + soff0 + 16, pv + 8);
            const bf16* pv2 = Vl + (size_t)(jt + qr) * Dd + ghead;
            cpa16(uVl + soff0, pv2);
            cpa16(uVl + soff0 + 16, pv2 + 8);
        }
        CP_COMMIT();
        if (t + 1 < Nn / 64) {
            const bf16* pk = Kh + (size_t)(jt + 64 + qr) * Dd + ghead;
            cpa16(uKhb[buf ^ 1] + soff0, pk);
            cpa16(uKhb[buf ^ 1] + soff0 + 16, pk + 8);
            const bf16* pk2 = Kl + (size_t)(jt + 64 + qr) * Dd + ghead;
            cpa16(uKlb[buf ^ 1] + soff0, pk2);
            cpa16(uKlb[buf ^ 1] + soff0 + 16, pk2 + 8);
        }
        CP_COMMIT();

        unsigned short eu0[8], eu1[8];
#pragma unroll
        for (int nf = 0; nf < 8; nf++) {
            eu0[nf] = *(const unsigned short*)&E8[r0e + jt + (nf << 3) + lc];
            eu1[nf] = *(const unsigned short*)&E8[r1e + jt + (nf << 3) + lc];
        }

        float sf[8][4];
#pragma unroll
        for (int nf = 0; nf < 8; nf++)
#pragma unroll
            for (int cc = 0; cc < 4; cc++) sf[nf][cc] = 0.f;
#pragma unroll
        for (int ks = 0; ks < 2; ks++) {
            const int kk = ks << 4;
            uint32_t aqh[4], aql[4];
            uint32_t offa = (uint32_t)(((mw + a_r) * 40 + kk + a_k) << 1);
            ldsm4(aqh[0], aqh[1], aqh[2], aqh[3], uQh + offa);
            ldsm4(aql[0], aql[1], aql[2], aql[3], uQl + offa);
#pragma unroll
            for (int g = 0; g < 4; g++) {
                uint32_t bkh[4], bkl[4];
                uint32_t offb = (uint32_t)((((g << 4) + b_n) * 40 + kk + b_k) << 1);
                ldsm4(bkh[0], bkh[1], bkh[2], bkh[3], uKhb[buf] + offb);
                ldsm4(bkl[0], bkl[1], bkl[2], bkl[3], uKlb[buf] + offb);
#pragma unroll
                for (int sub = 0; sub < 2; sub++) {
                    int nf = (g << 1) + sub;
                    const uint32_t* ph = &bkh[sub << 1];
                    const uint32_t* pl = &bkl[sub << 1];
                    mma_bf16(sf[nf], aqh, ph);
                    mma_bf16(sf[nf], aqh, pl);
                    mma_bf16(sf[nf], aql, ph);
                }
            }
        }

        float mx0 = -1e30f, mx1 = -1e30f;
#pragma unroll
        for (int nf = 0; nf < 8; nf++) {
            sf[nf][0] = fmaf(sf[nf][0], scale2, s_eb[eu0[nf] & 0xffu]);
            sf[nf][1] = fmaf(sf[nf][1], scale2, s_eb[eu0[nf] >> 8]);
            sf[nf][2] = fmaf(sf[nf][2], scale2, s_eb[eu1[nf] & 0xffu]);
            sf[nf][3] = fmaf(sf[nf][3], scale2, s_eb[eu1[nf] >> 8]);
            mx0 = fmaxf(mx0, fmaxf(sf[nf][0], sf[nf][1]));
            mx1 = fmaxf(mx1, fmaxf(sf[nf][2], sf[nf][3]));
        }
        mx0 = fmaxf(mx0, __shfl_xor_sync(0xffffffffu, mx0, 1));
        mx0 = fmaxf(mx0, __shfl_xor_sync(0xffffffffu, mx0, 2));
        mx1 = fmaxf(mx1, __shfl_xor_sync(0xffffffffu, mx1, 1));
        mx1 = fmaxf(mx1, __shfl_xor_sync(0xffffffffu, mx1, 2));
        float mn0 = fmaxf(m0, mx0), mn1 = fmaxf(m1, mx1);
        float al0 = ex2f(m0 - mn0), al1 = ex2f(m1 - mn1);
        m0 = mn0;
        m1 = mn1;
#pragma unroll
        for (int nf = 0; nf < 4; nf++) {
            of[nf][0] *= al0;
            of[nf][1] *= al0;
            of[nf][2] *= al1;
            of[nf][3] *= al1;
        }

        float ps0 = 0.f, ps1 = 0.f;
        uint32_t aph[4][4];
#pragma unroll
        for (int nf = 0; nf < 8; nf++) {
            float p0 = ex2f(sf[nf][0] - mn0);
            float p1 = ex2f(sf[nf][1] - mn0);
            float p2 = ex2f(sf[nf][2] - mn1);
            float p3 = ex2f(sf[nf][3] - mn1);
            ps0 += p0 + p1;
            ps1 += p2 + p3;
            int ks = nf >> 1, base = (nf & 1) << 1;
            aph[ks][base + 0] = pack2bf(p0, p1);
            aph[ks][base + 1] = pack2bf(p2, p3);
        }
        ps0 += __shfl_xor_sync(0xffffffffu, ps0, 1);
        ps0 += __shfl_xor_sync(0xffffffffu, ps0, 2);
        ps1 += __shfl_xor_sync(0xffffffffu, ps1, 1);
        ps1 += __shfl_xor_sync(0xffffffffu, ps1, 2);
        l0 = l0 * al0 + ps0;
        l1 = l1 * al1 + ps1;

        CP_WAIT(1);
        __syncthreads();
#pragma unroll
        for (int ks = 0; ks < 4; ks++) {
            const int kk = ks << 4;
#pragma unroll
            for (int dg = 0; dg < 2; dg++) {
                uint32_t bvh[4], bvl[4];
                uint32_t offv = (uint32_t)(((kk + a_r) * 40 + (dg << 4) + a_k) << 1);
                ldsm4t(bvh[0], bvh[1], bvh[2], bvh[3], uVh + offv);
                ldsm4t(bvl[0], bvl[1], bvl[2], bvl[3], uVl + offv);
#pragma unroll
                for (int sub = 0; sub < 2; sub++) {
                    int nf = (dg << 1) + sub;
                    mma_bf16(of[nf], aph[ks], &bvh[sub << 1]);
                    mma_bf16(of[nf], aph[ks], &bvl[sub << 1]);
                }
            }
        }
    }

    float inv0 = 1.0f / l0, inv1 = 1.0f / l1;
    int row0 = i0 + mw + lr, row1 = row0 + 8;
#pragma unroll
    for (int nf = 0; nf < 4; nf++) {
        int col = h * DKk + (nf << 3) + lc;
        float v0 = of[nf][0] * inv0, v1 = of[nf][1] * inv0;
        float v2 = of[nf][2] * inv1, v3 = of[nf][3] * inv1;
        float h0 = __bfloat162float(__float2bfloat16(v0));
        float h1 = __bfloat162float(__float2bfloat16(v1));
        float h2 = __bfloat162float(__float2bfloat16(v2));
        float h3 = __bfloat162float(__float2bfloat16(v3));
        *(uint32_t*)&Oh[(size_t)row0 * Dd + col] = pack2bf(h0, h1);
        *(uint32_t*)&Oh[(size_t)row1 * Dd + col] = pack2bf(h2, h3);
        *(uint32_t*)&Ol[(size_t)row0 * Dd + col] = pack2bf(v0 - h0, v1 - h1);
        *(uint32_t*)&Ol[(size_t)row1 * Dd + col] = pack2bf(v2 - h2, v3 - h3);
    }
}

// ---------------- reduce + bias + residual + LayerNorm, warp-shuffle version ------
template <int S>
__global__ void addln_red_kernel(float* __restrict__ x, const float* __restrict__ part,
                                 const float* __restrict__ bias, const float* __restrict__ g,
                                 const float* __restrict__ b, bf16* __restrict__ xh,
                                 bf16* __restrict__ xl) {
    int i = blockIdx.x, d = threadIdx.x;
    int lane = d & 31, w = d >> 5;
    __shared__ float ws[8];
    float v = x[i * Dd + d] + bias[d];
#pragma unroll
    for (int s = 0; s < S; s++) v += part[(size_t)s * Nn * Dd + (size_t)i * Dd + d];
    float t = v;
#pragma unroll
    for (int off = 16; off > 0; off >>= 1) t += __shfl_xor_sync(0xffffffffu, t, off);
    if (lane == 0) ws[w] = t;
    __syncthreads();
    float mean = (ws[0] + ws[1] + ws[2] + ws[3] + ws[4] + ws[5] + ws[6] + ws[7]) * (1.0f / Dd);
    float dv = v - mean;
    t = dv * dv;
#pragma unroll
    for (int off = 16; off > 0; off >>= 1) t += __shfl_xor_sync(0xffffffffu, t, off);
    __syncthreads();  // all reads of ws (mean) done before overwrite
    if (lane == 0) ws[w] = t;
    __syncthreads();
    float var = (ws[0] + ws[1] + ws[2] + ws[3] + ws[4] + ws[5] + ws[6] + ws[7]) * (1.0f / Dd);
    float outv = dv * rsqrtf(var + 1e-5f) * g[d] + b[d];
    x[i * Dd + d] = outv;
    bf16 h = __float2bfloat16(outv);
    xh[i * Dd + d] = h;
    xl[i * Dd + d] = __float2bfloat16(outv - __bfloat162float(h));
}

__global__ void pool_kernel(const float* __restrict__ x, float* __restrict__ p) {
    int j = blockIdx.x * 32 + threadIdx.x;
    int yy = threadIdx.y;
    float s = 0.f, mx = -1e30f;
    for (int i = yy; i < Nn; i += 8) {
        float v = x[(size_t)i * Dd + j];
        s += v;
        mx = fmaxf(mx, v);
    }
    __shared__ float ss[8][33], sm[8][33];
    ss[yy][threadIdx.x] = s;
    sm[yy][threadIdx.x] = mx;
    __syncthreads();
    if (yy == 0) {
        for (int k2 = 1; k2 < 8; k2++) {
            s += ss[k2][threadIdx.x];
            mx = fmaxf(mx, sm[k2][threadIdx.x]);
        }
        p[j] = s * (1.0f / Nn);
        p[Dd + j] = mx;
    }
}

__global__ void head_kernel(const float* __restrict__ pooled, const float* __restrict__ Wr,
                            const float* __restrict__ br, float* __restrict__ out) {
    __shared__ float sp[2 * Dd];
    int d = threadIdx.x;
    sp[d] = pooled[d];
    sp[d + Dd] = pooled[d + Dd];
    __syncthreads();
    float acc = br[d];
#pragma unroll 8
    for (int k2 = 0; k2 < 2 * Dd; k2++) acc = fmaf(sp[k2], Wr[(size_t)k2 * Dd + d], acc);
    out[d] = acc;
}

// ---------------- host launcher ----------------
extern "C" void kernel_launch(void* const* d_in, const int* in_sizes, int n_in,
                              void* d_out, int out_size) {
    const int* node_types = (const int*)d_in[0];
    const int* edge_idx = (const int*)d_in[1];
    const float* node_emb = (const float*)d_in[2];
    const float* Wq = (const float*)d_in[3];
    const float* Wk = (const float*)d_in[4];
    const float* Wv = (const float*)d_in[5];
    const float* Wo = (const float*)d_in[6];
    const float* bo = (const float*)d_in[7];
    const float* eb = (const float*)d_in[8];
    const float* W1 = (const float*)d_in[9];
    const float* b1 = (const float*)d_in[10];
    const float* W2 = (const float*)d_in[11];
    const float* b2 = (const float*)d_in[12];
    const float* ln1g = (const float*)d_in[13];
    const float* ln1b = (const float*)d_in[14];
    const float* ln2g = (const float*)d_in[15];
    const float* ln2b = (const float*)d_in[16];
    const float* Wr = (const float*)d_in[17];
    const float* brr = (const float*)d_in[18];
    float* out = (float*)d_out;

    float *x, *part, *pool;
    unsigned char* e8;
    bf16 *xh, *xl, *qh, *ql, *kh, *kl, *vh, *vl, *atth, *attl, *t1h, *t1l;
    bf16 *wqh, *wql, *wkh, *wkl, *wvh, *wvl, *woh, *wol, *w1h, *w1l, *w2h, *w2l;
    cudaGetSymbolAddress((void**)&x, g_x);
    cudaGetSymbolAddress((void**)&part, g_part);
    cudaGetSymbolAddress((void**)&pool, g_pool);
    cudaGetSymbolAddress((void**)&e8, g_e8);
    cudaGetSymbolAddress((void**)&xh, g_xh);
    cudaGetSymbolAddress((void**)&xl, g_xl);
    cudaGetSymbolAddress((void**)&qh, g_qh);
    cudaGetSymbolAddress((void**)&ql, g_ql);
    cudaGetSymbolAddress((void**)&kh, g_kh);
    cudaGetSymbolAddress((void**)&kl, g_kl);
    cudaGetSymbolAddress((void**)&vh, g_vh);
    cudaGetSymbolAddress((void**)&vl, g_vl);
    cudaGetSymbolAddress((void**)&atth, g_atth);
    cudaGetSymbolAddress((void**)&attl, g_attl);
    cudaGetSymbolAddress((void**)&t1h, g_t1h);
    cudaGetSymbolAddress((void**)&t1l, g_t1l);
    cudaGetSymbolAddress((void**)&wqh, g_wqh);
    cudaGetSymbolAddress((void**)&wql, g_wql);
    cudaGetSymbolAddress((void**)&wkh, g_wkh);
    cudaGetSymbolAddress((void**)&wkl, g_wkl);
    cudaGetSymbolAddress((void**)&wvh, g_wvh);
    cudaGetSymbolAddress((void**)&wvl, g_wvl);
    cudaGetSymbolAddress((void**)&woh, g_woh);
    cudaGetSymbolAddress((void**)&wol, g_wol);
    cudaGetSymbolAddress((void**)&w1h, g_w1h);
    cudaGetSymbolAddress((void**)&w1l, g_w1l);
    cudaGetSymbolAddress((void**)&w2h, g_w2h);
    cudaGetSymbolAddress((void**)&w2l, g_w2l);

    embed_kernel<<<Nn, Dd>>>(node_types, node_emb, x, xh, xl);
    cvt_e8_kernel<<<(Nn * Nn / 4) / 256, 256>>>(edge_idx, e8);

    wsplit_kernel<<<dim3(8, 8, Ll), dim3(32, 8)>>>(Wq, wqh, wql, Dd, Dd);
    wsplit_kernel<<<dim3(8, 8, Ll), dim3(32, 8)>>>(Wk, wkh, wkl, Dd, Dd);
    wsplit_kernel<<<dim3(8, 8, Ll), dim3(32, 8)>>>(Wv, wvh, wvl, Dd, Dd);
    wsplit_kernel<<<dim3(8, 8, Ll), dim3(32, 8)>>>(Wo, woh, wol, Dd, Dd);
    wsplit_kernel<<<dim3(32, 8, Ll), dim3(32, 8)>>>(W1, w1h, w1l, Dd, DFFf);
    wsplit_kernel<<<dim3(8, 32, Ll), dim3(32, 8)>>>(W2, w2h, w2l, DFFf, Dd);

    for (int l = 0; l < Ll; l++) {
        size_t wo256 = (size_t)l * Dd * Dd;
        size_t woff1 = (size_t)l * Dd * DFFf;
        hmma_qkv_kernel<<<dim3(4, 16, 3), 256>>>(
            xh, xl, wqh + wo256, wql + wo256, wkh + wo256, wkl + wo256, wvh + wo256,
            wvl + wo256, qh, ql, kh, kl, vh, vl);

        attn_hmma_kernel<<<dim3(Nn / 64, Hh), 128>>>(qh, ql, kh, kl, vh, vl, e8,
                                                     eb + l * NEDGEe * Hh, atth, attl);

        hmma_gemm_kernel<0, 2, 0><<<dim3(4, 16, 2), 256>>>(
            atth, attl, woh + wo256, wol + wo256, nullptr, part, nullptr, nullptr, Dd, Dd);
        addln_red_kernel<2><<<Nn, Dd>>>(x, part, bo + l * Dd, ln1g + l * Dd, ln1b + l * Dd, xh,
                                        xl);

        hmma_gemm_kernel<1, 1, 1><<<dim3(16, 16, 1), 256>>>(
            xh, xl, w1h + woff1, w1l + woff1, b1 + l * DFFf, nullptr, t1h, t1l, Dd, DFFf);

        hmma_gemm_kernel<0, 2, 0><<<dim3(4, 16, 2), 256>>>(
            t1h, t1l, w2h + woff1, w2l + woff1, nullptr, part, nullptr, nullptr, DFFf, Dd);
        addln_red_kernel<2><<<Nn, Dd>>>(x, part, b2 + l * Dd, ln2g + l * Dd, ln2b + l * Dd, xh,
                                        xl);
    }

    pool_kernel<<<Dd / 32, dim3(32, 8)>>>(x, pool);
    head_kernel<<<1, Dd>>>(pool, Wr, brr, out);
}

// round 12
// speedup vs baseline: 2.0289x; 1.0836x over previous
#include <cuda_runtime.h>
#include <cuda_bf16.h>
#include <stdint.h>
#include <math.h>

#define Nn 2048
#define Dd 256
#define Hh 8
#define DKk 32
#define Ll 4
#define DFFf 1024
#define NEDGEe 5

typedef __nv_bfloat16 bf16;

// ---------------- portable MMA helpers (validated R8-R11) ----------------
__device__ __forceinline__ uint32_t smem_u32(const void* p) {
    uint32_t a;
    asm("{ .reg .u64 t; cvta.to.shared.u64 t, %1; cvt.u32.u64 %0, t; }" : "=r"(a) : "l"(p));
    return a;
}
__device__ __forceinline__ void ldsm4(uint32_t& r0, uint32_t& r1, uint32_t& r2, uint32_t& r3,
                                      uint32_t addr) {
    asm volatile("ldmatrix.sync.aligned.m8n8.x4.shared.b16 {%0,%1,%2,%3}, [%4];"
                 : "=r"(r0), "=r"(r1), "=r"(r2), "=r"(r3)
                 : "r"(addr));
}
__device__ __forceinline__ void ldsm4t(uint32_t& r0, uint32_t& r1, uint32_t& r2, uint32_t& r3,
                                       uint32_t addr) {
    asm volatile("ldmatrix.sync.aligned.m8n8.x4.trans.shared.b16 {%0,%1,%2,%3}, [%4];"
                 : "=r"(r0), "=r"(r1), "=r"(r2), "=r"(r3)
                 : "r"(addr));
}
__device__ __forceinline__ void mma_bf16(float* d, const uint32_t* a, const uint32_t* b) {
    asm volatile(
        "mma.sync.aligned.m16n8k16.row.col.f32.bf16.bf16.f32 "
        "{%0,%1,%2,%3}, {%4,%5,%6,%7}, {%8,%9}, {%0,%1,%2,%3};"
        : "+f"(d[0]), "+f"(d[1]), "+f"(d[2]), "+f"(d[3])
        : "r"(a[0]), "r"(a[1]), "r"(a[2]), "r"(a[3]), "r"(b[0]), "r"(b[1]));
}
__device__ __forceinline__ uint32_t pack2bf(float a, float b) {
    uint32_t r;
    asm("cvt.rn.bf16x2.f32 %0, %1, %2;" : "=r"(r) : "f"(b), "f"(a));
    return r;
}
__device__ __forceinline__ float ex2f(float x) {
    float y;
    asm("ex2.approx.f32 %0, %1;" : "=f"(y) : "f"(x));
    return y;
}
__device__ __forceinline__ void cpa16(uint32_t dst, const void* src) {
    asm volatile("cp.async.cg.shared.global [%0], [%1], 16;" :: "r"(dst), "l"(src));
}
#define CP_COMMIT() asm volatile("cp.async.commit_group;" ::: "memory")
#define CP_WAIT(n) asm volatile("cp.async.wait_group %0;" :: "n"(n) : "memory")
#define GBAR(id) asm volatile("bar.sync %0, %1;" :: "r"(id), "r"(128) : "memory")

// ---------------- scratch ----------------
__device__ float g_x[Nn * Dd];
__device__ float g_part[2 * Nn * Dd];
__device__ unsigned char g_e8[Nn * Nn];
__device__ float g_pool[2 * Dd];
__device__ bf16 g_xh[Nn * Dd], g_xl[Nn * Dd];
__device__ bf16 g_qh[Nn * Dd], g_ql[Nn * Dd];
__device__ bf16 g_kh[Nn * Dd], g_kl[Nn * Dd];
__device__ bf16 g_vh[Nn * Dd], g_vl[Nn * Dd];
__device__ bf16 g_atth[Nn * Dd], g_attl[Nn * Dd];
__device__ bf16 g_t1h[Nn * DFFf], g_t1l[Nn * DFFf];
__device__ bf16 g_wqh[Ll * Dd * Dd], g_wql[Ll * Dd * Dd];
__device__ bf16 g_wkh[Ll * Dd * Dd], g_wkl[Ll * Dd * Dd];
__device__ bf16 g_wvh[Ll * Dd * Dd], g_wvl[Ll * Dd * Dd];
__device__ bf16 g_woh[Ll * Dd * Dd], g_wol[Ll * Dd * Dd];
__device__ bf16 g_w1h[Ll * Dd * DFFf], g_w1l[Ll * Dd * DFFf];
__device__ bf16 g_w2h[Ll * DFFf * Dd], g_w2l[Ll * DFFf * Dd];

// ---------------- embedding gather (+split) ----------------
__global__ void embed_kernel(const int* __restrict__ nt, const float* __restrict__ emb,
                             float* __restrict__ x, bf16* __restrict__ xh, bf16* __restrict__ xl) {
    int i = blockIdx.x;
    int d = threadIdx.x;
    float v = emb[nt[i] * Dd + d];
    x[i * Dd + d] = v;
    bf16 h = __float2bfloat16(v);
    xh[i * Dd + d] = h;
    xl[i * Dd + d] = __float2bfloat16(v - __bfloat162float(h));
}

__global__ void cvt_e8_kernel(const int* __restrict__ e, unsigned char* __restrict__ o) {
    int i = blockIdx.x * blockDim.x + threadIdx.x;
    int4 v = ((const int4*)e)[i];
    uchar4 u;
    u.x = (unsigned char)v.x; u.y = (unsigned char)v.y;
    u.z = (unsigned char)v.z; u.w = (unsigned char)v.w;
    ((uchar4*)o)[i] = u;
}

// ---------------- weight transpose + split ----------------
__global__ void wsplit_kernel(const float* __restrict__ W, bf16* __restrict__ Th,
                              bf16* __restrict__ Tl, int Kd, int Nc) {
    __shared__ float sh[32][33], slo[32][33];
    const float* Wl = W + (size_t)blockIdx.z * Kd * Nc;
    bf16* Thl = Th + (size_t)blockIdx.z * Kd * Nc;
    bf16* Tll = Tl + (size_t)blockIdx.z * Kd * Nc;
    int n0 = blockIdx.x << 5, k0 = blockIdx.y << 5;
    int tx = threadIdx.x, ty = threadIdx.y;
#pragma unroll
    for (int r = 0; r < 4; r++) {
        int kk = ty + (r << 3);
        float v = Wl[(size_t)(k0 + kk) * Nc + n0 + tx];
        float h = __bfloat162float(__float2bfloat16(v));
        sh[kk][tx] = h;
        slo[kk][tx] = v - h;
    }
    __syncthreads();
#pragma unroll
    for (int r = 0; r < 4; r++) {
        int nn = ty + (r << 3);
        Thl[(size_t)(n0 + nn) * Kd + k0 + tx] = __float2bfloat16(sh[tx][nn]);
        Tll[(size_t)(n0 + nn) * Kd + k0 + tx] = __float2bfloat16(slo[tx][nn]);
    }
}

// ---------------- split-bf16 HMMA GEMM with register prefetch (R11) ----------------
template <int ACT, int OSPLIT>
__device__ __forceinline__ void hmma_gemm_body(
    const bf16* __restrict__ Ah, const bf16* __restrict__ Al,
    const bf16* __restrict__ Bh, const bf16* __restrict__ Bl,
    const float* __restrict__ bias, float* __restrict__ Cf,
    bf16* __restrict__ Ch, bf16* __restrict__ Cl,
    int Kd, int kbeg, int kslice, int Nc) {
    __shared__ bf16 sAh[128][40], sAl[128][40], sBh[64][40], sBl[64][40];
    const int tid = threadIdx.x;
    const int wid = tid >> 5, lane = tid & 31;
    const int i0 = blockIdx.y << 7, j0 = blockIdx.x << 6;
    const int mw = (wid & 3) << 5;
    const int nw = (wid >> 2) << 5;

    float acc[2][4][4];
#pragma unroll
    for (int a = 0; a < 2; a++)
#pragma unroll
        for (int b = 0; b < 4; b++)
#pragma unroll
            for (int cc = 0; cc < 4; cc++) acc[a][b][cc] = 0.f;

    const int a_r = lane & 15;
    const int a_k = (lane >> 4) << 3;
    const int b_n = (lane & 7) + ((lane & 16) >> 1);
    const int b_k = lane & 8;

    const uint32_t uAh = smem_u32(&sAh[0][0]);
    const uint32_t uAl = smem_u32(&sAl[0][0]);
    const uint32_t uBh = smem_u32(&sBh[0][0]);
    const uint32_t uBl = smem_u32(&sBl[0][0]);

    const int r = tid >> 1, hf = (tid & 1) << 4;
    const int tb = tid & 127;
    const int rb = tb >> 1, hb = (tb & 1) << 4;
    const bf16* Bsel = (tid < 128) ? Bh : Bl;

    uint4 rA0, rA1, rA2, rA3, rB0, rB1;
    {
        const bf16* pAh = Ah + (size_t)(i0 + r) * Kd + kbeg + hf;
        const bf16* pAl = Al + (size_t)(i0 + r) * Kd + kbeg + hf;
        rA0 = *(const uint4*)pAh;
        rA1 = *(const uint4*)(pAh + 8);
        rA2 = *(const uint4*)pAl;
        rA3 = *(const uint4*)(pAl + 8);
        const bf16* pB = Bsel + (size_t)(j0 + rb) * Kd + kbeg + hb;
        rB0 = *(const uint4*)pB;
        rB1 = *(const uint4*)(pB + 8);
    }

    const int nch = kslice >> 5;
    for (int c = 0; c < nch; c++) {
        *(uint4*)&sAh[r][hf] = rA0;
        *(uint4*)&sAh[r][hf + 8] = rA1;
        *(uint4*)&sAl[r][hf] = rA2;
        *(uint4*)&sAl[r][hf + 8] = rA3;
        if (tid < 128) {
            *(uint4*)&sBh[rb][hb] = rB0;
            *(uint4*)&sBh[rb][hb + 8] = rB1;
        } else {
            *(uint4*)&sBl[rb][hb] = rB0;
            *(uint4*)&sBl[rb][hb + 8] = rB1;
        }
        __syncthreads();

        if (c + 1 < nch) {
            int kt = kbeg + ((c + 1) << 5);
            const bf16* pAh = Ah + (size_t)(i0 + r) * Kd + kt + hf;
            const bf16* pAl = Al + (size_t)(i0 + r) * Kd + kt + hf;
            rA0 = *(const uint4*)pAh;
            rA1 = *(const uint4*)(pAh + 8);
            rA2 = *(const uint4*)pAl;
            rA3 = *(const uint4*)(pAl + 8);
            const bf16* pB = Bsel + (size_t)(j0 + rb) * Kd + kt + hb;
            rB0 = *(const uint4*)pB;
            rB1 = *(const uint4*)(pB + 8);
        }

#pragma unroll
        for (int ks = 0; ks < 2; ks++) {
            const int kk = ks << 4;
            uint32_t ah[2][4], al[2][4], bhf[2][4], blf[2][4];
#pragma unroll
            for (int mf = 0; mf < 2; mf++) {
                uint32_t off = (uint32_t)(((mw + (mf << 4) + a_r) * 40 + kk + a_k) << 1);
                ldsm4(ah[mf][0], ah[mf][1], ah[mf][2], ah[mf][3], uAh + off);
                ldsm4(al[mf][0], al[mf][1], al[mf][2], al[mf][3], uAl + off);
            }
#pragma unroll
            for (int g = 0; g < 2; g++) {
                uint32_t off = (uint32_t)(((nw + (g << 4) + b_n) * 40 + kk + b_k) << 1);
                ldsm4(bhf[g][0], bhf[g][1], bhf[g][2], bhf[g][3], uBh + off);
                ldsm4(blf[g][0], blf[g][1], blf[g][2], blf[g][3], uBl + off);
            }
#pragma unroll
            for (int mf = 0; mf < 2; mf++)
#pragma unroll
                for (int nf = 0; nf < 4; nf++) {
                    const uint32_t* ph = &bhf[nf >> 1][(nf & 1) << 1];
                    const uint32_t* pl = &blf[nf >> 1][(nf & 1) << 1];
                    mma_bf16(acc[mf][nf], ah[mf], ph);
                    mma_bf16(acc[mf][nf], ah[mf], pl);
                    mma_bf16(acc[mf][nf], al[mf], ph);
                }
        }
        if (c + 1 < nch) __syncthreads();
    }

    const int lr = lane >> 2, lc = (lane & 3) << 1;
#pragma unroll
    for (int mf = 0; mf < 2; mf++)
#pragma unroll
        for (int rp = 0; rp < 2; rp++) {
            int row = i0 + mw + (mf << 4) + lr + (rp << 3);
#pragma unroll
            for (int nf = 0; nf < 4; nf++) {
                float v0 = acc[mf][nf][(rp << 1) + 0];
                float v1 = acc[mf][nf][(rp << 1) + 1];
                int col = j0 + nw + (nf << 3) + lc;
                if (OSPLIT == 0) {
                    if (bias) {
                        v0 += bias[col];
                        v1 += bias[col + 1];
                    }
                    *(float2*)&Cf[(size_t)row * Nc + col] = make_float2(v0, v1);
                } else {
                    if (OSPLIT == 1) {
                        v0 += bias[col];
                        v1 += bias[col + 1];
                        if (ACT == 1) {
                            v0 = 0.5f * v0 * (1.0f + erff(v0 * 0.70710678118654752f));
                            v1 = 0.5f * v1 * (1.0f + erff(v1 * 0.70710678118654752f));
                        }
                    }
                    bf16 h0 = __float2bfloat16(v0), h1 = __float2bfloat16(v1);
                    Ch[(size_t)row * Nc + col] = h0;
                    Ch[(size_t)row * Nc + col + 1] = h1;
                    Cl[(size_t)row * Nc + col] = __float2bfloat16(v0 - __bfloat162float(h0));
                    Cl[(size_t)row * Nc + col + 1] = __float2bfloat16(v1 - __bfloat162float(h1));
                }
            }
        }
}

template <int ACT, int SPLIT, int OSPLIT>
__global__ void __launch_bounds__(256) hmma_gemm_kernel(
    const bf16* __restrict__ Ah, const bf16* __restrict__ Al,
    const bf16* __restrict__ Bh, const bf16* __restrict__ Bl,
    const float* __restrict__ bias, float* __restrict__ Cf,
    bf16* __restrict__ Ch, bf16* __restrict__ Cl, int Kd, int Nc) {
    int kslice = Kd / SPLIT;
    int kbeg = blockIdx.z * kslice;
    float* Cz = (SPLIT > 1) ? Cf + (size_t)blockIdx.z * Nn * Nc : Cf;
    hmma_gemm_body<ACT, OSPLIT>(Ah, Al, Bh, Bl, SPLIT > 1 ? nullptr : bias, Cz, Ch, Cl,
                                Kd, kbeg, kslice, Nc);
}

__global__ void __launch_bounds__(256) hmma_qkv_kernel(
    const bf16* __restrict__ Ah, const bf16* __restrict__ Al,
    const bf16* __restrict__ Bh0, const bf16* __restrict__ Bl0,
    const bf16* __restrict__ Bh1, const bf16* __restrict__ Bl1,
    const bf16* __restrict__ Bh2, const bf16* __restrict__ Bl2,
    bf16* __restrict__ qh, bf16* __restrict__ ql, bf16* __restrict__ kh,
    bf16* __restrict__ kl, bf16* __restrict__ vh, bf16* __restrict__ vl) {
    int z = blockIdx.z;
    const bf16* Bh = (z == 0) ? Bh0 : (z == 1) ? Bh1 : Bh2;
    const bf16* Bl = (z == 0) ? Bl0 : (z == 1) ? Bl1 : Bl2;
    bf16* Ch = (z == 0) ? qh : (z == 1) ? kh : vh;
    bf16* Cl = (z == 0) ? ql : (z == 1) ? kl : vl;
    hmma_gemm_body<0, 2>(Ah, Al, Bh, Bl, nullptr, nullptr, Ch, Cl, Dd, 0, Dd, Dd);
}

// ---------------- HMMA flash attention v3: intra-block KV split ----------------
// 256 thr = 2 warp-groups. Group g handles j-tiles g, g+2, g+4, ... with private
// K (double-buffered) + V smem; groups sync on named barriers; split-softmax merge.
// Dynamic smem layout (bf16 elements):
//   QH 0, QL 2560, KH(g,b) 5120+(g*2+b)*2560, KL(g,b) 15360+(g*2+b)*2560,
//   VH(g) 25600+g*2560, VL(g) 30720+g*2560. Total 35840 el = 71680 B.
#define ATTN_SMEM 71680
__global__ void __launch_bounds__(256) attn_hmma_kernel(
    const bf16* __restrict__ Qh, const bf16* __restrict__ Ql,
    const bf16* __restrict__ Kh, const bf16* __restrict__ Kl,
    const bf16* __restrict__ Vh, const bf16* __restrict__ Vl,
    const unsigned char* __restrict__ E8, const float* __restrict__ ebl,
    bf16* __restrict__ Oh, bf16* __restrict__ Ol) {
    extern __shared__ bf16 dsm[];
    __shared__ float s_eb[8];

    const int h = blockIdx.y;
    const int i0 = blockIdx.x << 6;
    const int tid = threadIdx.x;
    const int wid = tid >> 5, lane = tid & 31;
    const int gid = wid >> 2;        // warp-group 0/1
    const int mw = (wid & 3) << 4;   // q-row offset of this warp (same rows both groups)
    const int gt = tid & 127;        // thread id within group

    if (tid < NEDGEe) s_eb[tid] = ebl[tid * Hh + h] * 1.4426950408889634f;

    const int a_r = lane & 15, a_k = (lane >> 4) << 3;
    const int b_n = (lane & 7) + ((lane & 16) >> 1), b_k = lane & 8;
    const int lr = lane >> 2, lc = (lane & 3) << 1;

    const uint32_t uQh = smem_u32(dsm);
    const uint32_t uQl = smem_u32(dsm + 2560);
    uint32_t uKh[2], uKl[2];
    uKh[0] = smem_u32(dsm + 5120 + (gid * 2) * 2560);
    uKh[1] = smem_u32(dsm + 5120 + (gid * 2 + 1) * 2560);
    uKl[0] = smem_u32(dsm + 15360 + (gid * 2) * 2560);
    uKl[1] = smem_u32(dsm + 15360 + (gid * 2 + 1) * 2560);
    const uint32_t uVh = smem_u32(dsm + 25600 + gid * 2560);
    const uint32_t uVl = smem_u32(dsm + 30720 + gid * 2560);

    const int qr = gt >> 1, qh4 = (gt & 1) << 4;
    const uint32_t soff0 = (uint32_t)((qr * 40 + qh4) << 1);
    const size_t ghead = (size_t)h * DKk + qh4;

    // group-specific K tile-0 prefetch; group 0 also loads Q
    {
        const bf16* pk = Kh + (size_t)(gid * 64 + qr) * Dd + ghead;
        cpa16(uKh[0] + soff0, pk);
        cpa16(uKh[0] + soff0 + 16, pk + 8);
        const bf16* pk2 = Kl + (size_t)(gid * 64 + qr) * Dd + ghead;
        cpa16(uKl[0] + soff0, pk2);
        cpa16(uKl[0] + soff0 + 16, pk2 + 8);
    }
    CP_COMMIT();
    if (gid == 0) {
        const bf16* p = Qh + (size_t)(i0 + qr) * Dd + ghead;
        *(uint4*)(dsm + qr * 40 + qh4) = *(const uint4*)p;
        *(uint4*)(dsm + qr * 40 + qh4 + 8) = *(const uint4*)(p + 8);
        const bf16* p2 = Ql + (size_t)(i0 + qr) * Dd + ghead;
        *(uint4*)(dsm + 2560 + qr * 40 + qh4) = *(const uint4*)p2;
        *(uint4*)(dsm + 2560 + qr * 40 + qh4 + 8) = *(const uint4*)(p2 + 8);
    }
    __syncthreads();  // Q visible to both groups

    float of[4][4];
#pragma unroll
    for (int a = 0; a < 4; a++)
#pragma unroll
        for (int b = 0; b < 4; b++) of[a][b] = 0.f;
    float m0 = -1e30f, m1 = -1e30f, l0 = 0.f, l1 = 0.f;
    const float scale2 = 0.17677669529663687f * 1.4426950408889634f;
    const size_t r0e = (size_t)(i0 + mw + lr) * Nn;
    const size_t r1e = (size_t)(i0 + mw + lr + 8) * Nn;

    for (int t = 0; t < 16; t++) {
        const int jt = ((t << 1) + gid) << 6;
        const int buf = t & 1;
        CP_WAIT(0);
        GBAR(gid + 1);

        // issue V(t)
        {
            const bf16* pv = Vh + (size_t)(jt + qr) * Dd + ghead;
            cpa16(uVh + soff0, pv);
            cpa16(uVh + soff0 + 16, pv + 8);
            const bf16* pv2 = Vl + (size_t)(jt + qr) * Dd + ghead;
            cpa16(uVl + soff0, pv2);
            cpa16(uVl + soff0 + 16, pv2 + 8);
        }
        CP_COMMIT();
        // issue K(t+1) for this group (tile jt+128)
        if (t + 1 < 16) {
            const bf16* pk = Kh + (size_t)(jt + 128 + qr) * Dd + ghead;
            cpa16(uKh[buf ^ 1] + soff0, pk);
            cpa16(uKh[buf ^ 1] + soff0 + 16, pk + 8);
            const bf16* pk2 = Kl + (size_t)(jt + 128 + qr) * Dd + ghead;
            cpa16(uKl[buf ^ 1] + soff0, pk2);
            cpa16(uKl[buf ^ 1] + soff0 + 16, pk2 + 8);
        }
        CP_COMMIT();

        unsigned short eu0[8], eu1[8];
#pragma unroll
        for (int nf = 0; nf < 8; nf++) {
            eu0[nf] = *(const unsigned short*)&E8[r0e + jt + (nf << 3) + lc];
            eu1[nf] = *(const unsigned short*)&E8[r1e + jt + (nf << 3) + lc];
        }

        // ---- S = Q K^T (3-term split) ----
        float sf[8][4];
#pragma unroll
        for (int nf = 0; nf < 8; nf++)
#pragma unroll
            for (int cc = 0; cc < 4; cc++) sf[nf][cc] = 0.f;
#pragma unroll
        for (int ks = 0; ks < 2; ks++) {
            const int kk = ks << 4;
            uint32_t aqh[4], aql[4];
            uint32_t offa = (uint32_t)(((mw + a_r) * 40 + kk + a_k) << 1);
            ldsm4(aqh[0], aqh[1], aqh[2], aqh[3], uQh + offa);
            ldsm4(aql[0], aql[1], aql[2], aql[3], uQl + offa);
#pragma unroll
            for (int g = 0; g < 4; g++) {
                uint32_t bkh[4], bkl[4];
                uint32_t offb = (uint32_t)((((g << 4) + b_n) * 40 + kk + b_k) << 1);
                ldsm4(bkh[0], bkh[1], bkh[2], bkh[3], uKh[buf] + offb);
                ldsm4(bkl[0], bkl[1], bkl[2], bkl[3], uKl[buf] + offb);
#pragma unroll
                for (int sub = 0; sub < 2; sub++) {
                    int nf = (g << 1) + sub;
                    const uint32_t* ph = &bkh[sub << 1];
                    const uint32_t* pl = &bkl[sub << 1];
                    mma_bf16(sf[nf], aqh, ph);
                    mma_bf16(sf[nf], aqh, pl);
                    mma_bf16(sf[nf], aql, ph);
                }
            }
        }

        // ---- scale + edge bias + row max (log2 domain) ----
        float mx0 = -1e30f, mx1 = -1e30f;
#pragma unroll
        for (int nf = 0; nf < 8; nf++) {
            sf[nf][0] = fmaf(sf[nf][0], scale2, s_eb[eu0[nf] & 0xffu]);
            sf[nf][1] = fmaf(sf[nf][1], scale2, s_eb[eu0[nf] >> 8]);
            sf[nf][2] = fmaf(sf[nf][2], scale2, s_eb[eu1[nf] & 0xffu]);
            sf[nf][3] = fmaf(sf[nf][3], scale2, s_eb[eu1[nf] >> 8]);
            mx0 = fmaxf(mx0, fmaxf(sf[nf][0], sf[nf][1]));
            mx1 = fmaxf(mx1, fmaxf(sf[nf][2], sf[nf][3]));
        }
        mx0 = fmaxf(mx0, __shfl_xor_sync(0xffffffffu, mx0, 1));
        mx0 = fmaxf(mx0, __shfl_xor_sync(0xffffffffu, mx0, 2));
        mx1 = fmaxf(mx1, __shfl_xor_sync(0xffffffffu, mx1, 1));
        mx1 = fmaxf(mx1, __shfl_xor_sync(0xffffffffu, mx1, 2));
        float mn0 = fmaxf(m0, mx0), mn1 = fmaxf(m1, mx1);
        float al0 = ex2f(m0 - mn0), al1 = ex2f(m1 - mn1);
        m0 = mn0;
        m1 = mn1;
#pragma unroll
        for (int nf = 0; nf < 4; nf++) {
            of[nf][0] *= al0;
            of[nf][1] *= al0;
            of[nf][2] *= al1;
            of[nf][3] *= al1;
        }

        // ---- P = 2^(S-m), hi-only bf16 A-fragments ----
        float ps0 = 0.f, ps1 = 0.f;
        uint32_t aph[4][4];
#pragma unroll
        for (int nf = 0; nf < 8; nf++) {
            float p0 = ex2f(sf[nf][0] - mn0);
            float p1 = ex2f(sf[nf][1] - mn0);
            float p2 = ex2f(sf[nf][2] - mn1);
            float p3 = ex2f(sf[nf][3] - mn1);
            ps0 += p0 + p1;
            ps1 += p2 + p3;
            int ks = nf >> 1, base = (nf & 1) << 1;
            aph[ks][base + 0] = pack2bf(p0, p1);
            aph[ks][base + 1] = pack2bf(p2, p3);
        }
        ps0 += __shfl_xor_sync(0xffffffffu, ps0, 1);
        ps0 += __shfl_xor_sync(0xffffffffu, ps0, 2);
        ps1 += __shfl_xor_sync(0xffffffffu, ps1, 1);
        ps1 += __shfl_xor_sync(0xffffffffu, ps1, 2);
        l0 = l0 * al0 + ps0;
        l1 = l1 * al1 + ps1;

        // ---- wait V(t), then O += P V (2-term) ----
        CP_WAIT(1);
        GBAR(gid + 1);
#pragma unroll
        for (int ks = 0; ks < 4; ks++) {
            const int kk = ks << 4;
#pragma unroll
            for (int dg = 0; dg < 2; dg++) {
                uint32_t bvh[4], bvl[4];
                uint32_t offv = (uint32_t)(((kk + a_r) * 40 + (dg << 4) + a_k) << 1);
                ldsm4t(bvh[0], bvh[1], bvh[2], bvh[3], uVh + offv);
                ldsm4t(bvl[0], bvl[1], bvl[2], bvl[3], uVl + offv);
#pragma unroll
                for (int sub = 0; sub < 2; sub++) {
                    int nf = (dg << 1) + sub;
                    mma_bf16(of[nf], aph[ks], &bvh[sub << 1]);
                    mma_bf16(of[nf], aph[ks], &bvl[sub << 1]);
                }
            }
        }
    }

    // ---- split-softmax merge across the two groups ----
    CP_WAIT(0);
    __syncthreads();  // all smem traffic drained; safe to reuse dsm
    float* mg = (float*)dsm;          // [128][2]
    float* lg = mg + 256;             // [128][2]
    float* og = lg + 256;             // [128][16]
    if (gid == 1) {
        mg[gt * 2] = m0;
        mg[gt * 2 + 1] = m1;
        lg[gt * 2] = l0;
        lg[gt * 2 + 1] = l1;
#pragma unroll
        for (int nf = 0; nf < 4; nf++)
#pragma unroll
            for (int c = 0; c < 4; c++) og[gt * 16 + nf * 4 + c] = of[nf][c];
    }
    __syncthreads();
    if (gid == 0) {
        float mb0 = mg[gt * 2], mb1 = mg[gt * 2 + 1];
        float lb0 = lg[gt * 2], lb1 = lg[gt * 2 + 1];
        float mn0 = fmaxf(m0, mb0), mn1 = fmaxf(m1, mb1);
        float a0 = ex2f(m0 - mn0), bb0 = ex2f(mb0 - mn0);
        float a1 = ex2f(m1 - mn1), bb1 = ex2f(mb1 - mn1);
        float inv0 = 1.0f / (l0 * a0 + lb0 * bb0);
        float inv1 = 1.0f / (l1 * a1 + lb1 * bb1);
        int row0 = i0 + mw + lr, row1 = row0 + 8;
#pragma unroll
        for (int nf = 0; nf < 4; nf++) {
            int col = h * DKk + (nf << 3) + lc;
            float v0 = (of[nf][0] * a0 + og[gt * 16 + nf * 4 + 0] * bb0) * inv0;
            float v1 = (of[nf][1] * a0 + og[gt * 16 + nf * 4 + 1] * bb0) * inv0;
            float v2 = (of[nf][2] * a1 + og[gt * 16 + nf * 4 + 2] * bb1) * inv1;
            float v3 = (of[nf][3] * a1 + og[gt * 16 + nf * 4 + 3] * bb1) * inv1;
            float h0 = __bfloat162float(__float2bfloat16(v0));
            float h1 = __bfloat162float(__float2bfloat16(v1));
            float h2 = __bfloat162float(__float2bfloat16(v2));
            float h3 = __bfloat162float(__float2bfloat16(v3));
            *(uint32_t*)&Oh[(size_t)row0 * Dd + col] = pack2bf(h0, h1);
            *(uint32_t*)&Oh[(size_t)row1 * Dd + col] = pack2bf(h2, h3);
            *(uint32_t*)&Ol[(size_t)row0 * Dd + col] = pack2bf(v0 - h0, v1 - h1);
            *(uint32_t*)&Ol[(size_t)row1 * Dd + col] = pack2bf(v2 - h2, v3 - h3);
        }
    }
}

// ---------------- reduce + bias + residual + LayerNorm (warp shuffle) ----------------
template <int S>
__global__ void addln_red_kernel(float* __restrict__ x, const float* __restrict__ part,
                                 const float* __restrict__ bias, const float* __restrict__ g,
                                 const float* __restrict__ b, bf16* __restrict__ xh,
                                 bf16* __restrict__ xl) {
    int i = blockIdx.x, d = threadIdx.x;
    int lane = d & 31, w = d >> 5;
    __shared__ float ws[8];
    float v = x[i * Dd + d] + bias[d];
#pragma unroll
    for (int s = 0; s < S; s++) v += part[(size_t)s * Nn * Dd + (size_t)i * Dd + d];
    float t = v;
#pragma unroll
    for (int off = 16; off > 0; off >>= 1) t += __shfl_xor_sync(0xffffffffu, t, off);
    if (lane == 0) ws[w] = t;
    __syncthreads();
    float mean = (ws[0] + ws[1] + ws[2] + ws[3] + ws[4] + ws[5] + ws[6] + ws[7]) * (1.0f / Dd);
    float dv = v - mean;
    t = dv * dv;
#pragma unroll
    for (int off = 16; off > 0; off >>= 1) t += __shfl_xor_sync(0xffffffffu, t, off);
    __syncthreads();
    if (lane == 0) ws[w] = t;
    __syncthreads();
    float var = (ws[0] + ws[1] + ws[2] + ws[3] + ws[4] + ws[5] + ws[6] + ws[7]) * (1.0f / Dd);
    float outv = dv * rsqrtf(var + 1e-5f) * g[d] + b[d];
    x[i * Dd + d] = outv;
    bf16 h = __float2bfloat16(outv);
    xh[i * Dd + d] = h;
    xl[i * Dd + d] = __float2bfloat16(outv - __bfloat162float(h));
}

__global__ void pool_kernel(const float* __restrict__ x, float* __restrict__ p) {
    int j = blockIdx.x * 32 + threadIdx.x;
    int yy = threadIdx.y;
    float s = 0.f, mx = -1e30f;
    for (int i = yy; i < Nn; i += 8) {
        float v = x[(size_t)i * Dd + j];
        s += v;
        mx = fmaxf(mx, v);
    }
    __shared__ float ss[8][33], sm[8][33];
    ss[yy][threadIdx.x] = s;
    sm[yy][threadIdx.x] = mx;
    __syncthreads();
    if (yy == 0) {
        for (int k2 = 1; k2 < 8; k2++) {
            s += ss[k2][threadIdx.x];
            mx = fmaxf(mx, sm[k2][threadIdx.x]);
        }
        p[j] = s * (1.0f / Nn);
        p[Dd + j] = mx;
    }
}

__global__ void head_kernel(const float* __restrict__ pooled, const float* __restrict__ Wr,
                            const float* __restrict__ br, float* __restrict__ out) {
    __shared__ float sp[2 * Dd];
    int d = threadIdx.x;
    sp[d] = pooled[d];
    sp[d + Dd] = pooled[d + Dd];
    __syncthreads();
    float acc = br[d];
#pragma unroll 8
    for (int k2 = 0; k2 < 2 * Dd; k2++) acc = fmaf(sp[k2], Wr[(size_t)k2 * Dd + d], acc);
    out[d] = acc;
}

// ---------------- host launcher ----------------
extern "C" void kernel_launch(void* const* d_in, const int* in_sizes, int n_in,
                              void* d_out, int out_size) {
    const int* node_types = (const int*)d_in[0];
    const int* edge_idx = (const int*)d_in[1];
    const float* node_emb = (const float*)d_in[2];
    const float* Wq = (const float*)d_in[3];
    const float* Wk = (const float*)d_in[4];
    const float* Wv = (const float*)d_in[5];
    const float* Wo = (const float*)d_in[6];
    const float* bo = (const float*)d_in[7];
    const float* eb = (const float*)d_in[8];
    const float* W1 = (const float*)d_in[9];
    const float* b1 = (const float*)d_in[10];
    const float* W2 = (const float*)d_in[11];
    const float* b2 = (const float*)d_in[12];
    const float* ln1g = (const float*)d_in[13];
    const float* ln1b = (const float*)d_in[14];
    const float* ln2g = (const float*)d_in[15];
    const float* ln2b = (const float*)d_in[16];
    const float* Wr = (const float*)d_in[17];
    const float* brr = (const float*)d_in[18];
    float* out = (float*)d_out;

    float *x, *part, *pool;
    unsigned char* e8;
    bf16 *xh, *xl, *qh, *ql, *kh, *kl, *vh, *vl, *atth, *attl, *t1h, *t1l;
    bf16 *wqh, *wql, *wkh, *wkl, *wvh, *wvl, *woh, *wol, *w1h, *w1l, *w2h, *w2l;
    cudaGetSymbolAddress((void**)&x, g_x);
    cudaGetSymbolAddress((void**)&part, g_part);
    cudaGetSymbolAddress((void**)&pool, g_pool);
    cudaGetSymbolAddress((void**)&e8, g_e8);
    cudaGetSymbolAddress((void**)&xh, g_xh);
    cudaGetSymbolAddress((void**)&xl, g_xl);
    cudaGetSymbolAddress((void**)&qh, g_qh);
    cudaGetSymbolAddress((void**)&ql, g_ql);
    cudaGetSymbolAddress((void**)&kh, g_kh);
    cudaGetSymbolAddress((void**)&kl, g_kl);
    cudaGetSymbolAddress((void**)&vh, g_vh);
    cudaGetSymbolAddress((void**)&vl, g_vl);
    cudaGetSymbolAddress((void**)&atth, g_atth);
    cudaGetSymbolAddress((void**)&attl, g_attl);
    cudaGetSymbolAddress((void**)&t1h, g_t1h);
    cudaGetSymbolAddress((void**)&t1l, g_t1l);
    cudaGetSymbolAddress((void**)&wqh, g_wqh);
    cudaGetSymbolAddress((void**)&wql, g_wql);
    cudaGetSymbolAddress((void**)&wkh, g_wkh);
    cudaGetSymbolAddress((void**)&wkl, g_wkl);
    cudaGetSymbolAddress((void**)&wvh, g_wvh);
    cudaGetSymbolAddress((void**)&wvl, g_wvl);
    cudaGetSymbolAddress((void**)&woh, g_woh);
    cudaGetSymbolAddress((void**)&wol, g_wol);
    cudaGetSymbolAddress((void**)&w1h, g_w1h);
    cudaGetSymbolAddress((void**)&w1l, g_w1l);
    cudaGetSymbolAddress((void**)&w2h, g_w2h);
    cudaGetSymbolAddress((void**)&w2l, g_w2l);

    cudaFuncSetAttribute(attn_hmma_kernel, cudaFuncAttributeMaxDynamicSharedMemorySize,
                         ATTN_SMEM);

    embed_kernel<<<Nn, Dd>>>(node_types, node_emb, x, xh, xl);
    cvt_e8_kernel<<<(Nn * Nn / 4) / 256, 256>>>(edge_idx, e8);

    wsplit_kernel<<<dim3(8, 8, Ll), dim3(32, 8)>>>(Wq, wqh, wql, Dd, Dd);
    wsplit_kernel<<<dim3(8, 8, Ll), dim3(32, 8)>>>(Wk, wkh, wkl, Dd, Dd);
    wsplit_kernel<<<dim3(8, 8, Ll), dim3(32, 8)>>>(Wv, wvh, wvl, Dd, Dd);
    wsplit_kernel<<<dim3(8, 8, Ll), dim3(32, 8)>>>(Wo, woh, wol, Dd, Dd);
    wsplit_kernel<<<dim3(32, 8, Ll), dim3(32, 8)>>>(W1, w1h, w1l, Dd, DFFf);
    wsplit_kernel<<<dim3(8, 32, Ll), dim3(32, 8)>>>(W2, w2h, w2l, DFFf, Dd);

    for (int l = 0; l < Ll; l++) {
        size_t wo256 = (size_t)l * Dd * Dd;
        size_t woff1 = (size_t)l * Dd * DFFf;
        hmma_qkv_kernel<<<dim3(4, 16, 3), 256>>>(
            xh, xl, wqh + wo256, wql + wo256, wkh + wo256, wkl + wo256, wvh + wo256,
            wvl + wo256, qh, ql, kh, kl, vh, vl);

        attn_hmma_kernel<<<dim3(Nn / 64, Hh), 256, ATTN_SMEM>>>(
            qh, ql, kh, kl, vh, vl, e8, eb + l * NEDGEe * Hh, atth, attl);

        hmma_gemm_kernel<0, 2, 0><<<dim3(4, 16, 2), 256>>>(
            atth, attl, woh + wo256, wol + wo256, nullptr, part, nullptr, nullptr, Dd, Dd);
        addln_red_kernel<2><<<Nn, Dd>>>(x, part, bo + l * Dd, ln1g + l * Dd, ln1b + l * Dd, xh,
                                        xl);

        hmma_gemm_kernel<1, 1, 1><<<dim3(16, 16, 1), 256>>>(
            xh, xl, w1h + woff1, w1l + woff1, b1 + l * DFFf, nullptr, t1h, t1l, Dd, DFFf);

        hmma_gemm_kernel<0, 2, 0><<<dim3(4, 16, 2), 256>>>(
            t1h, t1l, w2h + woff1, w2l + woff1, nullptr, part, nullptr, nullptr, DFFf, Dd);
        addln_red_kernel<2><<<Nn, Dd>>>(x, part, b2 + l * Dd, ln2g + l * Dd, ln2b + l * Dd, xh,
                                        xl);
    }

    pool_kernel<<<Dd / 32, dim3(32, 8)>>>(x, pool);
    head_kernel<<<1, Dd>>>(pool, Wr, brr, out);
}

// round 13
// speedup vs baseline: 2.1177x; 1.0437x over previous
#include <cuda_runtime.h>
#include <cuda_bf16.h>
#include <stdint.h>
#include <math.h>

#define Nn 2048
#define Dd 256
#define Hh 8
#define DKk 32
#define Ll 4
#define DFFf 1024
#define NEDGEe 5

typedef __nv_bfloat16 bf16;

// ---------------- portable MMA helpers (validated R8-R12) ----------------
__device__ __forceinline__ uint32_t smem_u32(const void* p) {
    uint32_t a;
    asm("{ .reg .u64 t; cvta.to.shared.u64 t, %1; cvt.u32.u64 %0, t; }" : "=r"(a) : "l"(p));
    return a;
}
__device__ __forceinline__ void ldsm4(uint32_t& r0, uint32_t& r1, uint32_t& r2, uint32_t& r3,
                                      uint32_t addr) {
    asm volatile("ldmatrix.sync.aligned.m8n8.x4.shared.b16 {%0,%1,%2,%3}, [%4];"
                 : "=r"(r0), "=r"(r1), "=r"(r2), "=r"(r3)
                 : "r"(addr));
}
__device__ __forceinline__ void ldsm4t(uint32_t& r0, uint32_t& r1, uint32_t& r2, uint32_t& r3,
                                       uint32_t addr) {
    asm volatile("ldmatrix.sync.aligned.m8n8.x4.trans.shared.b16 {%0,%1,%2,%3}, [%4];"
                 : "=r"(r0), "=r"(r1), "=r"(r2), "=r"(r3)
                 : "r"(addr));
}
__device__ __forceinline__ void mma_bf16(float* d, const uint32_t* a, const uint32_t* b) {
    asm volatile(
        "mma.sync.aligned.m16n8k16.row.col.f32.bf16.bf16.f32 "
        "{%0,%1,%2,%3}, {%4,%5,%6,%7}, {%8,%9}, {%0,%1,%2,%3};"
        : "+f"(d[0]), "+f"(d[1]), "+f"(d[2]), "+f"(d[3])
        : "r"(a[0]), "r"(a[1]), "r"(a[2]), "r"(a[3]), "r"(b[0]), "r"(b[1]));
}
__device__ __forceinline__ uint32_t pack2bf(float a, float b) {
    uint32_t r;
    asm("cvt.rn.bf16x2.f32 %0, %1, %2;" : "=r"(r) : "f"(b), "f"(a));
    return r;
}
__device__ __forceinline__ float ex2f(float x) {
    float y;
    asm("ex2.approx.f32 %0, %1;" : "=f"(y) : "f"(x));
    return y;
}
__device__ __forceinline__ void cpa16(uint32_t dst, const void* src) {
    asm volatile("cp.async.cg.shared.global [%0], [%1], 16;" :: "r"(dst), "l"(src));
}
#define CP_COMMIT() asm volatile("cp.async.commit_group;" ::: "memory")
#define CP_WAIT(n) asm volatile("cp.async.wait_group %0;" :: "n"(n) : "memory")
#define GBAR(id) asm volatile("bar.sync %0, %1;" :: "r"(id), "r"(128) : "memory")

// ---------------- scratch ----------------
__device__ float g_x[Nn * Dd];
__device__ float g_part[2 * Nn * Dd];
__device__ unsigned char g_e8[Nn * Nn];
__device__ float g_pool[2 * Dd];
__device__ bf16 g_xh[Nn * Dd], g_xl[Nn * Dd];
__device__ bf16 g_qh[Nn * Dd], g_ql[Nn * Dd];
__device__ bf16 g_kh[Nn * Dd], g_kl[Nn * Dd];
__device__ bf16 g_vh[Nn * Dd], g_vl[Nn * Dd];
__device__ bf16 g_atth[Nn * Dd], g_attl[Nn * Dd];
__device__ bf16 g_t1h[Nn * DFFf], g_t1l[Nn * DFFf];
__device__ bf16 g_wqh[Ll * Dd * Dd], g_wql[Ll * Dd * Dd];
__device__ bf16 g_wkh[Ll * Dd * Dd], g_wkl[Ll * Dd * Dd];
__device__ bf16 g_wvh[Ll * Dd * Dd], g_wvl[Ll * Dd * Dd];
__device__ bf16 g_woh[Ll * Dd * Dd], g_wol[Ll * Dd * Dd];
__device__ bf16 g_w1h[Ll * Dd * DFFf], g_w1l[Ll * Dd * DFFf];
__device__ bf16 g_w2h[Ll * DFFf * Dd], g_w2l[Ll * DFFf * Dd];

// ---------------- embedding gather (+split) ----------------
__global__ void embed_kernel(const int* __restrict__ nt, const float* __restrict__ emb,
                             float* __restrict__ x, bf16* __restrict__ xh, bf16* __restrict__ xl) {
    int i = blockIdx.x;
    int d = threadIdx.x;
    float v = emb[nt[i] * Dd + d];
    x[i * Dd + d] = v;
    bf16 h = __float2bfloat16(v);
    xh[i * Dd + d] = h;
    xl[i * Dd + d] = __float2bfloat16(v - __bfloat162float(h));
}

__global__ void cvt_e8_kernel(const int* __restrict__ e, unsigned char* __restrict__ o) {
    int i = blockIdx.x * blockDim.x + threadIdx.x;
    int4 v = ((const int4*)e)[i];
    uchar4 u;
    u.x = (unsigned char)v.x; u.y = (unsigned char)v.y;
    u.z = (unsigned char)v.z; u.w = (unsigned char)v.w;
    ((uchar4*)o)[i] = u;
}

// ---------------- weight transpose + split ----------------
__device__ __forceinline__ void wsplit_body(const float* __restrict__ Wl, bf16* __restrict__ Thl,
                                            bf16* __restrict__ Tll, int Kd, int Nc) {
    __shared__ float sh[32][33], slo[32][33];
    int n0 = blockIdx.x << 5, k0 = blockIdx.y << 5;
    int tx = threadIdx.x, ty = threadIdx.y;
#pragma unroll
    for (int r = 0; r < 4; r++) {
        int kk = ty + (r << 3);
        float v = Wl[(size_t)(k0 + kk) * Nc + n0 + tx];
        float h = __bfloat162float(__float2bfloat16(v));
        sh[kk][tx] = h;
        slo[kk][tx] = v - h;
    }
    __syncthreads();
#pragma unroll
    for (int r = 0; r < 4; r++) {
        int nn = ty + (r << 3);
        Thl[(size_t)(n0 + nn) * Kd + k0 + tx] = __float2bfloat16(sh[tx][nn]);
        Tll[(size_t)(n0 + nn) * Kd + k0 + tx] = __float2bfloat16(slo[tx][nn]);
    }
}

__global__ void wsplit_kernel(const float* __restrict__ W, bf16* __restrict__ Th,
                              bf16* __restrict__ Tl, int Kd, int Nc) {
    wsplit_body(W + (size_t)blockIdx.z * Kd * Nc, Th + (size_t)blockIdx.z * Kd * Nc,
                Tl + (size_t)blockIdx.z * Kd * Nc, Kd, Nc);
}

// fused 256x256 wsplit for Wq/Wk/Wv/Wo: z = l*4 + w
__global__ void wsplit4_kernel(const float* __restrict__ Wq, const float* __restrict__ Wk,
                               const float* __restrict__ Wv, const float* __restrict__ Wo,
                               bf16* __restrict__ qh, bf16* __restrict__ ql,
                               bf16* __restrict__ kh, bf16* __restrict__ kl,
                               bf16* __restrict__ vh, bf16* __restrict__ vl,
                               bf16* __restrict__ oh, bf16* __restrict__ ol) {
    int l = blockIdx.z >> 2, w = blockIdx.z & 3;
    size_t off = (size_t)l * Dd * Dd;
    const float* W = (w == 0) ? Wq : (w == 1) ? Wk : (w == 2) ? Wv : Wo;
    bf16* Th = (w == 0) ? qh : (w == 1) ? kh : (w == 2) ? vh : oh;
    bf16* Tl = (w == 0) ? ql : (w == 1) ? kl : (w == 2) ? vl : ol;
    wsplit_body(W + off, Th + off, Tl + off, Dd, Dd);
}

// ---------------- split-bf16 HMMA GEMM, cp.async 2-stage pipeline ----------------
// Dynamic smem layout (bf16 el): AH[2] @0/5120, AL[2] @10240/15360,
// BH[2] @20480/23040, BL[2] @25600/28160. Total 30720 el = 61440 B.
#define GEMM_SMEM 61440
template <int ACT, int OSPLIT>
__device__ __forceinline__ void hmma_gemm_body(
    const bf16* __restrict__ Ah, const bf16* __restrict__ Al,
    const bf16* __restrict__ Bh, const bf16* __restrict__ Bl,
    const float* __restrict__ bias, float* __restrict__ Cf,
    bf16* __restrict__ Ch, bf16* __restrict__ Cl,
    int Kd, int kbeg, int kslice, int Nc) {
    extern __shared__ bf16 gsm[];
    const int tid = threadIdx.x;
    const int wid = tid >> 5, lane = tid & 31;
    const int i0 = blockIdx.y << 7, j0 = blockIdx.x << 6;
    const int mw = (wid & 3) << 5;
    const int nw = (wid >> 2) << 5;

    float acc[2][4][4];
#pragma unroll
    for (int a = 0; a < 2; a++)
#pragma unroll
        for (int b = 0; b < 4; b++)
#pragma unroll
            for (int cc = 0; cc < 4; cc++) acc[a][b][cc] = 0.f;

    const int a_r = lane & 15;
    const int a_k = (lane >> 4) << 3;
    const int b_n = (lane & 7) + ((lane & 16) >> 1);
    const int b_k = lane & 8;

    uint32_t uAh[2] = {smem_u32(gsm), smem_u32(gsm + 5120)};
    uint32_t uAl[2] = {smem_u32(gsm + 10240), smem_u32(gsm + 15360)};
    uint32_t uBh[2] = {smem_u32(gsm + 20480), smem_u32(gsm + 23040)};
    uint32_t uBl[2] = {smem_u32(gsm + 25600), smem_u32(gsm + 28160)};

    const int r = tid >> 1, hf = (tid & 1) << 4;
    const int tb = tid & 127;
    const int rb = tb >> 1, hb = (tb & 1) << 4;
    const bf16* Bsel = (tid < 128) ? Bh : Bl;
    const uint32_t aoff = (uint32_t)((r * 40 + hf) << 1);
    const uint32_t boff = (uint32_t)((rb * 40 + hb) << 1);

    // prologue: issue chunk 0
    {
        const bf16* pAh = Ah + (size_t)(i0 + r) * Kd + kbeg + hf;
        const bf16* pAl = Al + (size_t)(i0 + r) * Kd + kbeg + hf;
        cpa16(uAh[0] + aoff, pAh);
        cpa16(uAh[0] + aoff + 16, pAh + 8);
        cpa16(uAl[0] + aoff, pAl);
        cpa16(uAl[0] + aoff + 16, pAl + 8);
        const bf16* pB = Bsel + (size_t)(j0 + rb) * Kd + kbeg + hb;
        uint32_t ub = (tid < 128) ? uBh[0] : uBl[0];
        cpa16(ub + boff, pB);
        cpa16(ub + boff + 16, pB + 8);
    }
    CP_COMMIT();

    const int nch = kslice >> 5;
    for (int c = 0; c < nch; c++) {
        const int buf = c & 1;
        CP_WAIT(0);
        __syncthreads();  // chunk c ready AND prior reads of buf finished

        if (c + 1 < nch) {
            int kt = kbeg + ((c + 1) << 5);
            int nb = buf ^ 1;
            const bf16* pAh = Ah + (size_t)(i0 + r) * Kd + kt + hf;
            const bf16* pAl = Al + (size_t)(i0 + r) * Kd + kt + hf;
            cpa16(uAh[nb] + aoff, pAh);
            cpa16(uAh[nb] + aoff + 16, pAh + 8);
            cpa16(uAl[nb] + aoff, pAl);
            cpa16(uAl[nb] + aoff + 16, pAl + 8);
            const bf16* pB = Bsel + (size_t)(j0 + rb) * Kd + kt + hb;
            uint32_t ub = (tid < 128) ? uBh[nb] : uBl[nb];
            cpa16(ub + boff, pB);
            cpa16(ub + boff + 16, pB + 8);
        }
        CP_COMMIT();

#pragma unroll
        for (int ks = 0; ks < 2; ks++) {
            const int kk = ks << 4;
            uint32_t ah[2][4], al[2][4], bhf[2][4], blf[2][4];
#pragma unroll
            for (int mf = 0; mf < 2; mf++) {
                uint32_t off = (uint32_t)(((mw + (mf << 4) + a_r) * 40 + kk + a_k) << 1);
                ldsm4(ah[mf][0], ah[mf][1], ah[mf][2], ah[mf][3], uAh[buf] + off);
                ldsm4(al[mf][0], al[mf][1], al[mf][2], al[mf][3], uAl[buf] + off);
            }
#pragma unroll
            for (int g = 0; g < 2; g++) {
                uint32_t off = (uint32_t)(((nw + (g << 4) + b_n) * 40 + kk + b_k) << 1);
                ldsm4(bhf[g][0], bhf[g][1], bhf[g][2], bhf[g][3], uBh[buf] + off);
                ldsm4(blf[g][0], blf[g][1], blf[g][2], blf[g][3], uBl[buf] + off);
            }
#pragma unroll
            for (int mf = 0; mf < 2; mf++)
#pragma unroll
                for (int nf = 0; nf < 4; nf++) {
                    const uint32_t* ph = &bhf[nf >> 1][(nf & 1) << 1];
                    const uint32_t* pl = &blf[nf >> 1][(nf & 1) << 1];
                    mma_bf16(acc[mf][nf], ah[mf], ph);
                    mma_bf16(acc[mf][nf], ah[mf], pl);
                    mma_bf16(acc[mf][nf], al[mf], ph);
                }
        }
    }

    const int lr = lane >> 2, lc = (lane & 3) << 1;
#pragma unroll
    for (int mf = 0; mf < 2; mf++)
#pragma unroll
        for (int rp = 0; rp < 2; rp++) {
            int row = i0 + mw + (mf << 4) + lr + (rp << 3);
#pragma unroll
            for (int nf = 0; nf < 4; nf++) {
                float v0 = acc[mf][nf][(rp << 1) + 0];
                float v1 = acc[mf][nf][(rp << 1) + 1];
                int col = j0 + nw + (nf << 3) + lc;
                if (OSPLIT == 0) {
                    if (bias) {
                        v0 += bias[col];
                        v1 += bias[col + 1];
                    }
                    *(float2*)&Cf[(size_t)row * Nc + col] = make_float2(v0, v1);
                } else {
                    if (OSPLIT == 1) {
                        v0 += bias[col];
                        v1 += bias[col + 1];
                        if (ACT == 1) {
                            v0 = 0.5f * v0 * (1.0f + erff(v0 * 0.70710678118654752f));
                            v1 = 0.5f * v1 * (1.0f + erff(v1 * 0.70710678118654752f));
                        }
                    }
                    bf16 h0 = __float2bfloat16(v0), h1 = __float2bfloat16(v1);
                    Ch[(size_t)row * Nc + col] = h0;
                    Ch[(size_t)row * Nc + col + 1] = h1;
                    Cl[(size_t)row * Nc + col] = __float2bfloat16(v0 - __bfloat162float(h0));
                    Cl[(size_t)row * Nc + col + 1] = __float2bfloat16(v1 - __bfloat162float(h1));
                }
            }
        }
}

template <int ACT, int SPLIT, int OSPLIT>
__global__ void __launch_bounds__(256) hmma_gemm_kernel(
    const bf16* __restrict__ Ah, const bf16* __restrict__ Al,
    const bf16* __restrict__ Bh, const bf16* __restrict__ Bl,
    const float* __restrict__ bias, float* __restrict__ Cf,
    bf16* __restrict__ Ch, bf16* __restrict__ Cl, int Kd, int Nc) {
    int kslice = Kd / SPLIT;
    int kbeg = blockIdx.z * kslice;
    float* Cz = (SPLIT > 1) ? Cf + (size_t)blockIdx.z * Nn * Nc : Cf;
    hmma_gemm_body<ACT, OSPLIT>(Ah, Al, Bh, Bl, SPLIT > 1 ? nullptr : bias, Cz, Ch, Cl,
                                Kd, kbeg, kslice, Nc);
}

__global__ void __launch_bounds__(256) hmma_qkv_kernel(
    const bf16* __restrict__ Ah, const bf16* __restrict__ Al,
    const bf16* __restrict__ Bh0, const bf16* __restrict__ Bl0,
    const bf16* __restrict__ Bh1, const bf16* __restrict__ Bl1,
    const bf16* __restrict__ Bh2, const bf16* __restrict__ Bl2,
    bf16* __restrict__ qh, bf16* __restrict__ ql, bf16* __restrict__ kh,
    bf16* __restrict__ kl, bf16* __restrict__ vh, bf16* __restrict__ vl) {
    int z = blockIdx.z;
    const bf16* Bh = (z == 0) ? Bh0 : (z == 1) ? Bh1 : Bh2;
    const bf16* Bl = (z == 0) ? Bl0 : (z == 1) ? Bl1 : Bl2;
    bf16* Ch = (z == 0) ? qh : (z == 1) ? kh : vh;
    bf16* Cl = (z == 0) ? ql : (z == 1) ? kl : vl;
    hmma_gemm_body<0, 2>(Ah, Al, Bh, Bl, nullptr, nullptr, Ch, Cl, Dd, 0, Dd, Dd);
}

// ---------------- HMMA flash attention v3 (R12, unchanged) ----------------
#define ATTN_SMEM 71680
__global__ void __launch_bounds__(256) attn_hmma_kernel(
    const bf16* __restrict__ Qh, const bf16* __restrict__ Ql,
    const bf16* __restrict__ Kh, const bf16* __restrict__ Kl,
    const bf16* __restrict__ Vh, const bf16* __restrict__ Vl,
    const unsigned char* __restrict__ E8, const float* __restrict__ ebl,
    bf16* __restrict__ Oh, bf16* __restrict__ Ol) {
    extern __shared__ bf16 dsm[];
    __shared__ float s_eb[8];

    const int h = blockIdx.y;
    const int i0 = blockIdx.x << 6;
    const int tid = threadIdx.x;
    const int wid = tid >> 5, lane = tid & 31;
    const int gid = wid >> 2;
    const int mw = (wid & 3) << 4;
    const int gt = tid & 127;

    if (tid < NEDGEe) s_eb[tid] = ebl[tid * Hh + h] * 1.4426950408889634f;

    const int a_r = lane & 15, a_k = (lane >> 4) << 3;
    const int b_n = (lane & 7) + ((lane & 16) >> 1), b_k = lane & 8;
    const int lr = lane >> 2, lc = (lane & 3) << 1;

    const uint32_t uQh = smem_u32(dsm);
    const uint32_t uQl = smem_u32(dsm + 2560);
    uint32_t uKh[2], uKl[2];
    uKh[0] = smem_u32(dsm + 5120 + (gid * 2) * 2560);
    uKh[1] = smem_u32(dsm + 5120 + (gid * 2 + 1) * 2560);
    uKl[0] = smem_u32(dsm + 15360 + (gid * 2) * 2560);
    uKl[1] = smem_u32(dsm + 15360 + (gid * 2 + 1) * 2560);
    const uint32_t uVh = smem_u32(dsm + 25600 + gid * 2560);
    const uint32_t uVl = smem_u32(dsm + 30720 + gid * 2560);

    const int qr = gt >> 1, qh4 = (gt & 1) << 4;
    const uint32_t soff0 = (uint32_t)((qr * 40 + qh4) << 1);
    const size_t ghead = (size_t)h * DKk + qh4;

    {
        const bf16* pk = Kh + (size_t)(gid * 64 + qr) * Dd + ghead;
        cpa16(uKh[0] + soff0, pk);
        cpa16(uKh[0] + soff0 + 16, pk + 8);
        const bf16* pk2 = Kl + (size_t)(gid * 64 + qr) * Dd + ghead;
        cpa16(uKl[0] + soff0, pk2);
        cpa16(uKl[0] + soff0 + 16, pk2 + 8);
    }
    CP_COMMIT();
    if (gid == 0) {
        const bf16* p = Qh + (size_t)(i0 + qr) * Dd + ghead;
        *(uint4*)(dsm + qr * 40 + qh4) = *(const uint4*)p;
        *(uint4*)(dsm + qr * 40 + qh4 + 8) = *(const uint4*)(p + 8);
        const bf16* p2 = Ql + (size_t)(i0 + qr) * Dd + ghead;
        *(uint4*)(dsm + 2560 + qr * 40 + qh4) = *(const uint4*)p2;
        *(uint4*)(dsm + 2560 + qr * 40 + qh4 + 8) = *(const uint4*)(p2 + 8);
    }
    __syncthreads();

    float of[4][4];
#pragma unroll
    for (int a = 0; a < 4; a++)
#pragma unroll
        for (int b = 0; b < 4; b++) of[a][b] = 0.f;
    float m0 = -1e30f, m1 = -1e30f, l0 = 0.f, l1 = 0.f;
    const float scale2 = 0.17677669529663687f * 1.4426950408889634f;
    const size_t r0e = (size_t)(i0 + mw + lr) * Nn;
    const size_t r1e = (size_t)(i0 + mw + lr + 8) * Nn;

    for (int t = 0; t < 16; t++) {
        const int jt = ((t << 1) + gid) << 6;
        const int buf = t & 1;
        CP_WAIT(0);
        GBAR(gid + 1);

        {
            const bf16* pv = Vh + (size_t)(jt + qr) * Dd + ghead;
            cpa16(uVh + soff0, pv);
            cpa16(uVh + soff0 + 16, pv + 8);
            const bf16* pv2 = Vl + (size_t)(jt + qr) * Dd + ghead;
            cpa16(uVl + soff0, pv2);
            cpa16(uVl + soff0 + 16, pv2 + 8);
        }
        CP_COMMIT();
        if (t + 1 < 16) {
            const bf16* pk = Kh + (size_t)(jt + 128 + qr) * Dd + ghead;
            cpa16(uKh[buf ^ 1] + soff0, pk);
            cpa16(uKh[buf ^ 1] + soff0 + 16, pk + 8);
            const bf16* pk2 = Kl + (size_t)(jt + 128 + qr) * Dd + ghead;
            cpa16(uKl[buf ^ 1] + soff0, pk2);
            cpa16(uKl[buf ^ 1] + soff0 + 16, pk2 + 8);
        }
        CP_COMMIT();

        unsigned short eu0[8], eu1[8];
#pragma unroll
        for (int nf = 0; nf < 8; nf++) {
            eu0[nf] = *(const unsigned short*)&E8[r0e + jt + (nf << 3) + lc];
            eu1[nf] = *(const unsigned short*)&E8[r1e + jt + (nf << 3) + lc];
        }

        float sf[8][4];
#pragma unroll
        for (int nf = 0; nf < 8; nf++)
#pragma unroll
            for (int cc = 0; cc < 4; cc++) sf[nf][cc] = 0.f;
#pragma unroll
        for (int ks = 0; ks < 2; ks++) {
            const int kk = ks << 4;
            uint32_t aqh[4], aql[4];
            uint32_t offa = (uint32_t)(((mw + a_r) * 40 + kk + a_k) << 1);
            ldsm4(aqh[0], aqh[1], aqh[2], aqh[3], uQh + offa);
            ldsm4(aql[0], aql[1], aql[2], aql[3], uQl + offa);
#pragma unroll
            for (int g = 0; g < 4; g++) {
                uint32_t bkh[4], bkl[4];
                uint32_t offb = (uint32_t)((((g << 4) + b_n) * 40 + kk + b_k) << 1);
                ldsm4(bkh[0], bkh[1], bkh[2], bkh[3], uKh[buf] + offb);
                ldsm4(bkl[0], bkl[1], bkl[2], bkl[3], uKl[buf] + offb);
#pragma unroll
                for (int sub = 0; sub < 2; sub++) {
                    int nf = (g << 1) + sub;
                    const uint32_t* ph = &bkh[sub << 1];
                    const uint32_t* pl = &bkl[sub << 1];
                    mma_bf16(sf[nf], aqh, ph);
                    mma_bf16(sf[nf], aqh, pl);
                    mma_bf16(sf[nf], aql, ph);
                }
            }
        }

        float mx0 = -1e30f, mx1 = -1e30f;
#pragma unroll
        for (int nf = 0; nf < 8; nf++) {
            sf[nf][0] = fmaf(sf[nf][0], scale2, s_eb[eu0[nf] & 0xffu]);
            sf[nf][1] = fmaf(sf[nf][1], scale2, s_eb[eu0[nf] >> 8]);
            sf[nf][2] = fmaf(sf[nf][2], scale2, s_eb[eu1[nf] & 0xffu]);
            sf[nf][3] = fmaf(sf[nf][3], scale2, s_eb[eu1[nf] >> 8]);
            mx0 = fmaxf(mx0, fmaxf(sf[nf][0], sf[nf][1]));
            mx1 = fmaxf(mx1, fmaxf(sf[nf][2], sf[nf][3]));
        }
        mx0 = fmaxf(mx0, __shfl_xor_sync(0xffffffffu, mx0, 1));
        mx0 = fmaxf(mx0, __shfl_xor_sync(0xffffffffu, mx0, 2));
        mx1 = fmaxf(mx1, __shfl_xor_sync(0xffffffffu, mx1, 1));
        mx1 = fmaxf(mx1, __shfl_xor_sync(0xffffffffu, mx1, 2));
        float mn0 = fmaxf(m0, mx0), mn1 = fmaxf(m1, mx1);
        float al0 = ex2f(m0 - mn0), al1 = ex2f(m1 - mn1);
        m0 = mn0;
        m1 = mn1;
#pragma unroll
        for (int nf = 0; nf < 4; nf++) {
            of[nf][0] *= al0;
            of[nf][1] *= al0;
            of[nf][2] *= al1;
            of[nf][3] *= al1;
        }

        float ps0 = 0.f, ps1 = 0.f;
        uint32_t aph[4][4];
#pragma unroll
        for (int nf = 0; nf < 8; nf++) {
            float p0 = ex2f(sf[nf][0] - mn0);
            float p1 = ex2f(sf[nf][1] - mn0);
            float p2 = ex2f(sf[nf][2] - mn1);
            float p3 = ex2f(sf[nf][3] - mn1);
            ps0 += p0 + p1;
            ps1 += p2 + p3;
            int ks = nf >> 1, base = (nf & 1) << 1;
            aph[ks][base + 0] = pack2bf(p0, p1);
            aph[ks][base + 1] = pack2bf(p2, p3);
        }
        ps0 += __shfl_xor_sync(0xffffffffu, ps0, 1);
        ps0 += __shfl_xor_sync(0xffffffffu, ps0, 2);
        ps1 += __shfl_xor_sync(0xffffffffu, ps1, 1);
        ps1 += __shfl_xor_sync(0xffffffffu, ps1, 2);
        l0 = l0 * al0 + ps0;
        l1 = l1 * al1 + ps1;

        CP_WAIT(1);
        GBAR(gid + 1);
#pragma unroll
        for (int ks = 0; ks < 4; ks++) {
            const int kk = ks << 4;
#pragma unroll
            for (int dg = 0; dg < 2; dg++) {
                uint32_t bvh[4], bvl[4];
                uint32_t offv = (uint32_t)(((kk + a_r) * 40 + (dg << 4) + a_k) << 1);
                ldsm4t(bvh[0], bvh[1], bvh[2], bvh[3], uVh + offv);
                ldsm4t(bvl[0], bvl[1], bvl[2], bvl[3], uVl + offv);
#pragma unroll
                for (int sub = 0; sub < 2; sub++) {
                    int nf = (dg << 1) + sub;
                    mma_bf16(of[nf], aph[ks], &bvh[sub << 1]);
                    mma_bf16(of[nf], aph[ks], &bvl[sub << 1]);
                }
            }
        }
    }

    CP_WAIT(0);
    __syncthreads();
    float* mg = (float*)dsm;
    float* lg = mg + 256;
    float* og = lg + 256;
    if (gid == 1) {
        mg[gt * 2] = m0;
        mg[gt * 2 + 1] = m1;
        lg[gt * 2] = l0;
        lg[gt * 2 + 1] = l1;
#pragma unroll
        for (int nf = 0; nf < 4; nf++)
#pragma unroll
            for (int c = 0; c < 4; c++) og[gt * 16 + nf * 4 + c] = of[nf][c];
    }
    __syncthreads();
    if (gid == 0) {
        float mb0 = mg[gt * 2], mb1 = mg[gt * 2 + 1];
        float lb0 = lg[gt * 2], lb1 = lg[gt * 2 + 1];
        float mn0 = fmaxf(m0, mb0), mn1 = fmaxf(m1, mb1);
        float a0 = ex2f(m0 - mn0), bb0 = ex2f(mb0 - mn0);
        float a1 = ex2f(m1 - mn1), bb1 = ex2f(mb1 - mn1);
        float inv0 = 1.0f / (l0 * a0 + lb0 * bb0);
        float inv1 = 1.0f / (l1 * a1 + lb1 * bb1);
        int row0 = i0 + mw + lr, row1 = row0 + 8;
#pragma unroll
        for (int nf = 0; nf < 4; nf++) {
            int col = h * DKk + (nf << 3) + lc;
            float v0 = (of[nf][0] * a0 + og[gt * 16 + nf * 4 + 0] * bb0) * inv0;
            float v1 = (of[nf][1] * a0 + og[gt * 16 + nf * 4 + 1] * bb0) * inv0;
            float v2 = (of[nf][2] * a1 + og[gt * 16 + nf * 4 + 2] * bb1) * inv1;
            float v3 = (of[nf][3] * a1 + og[gt * 16 + nf * 4 + 3] * bb1) * inv1;
            float h0 = __bfloat162float(__float2bfloat16(v0));
            float h1 = __bfloat162float(__float2bfloat16(v1));
            float h2 = __bfloat162float(__float2bfloat16(v2));
            float h3 = __bfloat162float(__float2bfloat16(v3));
            *(uint32_t*)&Oh[(size_t)row0 * Dd + col] = pack2bf(h0, h1);
            *(uint32_t*)&Oh[(size_t)row1 * Dd + col] = pack2bf(h2, h3);
            *(uint32_t*)&Ol[(size_t)row0 * Dd + col] = pack2bf(v0 - h0, v1 - h1);
            *(uint32_t*)&Ol[(size_t)row1 * Dd + col] = pack2bf(v2 - h2, v3 - h3);
        }
    }
}

// ---------------- reduce + bias + residual + LayerNorm (warp shuffle) ----------------
template <int S>
__global__ void addln_red_kernel(float* __restrict__ x, const float* __restrict__ part,
                                 const float* __restrict__ bias, const float* __restrict__ g,
                                 const float* __restrict__ b, bf16* __restrict__ xh,
                                 bf16* __restrict__ xl) {
    int i = blockIdx.x, d = threadIdx.x;
    int lane = d & 31, w = d >> 5;
    __shared__ float ws[8];
    float v = x[i * Dd + d] + bias[d];
#pragma unroll
    for (int s = 0; s < S; s++) v += part[(size_t)s * Nn * Dd + (size_t)i * Dd + d];
    float t = v;
#pragma unroll
    for (int off = 16; off > 0; off >>= 1) t += __shfl_xor_sync(0xffffffffu, t, off);
    if (lane == 0) ws[w] = t;
    __syncthreads();
    float mean = (ws[0] + ws[1] + ws[2] + ws[3] + ws[4] + ws[5] + ws[6] + ws[7]) * (1.0f / Dd);
    float dv = v - mean;
    t = dv * dv;
#pragma unroll
    for (int off = 16; off > 0; off >>= 1) t += __shfl_xor_sync(0xffffffffu, t, off);
    __syncthreads();
    if (lane == 0) ws[w] = t;
    __syncthreads();
    float var = (ws[0] + ws[1] + ws[2] + ws[3] + ws[4] + ws[5] + ws[6] + ws[7]) * (1.0f / Dd);
    float outv = dv * rsqrtf(var + 1e-5f) * g[d] + b[d];
    x[i * Dd + d] = outv;
    bf16 h = __float2bfloat16(outv);
    xh[i * Dd + d] = h;
    xl[i * Dd + d] = __float2bfloat16(outv - __bfloat162float(h));
}

__global__ void pool_kernel(const float* __restrict__ x, float* __restrict__ p) {
    int j = blockIdx.x * 32 + threadIdx.x;
    int yy = threadIdx.y;
    float s = 0.f, mx = -1e30f;
    for (int i = yy; i < Nn; i += 8) {
        float v = x[(size_t)i * Dd + j];
        s += v;
        mx = fmaxf(mx, v);
    }
    __shared__ float ss[8][33], sm[8][33];
    ss[yy][threadIdx.x] = s;
    sm[yy][threadIdx.x] = mx;
    __syncthreads();
    if (yy == 0) {
        for (int k2 = 1; k2 < 8; k2++) {
            s += ss[k2][threadIdx.x];
            mx = fmaxf(mx, sm[k2][threadIdx.x]);
        }
        p[j] = s * (1.0f / Nn);
        p[Dd + j] = mx;
    }
}

__global__ void head_kernel(const float* __restrict__ pooled, const float* __restrict__ Wr,
                            const float* __restrict__ br, float* __restrict__ out) {
    __shared__ float sp[2 * Dd];
    int d = threadIdx.x;
    sp[d] = pooled[d];
    sp[d + Dd] = pooled[d + Dd];
    __syncthreads();
    float acc = br[d];
#pragma unroll 8
    for (int k2 = 0; k2 < 2 * Dd; k2++) acc = fmaf(sp[k2], Wr[(size_t)k2 * Dd + d], acc);
    out[d] = acc;
}

// ---------------- host launcher ----------------
extern "C" void kernel_launch(void* const* d_in, const int* in_sizes, int n_in,
                              void* d_out, int out_size) {
    const int* node_types = (const int*)d_in[0];
    const int* edge_idx = (const int*)d_in[1];
    const float* node_emb = (const float*)d_in[2];
    const float* Wq = (const float*)d_in[3];
    const float* Wk = (const float*)d_in[4];
    const float* Wv = (const float*)d_in[5];
    const float* Wo = (const float*)d_in[6];
    const float* bo = (const float*)d_in[7];
    const float* eb = (const float*)d_in[8];
    const float* W1 = (const float*)d_in[9];
    const float* b1 = (const float*)d_in[10];
    const float* W2 = (const float*)d_in[11];
    const float* b2 = (const float*)d_in[12];
    const float* ln1g = (const float*)d_in[13];
    const float* ln1b = (const float*)d_in[14];
    const float* ln2g = (const float*)d_in[15];
    const float* ln2b = (const float*)d_in[16];
    const float* Wr = (const float*)d_in[17];
    const float* brr = (const float*)d_in[18];
    float* out = (float*)d_out;

    float *x, *part, *pool;
    unsigned char* e8;
    bf16 *xh, *xl, *qh, *ql, *kh, *kl, *vh, *vl, *atth, *attl, *t1h, *t1l;
    bf16 *wqh, *wql, *wkh, *wkl, *wvh, *wvl, *woh, *wol, *w1h, *w1l, *w2h, *w2l;
    cudaGetSymbolAddress((void**)&x, g_x);
    cudaGetSymbolAddress((void**)&part, g_part);
    cudaGetSymbolAddress((void**)&pool, g_pool);
    cudaGetSymbolAddress((void**)&e8, g_e8);
    cudaGetSymbolAddress((void**)&xh, g_xh);
    cudaGetSymbolAddress((void**)&xl, g_xl);
    cudaGetSymbolAddress((void**)&qh, g_qh);
    cudaGetSymbolAddress((void**)&ql, g_ql);
    cudaGetSymbolAddress((void**)&kh, g_kh);
    cudaGetSymbolAddress((void**)&kl, g_kl);
    cudaGetSymbolAddress((void**)&vh, g_vh);
    cudaGetSymbolAddress((void**)&vl, g_vl);
    cudaGetSymbolAddress((void**)&atth, g_atth);
    cudaGetSymbolAddress((void**)&attl, g_attl);
    cudaGetSymbolAddress((void**)&t1h, g_t1h);
    cudaGetSymbolAddress((void**)&t1l, g_t1l);
    cudaGetSymbolAddress((void**)&wqh, g_wqh);
    cudaGetSymbolAddress((void**)&wql, g_wql);
    cudaGetSymbolAddress((void**)&wkh, g_wkh);
    cudaGetSymbolAddress((void**)&wkl, g_wkl);
    cudaGetSymbolAddress((void**)&wvh, g_wvh);
    cudaGetSymbolAddress((void**)&wvl, g_wvl);
    cudaGetSymbolAddress((void**)&woh, g_woh);
    cudaGetSymbolAddress((void**)&wol, g_wol);
    cudaGetSymbolAddress((void**)&w1h, g_w1h);
    cudaGetSymbolAddress((void**)&w1l, g_w1l);
    cudaGetSymbolAddress((void**)&w2h, g_w2h);
    cudaGetSymbolAddress((void**)&w2l, g_w2l);

    cudaFuncSetAttribute(attn_hmma_kernel, cudaFuncAttributeMaxDynamicSharedMemorySize,
                         ATTN_SMEM);
    cudaFuncSetAttribute(hmma_qkv_kernel, cudaFuncAttributeMaxDynamicSharedMemorySize,
                         GEMM_SMEM);
    cudaFuncSetAttribute(hmma_gemm_kernel<0, 2, 0>, cudaFuncAttributeMaxDynamicSharedMemorySize,
                         GEMM_SMEM);
    cudaFuncSetAttribute(hmma_gemm_kernel<1, 1, 1>, cudaFuncAttributeMaxDynamicSharedMemorySize,
                         GEMM_SMEM);

    embed_kernel<<<Nn, Dd>>>(node_types, node_emb, x, xh, xl);
    cvt_e8_kernel<<<(Nn * Nn / 4) / 256, 256>>>(edge_idx, e8);

    wsplit4_kernel<<<dim3(8, 8, 4 * Ll), dim3(32, 8)>>>(Wq, Wk, Wv, Wo, wqh, wql, wkh, wkl,
                                                        wvh, wvl, woh, wol);
    wsplit_kernel<<<dim3(32, 8, Ll), dim3(32, 8)>>>(W1, w1h, w1l, Dd, DFFf);
    wsplit_kernel<<<dim3(8, 32, Ll), dim3(32, 8)>>>(W2, w2h, w2l, DFFf, Dd);

    for (int l = 0; l < Ll; l++) {
        size_t wo256 = (size_t)l * Dd * Dd;
        size_t woff1 = (size_t)l * Dd * DFFf;
        hmma_qkv_kernel<<<dim3(4, 16, 3), 256, GEMM_SMEM>>>(
            xh, xl, wqh + wo256, wql + wo256, wkh + wo256, wkl + wo256, wvh + wo256,
            wvl + wo256, qh, ql, kh, kl, vh, vl);

        attn_hmma_kernel<<<dim3(Nn / 64, Hh), 256, ATTN_SMEM>>>(
            qh, ql, kh, kl, vh, vl, e8, eb + l * NEDGEe * Hh, atth, attl);

        hmma_gemm_kernel<0, 2, 0><<<dim3(4, 16, 2), 256, GEMM_SMEM>>>(
            atth, attl, woh + wo256, wol + wo256, nullptr, part, nullptr, nullptr, Dd, Dd);
        addln_red_kernel<2><<<Nn, Dd>>>(x, part, bo + l * Dd, ln1g + l * Dd, ln1b + l * Dd, xh,
                                        xl);

        hmma_gemm_kernel<1, 1, 1><<<dim3(16, 16, 1), 256, GEMM_SMEM>>>(
            xh, xl, w1h + woff1, w1l + woff1, b1 + l * DFFf, nullptr, t1h, t1l, Dd, DFFf);

        hmma_gemm_kernel<0, 2, 0><<<dim3(4, 16, 2), 256, GEMM_SMEM>>>(
            t1h, t1l, w2h + woff1, w2l + woff1, nullptr, part, nullptr, nullptr, DFFf, Dd);
        addln_red_kernel<2><<<Nn, Dd>>>(x, part, b2 + l * Dd, ln2g + l * Dd, ln2b + l * Dd, xh,
                                        xl);
    }

    pool_kernel<<<Dd / 32, dim3(32, 8)>>>(x, pool);
    head_kernel<<<1, Dd>>>(pool, Wr, brr, out);
}